// round 1
// baseline (speedup 1.0000x reference)
#include <cuda_runtime.h>
#include <math.h>

#define NCAP 20000
#define ECAP 320000

// ---------------- static scratch (no allocation allowed) ----------------
static __device__ float    d_x0  [NCAP * 64];
static __device__ float    d_hbuf[NCAP * 256];
static __device__ float    d_gA  [NCAP * 256];
static __device__ float    d_gB  [NCAP * 256];
static __device__ float    d_P   [NCAP * 128];
static __device__ unsigned d_Mx  [NCAP * 128];
static __device__ float    d_dinv[NCAP];
static __device__ int      d_indeg[NCAP];
static __device__ float    d_bna [512];
static __device__ float    d_bnb [512];

// ---------------- small elementwise kernels ----------------
__global__ void zero_i32(int* p, int n) {
    int i = blockIdx.x * 256 + threadIdx.x;
    if (i < n) p[i] = 0;
}
__global__ void zero_u32(unsigned* p, int n) {
    int i = blockIdx.x * 256 + threadIdx.x;
    if (i < n) p[i] = 0u;
}
__global__ void count_indeg(const int* __restrict__ dstv, int* __restrict__ indeg, int E) {
    int e = blockIdx.x * 256 + threadIdx.x;
    if (e < E) atomicAdd(&indeg[dstv[e]], 1);
}
__global__ void compute_dinv(const int* __restrict__ indeg, float* __restrict__ dinv, int N) {
    int i = blockIdx.x * 256 + threadIdx.x;
    if (i < N) dinv[i] = rsqrtf((float)indeg[i] + 1.0f);
}
__global__ void bn_coef(const float* __restrict__ g, const float* __restrict__ be,
                        const float* __restrict__ me, const float* __restrict__ va,
                        float* __restrict__ a, float* __restrict__ b, int n) {
    int i = blockIdx.x * 256 + threadIdx.x;
    if (i < n) {
        float ai = g[i] * rsqrtf(va[i] + 1e-5f);
        a[i] = ai;
        b[i] = be[i] - me[i] * ai;
    }
}

// ---------------- fused dual-projection GEMM: x0 = x @ (row%4==0 ? Wm : Wc) + b ----------------
// A:[M,512], Bm/Bc:[512,64], C:[M,64].  64-row blocks, 256 threads, 4x4 per thread.
__global__ __launch_bounds__(256) void proj_kernel(
    const float* __restrict__ A,
    const float* __restrict__ Bm, const float* __restrict__ bm,
    const float* __restrict__ Bc, const float* __restrict__ bc,
    float* __restrict__ C, int Mrows)
{
    const int K = 512;
    __shared__ float As[16][65];
    __shared__ float Bms[16][64];
    __shared__ float Bcs[16][64];
    int tid = threadIdx.x;
    int tx = tid & 15, ty = tid >> 4;
    int row0 = blockIdx.x * 64;
    float acc[4][4] = {};
    for (int k0 = 0; k0 < K; k0 += 16) {
#pragma unroll
        for (int i = 0; i < 4; i++) {
            int lin = tid + i * 256;
            int r = lin >> 4, kk = lin & 15;
            int gr = row0 + r;
            As[kk][r] = (gr < Mrows) ? A[gr * K + k0 + kk] : 0.f;
        }
#pragma unroll
        for (int i = 0; i < 4; i++) {
            int lin = tid + i * 256;
            int kk = lin >> 6, n = lin & 63;
            Bms[kk][n] = Bm[(k0 + kk) * 64 + n];
            Bcs[kk][n] = Bc[(k0 + kk) * 64 + n];
        }
        __syncthreads();
#pragma unroll
        for (int kk = 0; kk < 16; kk++) {
            float4 bmv = *(const float4*)&Bms[kk][tx * 4];
            float4 bcv = *(const float4*)&Bcs[kk][tx * 4];
            // within this thread's 4 consecutive rows, row r==0 is the "main" row
            // (row0 and ty*4 are multiples of 4)
            float av0 = As[kk][ty * 4 + 0];
            acc[0][0] += av0 * bmv.x; acc[0][1] += av0 * bmv.y;
            acc[0][2] += av0 * bmv.z; acc[0][3] += av0 * bmv.w;
#pragma unroll
            for (int r = 1; r < 4; r++) {
                float av = As[kk][ty * 4 + r];
                acc[r][0] += av * bcv.x; acc[r][1] += av * bcv.y;
                acc[r][2] += av * bcv.z; acc[r][3] += av * bcv.w;
            }
        }
        __syncthreads();
    }
#pragma unroll
    for (int r = 0; r < 4; r++) {
        int gr = row0 + ty * 4 + r;
        if (gr < Mrows) {
#pragma unroll
            for (int c = 0; c < 4; c++) {
                float bias = (r == 0) ? bm[tx * 4 + c] : bc[tx * 4 + c];
                C[gr * 64 + tx * 4 + c] = acc[r][c] + bias;
            }
        }
    }
}

// ---------------- generic node GEMM: C = f(A) @ B ----------------
// A:[M,K] (optionally transformed v -> relu(ta[k]*v+tb[k])), B:[K,Ncols], C:[M,Ncols]
// grid: (ceil(M/64), Ncols/64). K multiple of 16, Ncols multiple of 64.
__global__ __launch_bounds__(256) void gemm_kernel(
    const float* __restrict__ A, const float* __restrict__ B, float* __restrict__ C,
    int Mrows, int K, int Ncols,
    const float* __restrict__ ta, const float* __restrict__ tb)
{
    __shared__ float As[16][65];
    __shared__ float Bs[16][64];
    int tid = threadIdx.x;
    int tx = tid & 15, ty = tid >> 4;
    int row0 = blockIdx.x * 64;
    int col0 = blockIdx.y * 64;
    float acc[4][4] = {};
    for (int k0 = 0; k0 < K; k0 += 16) {
#pragma unroll
        for (int i = 0; i < 4; i++) {
            int lin = tid + i * 256;
            int r = lin >> 4, kk = lin & 15;
            int gr = row0 + r;
            float v = 0.f;
            if (gr < Mrows) {
                v = A[gr * K + k0 + kk];
                if (ta) {
                    int k = k0 + kk;
                    v = fmaxf(ta[k] * v + tb[k], 0.f);
                }
            }
            As[kk][r] = v;
        }
#pragma unroll
        for (int i = 0; i < 4; i++) {
            int lin = tid + i * 256;
            int kk = lin >> 6, n = lin & 63;
            Bs[kk][n] = B[(k0 + kk) * Ncols + col0 + n];
        }
        __syncthreads();
#pragma unroll
        for (int kk = 0; kk < 16; kk++) {
            float4 bv = *(const float4*)&Bs[kk][tx * 4];
#pragma unroll
            for (int r = 0; r < 4; r++) {
                float av = As[kk][ty * 4 + r];
                acc[r][0] += av * bv.x; acc[r][1] += av * bv.y;
                acc[r][2] += av * bv.z; acc[r][3] += av * bv.w;
            }
        }
        __syncthreads();
    }
#pragma unroll
    for (int r = 0; r < 4; r++) {
        int gr = row0 + ty * 4 + r;
        if (gr < Mrows) {
            float4 o = make_float4(acc[r][0], acc[r][1], acc[r][2], acc[r][3]);
            *(float4*)&C[gr * Ncols + col0 + tx * 4] = o;
        }
    }
}

// ---------------- GCN: init with self-loop term + bias ----------------
__global__ void gcn_init(const float* __restrict__ h, const float* __restrict__ bias,
                         const float* __restrict__ dinv, float* __restrict__ out,
                         int N, int lc)
{
    int idx = blockIdx.x * 256 + threadIdx.x;
    if (idx >= (N << lc)) return;
    int i = idx >> lc;
    int j = idx & ((1 << lc) - 1);
    float di = dinv[i];
    out[idx] = bias[j] + di * di * h[idx];
}

// ---------------- GCN: edge scatter (atomicAdd) ----------------
__global__ void gcn_edge(const float* __restrict__ h, const int* __restrict__ src,
                         const int* __restrict__ dstv, const float* __restrict__ dinv,
                         float* __restrict__ out, int E, int lc)
{
    int idx = blockIdx.x * 256 + threadIdx.x;
    if (idx >= (E << lc)) return;
    int e = idx >> lc;
    int j = idx & ((1 << lc) - 1);
    int s = src[e], d = dstv[e];
    float coef = dinv[s] * dinv[d];
    atomicAdd(&out[(d << lc) + j], h[(s << lc) + j] * coef);
}

// ---------------- EdgeConv edge GEMM + atomicMax scatter ----------------
// Per edge e: q[c] = relu(a2[c]*(g[src,c]-g[dst,c])+b2[c]),  m = q @ Wb  (C x 128)
// Encoded-key atomicMax into Mout[dst*128 + j].
// Block: 32 edges x 128 outputs, 256 threads, 4x4 per thread, K chunks of 16.
__global__ __launch_bounds__(256) void edgeconv_kernel(
    const float* __restrict__ g, const int* __restrict__ src, const int* __restrict__ dstv,
    const float* __restrict__ a2, const float* __restrict__ b2,
    const float* __restrict__ Wb, unsigned* __restrict__ Mout, int E, int C)
{
    __shared__ float qs[32][17];
    __shared__ float ws[16][128];
    __shared__ int ss[32], sd[32];
    int tid = threadIdx.x;
    int e0 = blockIdx.x * 32;
    if (tid < 32) {
        int e = e0 + tid;
        int ee = (e < E) ? e : 0;
        ss[tid] = src[ee];
        sd[tid] = dstv[ee];
    }
    __syncthreads();
    int tx = tid & 31, ty = tid >> 5;   // tx: 32 col-groups of 4, ty: 8 edge-groups of 4
    float acc[4][4] = {};
    for (int k0 = 0; k0 < C; k0 += 16) {
#pragma unroll
        for (int i = 0; i < 2; i++) {
            int lin = tid + i * 256;
            int e = lin >> 4, kk = lin & 15;
            int k = k0 + kk;
            float gs = g[ss[e] * C + k];
            float gd = g[sd[e] * C + k];
            qs[e][kk] = fmaxf(a2[k] * (gs - gd) + b2[k], 0.f);
        }
#pragma unroll
        for (int i = 0; i < 8; i++) {
            int lin = tid + i * 256;
            int kk = lin >> 7, n = lin & 127;
            ws[kk][n] = Wb[(k0 + kk) * 128 + n];
        }
        __syncthreads();
#pragma unroll
        for (int kk = 0; kk < 16; kk++) {
            float4 bv = *(const float4*)&ws[kk][tx * 4];
#pragma unroll
            for (int r = 0; r < 4; r++) {
                float av = qs[ty * 4 + r][kk];
                acc[r][0] += av * bv.x; acc[r][1] += av * bv.y;
                acc[r][2] += av * bv.z; acc[r][3] += av * bv.w;
            }
        }
        __syncthreads();
    }
#pragma unroll
    for (int r = 0; r < 4; r++) {
        int e = e0 + ty * 4 + r;
        if (e < E) {
            int d = sd[ty * 4 + r];
#pragma unroll
            for (int c = 0; c < 4; c++) {
                unsigned u = __float_as_uint(acc[r][c]);
                unsigned key = (u & 0x80000000u) ? ~u : (u | 0x80000000u);
                atomicMax(&Mout[d * 128 + tx * 4 + c], key);
            }
        }
    }
}

// ---------------- EdgeConv combine: out = indeg>0 ? P + decode(M) : 0 ----------------
__global__ void combine_kernel(const float* __restrict__ P, const unsigned* __restrict__ Mv,
                               const int* __restrict__ indeg, float* __restrict__ out, int N)
{
    int idx = blockIdx.x * 256 + threadIdx.x;
    if (idx >= N * 128) return;
    int i = idx >> 7;
    float v = 0.f;
    if (indeg[i] > 0) {
        unsigned k = Mv[idx];
        unsigned u = (k & 0x80000000u) ? (k & 0x7fffffffu) : ~k;
        v = P[idx] + __uint_as_float(u);
    }
    out[idx] = v;
}

// ---------------- final FC: out[i] = h[i,:] . Wfc + bfc ----------------
__global__ void fc_kernel(const float* __restrict__ h, const float* __restrict__ W,
                          const float* __restrict__ b, float* __restrict__ out, int N)
{
    int warp = (blockIdx.x * 256 + threadIdx.x) >> 5;
    int lane = threadIdx.x & 31;
    if (warp >= N) return;
    float s = 0.f;
#pragma unroll
    for (int j = lane; j < 128; j += 32) s += h[warp * 128 + j] * W[j];
#pragma unroll
    for (int o = 16; o; o >>= 1) s += __shfl_down_sync(0xffffffffu, s, o);
    if (lane == 0) out[warp] = s + b[0];
}

// ---------------- launch ----------------
extern "C" void kernel_launch(void* const* d_in, const int* in_sizes, int n_in,
                              void* d_out, int out_size)
{
    const float* x   = (const float*)d_in[0];
    const int*   ei  = (const int*)d_in[1];
    const float* Wm  = (const float*)d_in[2];
    const float* bm  = (const float*)d_in[3];
    const float* Wc  = (const float*)d_in[4];
    const float* bc  = (const float*)d_in[5];
    const float* Wg1 = (const float*)d_in[6];
    const float* bg1 = (const float*)d_in[7];
    const float* Wg2 = (const float*)d_in[8];
    const float* bg2 = (const float*)d_in[9];
    const float* Wg3 = (const float*)d_in[10];
    const float* bg3 = (const float*)d_in[11];
    const float* e1g = (const float*)d_in[12];
    const float* e1b = (const float*)d_in[13];
    const float* e1m = (const float*)d_in[14];
    const float* e1v = (const float*)d_in[15];
    const float* e1W = (const float*)d_in[16];
    const float* e2g = (const float*)d_in[17];
    const float* e2b = (const float*)d_in[18];
    const float* e2m = (const float*)d_in[19];
    const float* e2v = (const float*)d_in[20];
    const float* e2W = (const float*)d_in[21];
    const float* e3g = (const float*)d_in[22];
    const float* e3b = (const float*)d_in[23];
    const float* e3m = (const float*)d_in[24];
    const float* e3v = (const float*)d_in[25];
    const float* e3W = (const float*)d_in[26];
    const float* Wfc = (const float*)d_in[27];
    const float* bfc = (const float*)d_in[28];

    int N = in_sizes[0] / 512;
    int E = in_sizes[1] / 2;
    const int* src = ei;
    const int* dst = ei + E;

    float *x0, *hbuf, *gA, *gB, *P, *dinv, *bna, *bnb;
    unsigned* Mx;
    int* indeg;
    cudaGetSymbolAddress((void**)&x0,   d_x0);
    cudaGetSymbolAddress((void**)&hbuf, d_hbuf);
    cudaGetSymbolAddress((void**)&gA,   d_gA);
    cudaGetSymbolAddress((void**)&gB,   d_gB);
    cudaGetSymbolAddress((void**)&P,    d_P);
    cudaGetSymbolAddress((void**)&Mx,   d_Mx);
    cudaGetSymbolAddress((void**)&dinv, d_dinv);
    cudaGetSymbolAddress((void**)&indeg,d_indeg);
    cudaGetSymbolAddress((void**)&bna,  d_bna);
    cudaGetSymbolAddress((void**)&bnb,  d_bnb);

    dim3 t256(256);

    // input projection (fused row-select)
    proj_kernel<<<(N + 63) / 64, t256>>>(x, Wm, bm, Wc, bc, x0, N);

    // degrees
    zero_i32<<<(N + 255) / 256, t256>>>(indeg, N);
    count_indeg<<<(E + 255) / 256, t256>>>(dst, indeg, E);
    compute_dinv<<<(N + 255) / 256, t256>>>(indeg, dinv, N);

    // GCN1: x0[N,64] @ Wg1[64,128] -> gA
    gemm_kernel<<<dim3((N + 63) / 64, 2), t256>>>(x0, Wg1, hbuf, N, 64, 128, nullptr, nullptr);
    gcn_init<<<(N * 128 + 255) / 256, t256>>>(hbuf, bg1, dinv, gA, N, 7);
    gcn_edge<<<((E << 7) + 255) / 256, t256>>>(hbuf, src, dst, dinv, gA, E, 7);

    // GCN2: gA[N,128] @ Wg2[128,128] -> gB
    gemm_kernel<<<dim3((N + 63) / 64, 2), t256>>>(gA, Wg2, hbuf, N, 128, 128, nullptr, nullptr);
    gcn_init<<<(N * 128 + 255) / 256, t256>>>(hbuf, bg2, dinv, gB, N, 7);
    gcn_edge<<<((E << 7) + 255) / 256, t256>>>(hbuf, src, dst, dinv, gB, E, 7);

    // GCN3: gB[N,128] @ Wg3[128,256] -> gA
    gemm_kernel<<<dim3((N + 63) / 64, 4), t256>>>(gB, Wg3, hbuf, N, 128, 256, nullptr, nullptr);
    gcn_init<<<(N * 256 + 255) / 256, t256>>>(hbuf, bg3, dinv, gA, N, 8);
    gcn_edge<<<((E << 8) + 255) / 256, t256>>>(hbuf, src, dst, dinv, gA, E, 8);

    // EdgeConv1: in gA[N,256] -> gB[N,128]
    bn_coef<<<2, t256>>>(e1g, e1b, e1m, e1v, bna, bnb, 512);
    gemm_kernel<<<dim3((N + 63) / 64, 2), t256>>>(gA, e1W, P, N, 256, 128, bna, bnb);
    zero_u32<<<(N * 128 + 255) / 256, t256>>>(Mx, N * 128);
    edgeconv_kernel<<<(E + 31) / 32, t256>>>(gA, src, dst, bna + 256, bnb + 256,
                                             e1W + 256 * 128, Mx, E, 256);
    combine_kernel<<<(N * 128 + 255) / 256, t256>>>(P, Mx, indeg, gB, N);

    // EdgeConv2: in gB[N,128] -> gA[N,128]
    bn_coef<<<1, t256>>>(e2g, e2b, e2m, e2v, bna, bnb, 256);
    gemm_kernel<<<dim3((N + 63) / 64, 2), t256>>>(gB, e2W, P, N, 128, 128, bna, bnb);
    zero_u32<<<(N * 128 + 255) / 256, t256>>>(Mx, N * 128);
    edgeconv_kernel<<<(E + 31) / 32, t256>>>(gB, src, dst, bna + 128, bnb + 128,
                                             e2W + 128 * 128, Mx, E, 128);
    combine_kernel<<<(N * 128 + 255) / 256, t256>>>(P, Mx, indeg, gA, N);

    // EdgeConv3: in gA[N,128] -> gB[N,128]
    bn_coef<<<1, t256>>>(e3g, e3b, e3m, e3v, bna, bnb, 256);
    gemm_kernel<<<dim3((N + 63) / 64, 2), t256>>>(gA, e3W, P, N, 128, 128, bna, bnb);
    zero_u32<<<(N * 128 + 255) / 256, t256>>>(Mx, N * 128);
    edgeconv_kernel<<<(E + 31) / 32, t256>>>(gA, src, dst, bna + 128, bnb + 128,
                                             e3W + 128 * 128, Mx, E, 128);
    combine_kernel<<<(N * 128 + 255) / 256, t256>>>(P, Mx, indeg, gB, N);

    // final FC -> d_out [N,1]
    fc_kernel<<<(N + 7) / 8, t256>>>(gB, Wfc, bfc, (float*)d_out, N);
}

// round 2
// speedup vs baseline: 1.5909x; 1.5909x over previous
#include <cuda_runtime.h>
#include <math.h>

#define NCAP 20000
#define ECAP 320000

// ---------------- static scratch (no allocation allowed) ----------------
static __device__ float    d_x0  [NCAP * 64];
static __device__ float    d_hbuf[NCAP * 256];
static __device__ float    d_gA  [NCAP * 256];
static __device__ float    d_gB  [NCAP * 256];
static __device__ float    d_P   [NCAP * 128];
static __device__ unsigned d_Mx  [NCAP * 128];
static __device__ float    d_dinv[NCAP];
static __device__ int      d_indeg[NCAP];
static __device__ float    d_bna [512];
static __device__ float    d_bnb [512];

// ---------------- helpers ----------------
__device__ __forceinline__ unsigned f2tf32(float x) {
    unsigned y;
    asm("cvt.rna.tf32.f32 %0, %1;" : "=r"(y) : "f"(x));
    return y;
}

__device__ __forceinline__ void mma_tf32(float* d, const unsigned* a, const unsigned* b) {
    asm volatile(
        "mma.sync.aligned.m16n8k8.row.col.f32.tf32.tf32.f32 "
        "{%0,%1,%2,%3}, {%4,%5,%6,%7}, {%8,%9}, {%0,%1,%2,%3};"
        : "+f"(d[0]), "+f"(d[1]), "+f"(d[2]), "+f"(d[3])
        : "r"(a[0]), "r"(a[1]), "r"(a[2]), "r"(a[3]), "r"(b[0]), "r"(b[1]));
}

__device__ __forceinline__ void red_max_enc(unsigned* p, float v) {
    unsigned u = __float_as_uint(v);
    unsigned key = (u & 0x80000000u) ? ~u : (u | 0x80000000u);
    asm volatile("red.global.max.u32 [%0], %1;" :: "l"(p), "r"(key) : "memory");
}

// ---------------- small elementwise kernels ----------------
__global__ void zero_i32(int* p, int n) {
    int i = blockIdx.x * 256 + threadIdx.x;
    if (i < n) p[i] = 0;
}
__global__ void zero_u32(unsigned* p, int n) {
    int i = blockIdx.x * 256 + threadIdx.x;
    if (i < n) p[i] = 0u;
}
__global__ void count_indeg(const int* __restrict__ dstv, int* __restrict__ indeg, int E) {
    int e = blockIdx.x * 256 + threadIdx.x;
    if (e < E) atomicAdd(&indeg[dstv[e]], 1);
}
__global__ void compute_dinv(const int* __restrict__ indeg, float* __restrict__ dinv, int N) {
    int i = blockIdx.x * 256 + threadIdx.x;
    if (i < N) dinv[i] = rsqrtf((float)indeg[i] + 1.0f);
}
__global__ void bn_coef(const float* __restrict__ g, const float* __restrict__ be,
                        const float* __restrict__ me, const float* __restrict__ va,
                        float* __restrict__ a, float* __restrict__ b, int n) {
    int i = blockIdx.x * 256 + threadIdx.x;
    if (i < n) {
        float ai = g[i] * rsqrtf(va[i] + 1e-5f);
        a[i] = ai;
        b[i] = be[i] - me[i] * ai;
    }
}

// ---------------- fused dual-projection GEMM (fp32 SIMT, keeps input precision) ----------------
__global__ __launch_bounds__(256) void proj_kernel(
    const float* __restrict__ A,
    const float* __restrict__ Bm, const float* __restrict__ bm,
    const float* __restrict__ Bc, const float* __restrict__ bc,
    float* __restrict__ C, int Mrows)
{
    const int K = 512;
    __shared__ float As[16][65];
    __shared__ float Bms[16][64];
    __shared__ float Bcs[16][64];
    int tid = threadIdx.x;
    int tx = tid & 15, ty = tid >> 4;
    int row0 = blockIdx.x * 64;
    float acc[4][4] = {};
    for (int k0 = 0; k0 < K; k0 += 16) {
#pragma unroll
        for (int i = 0; i < 4; i++) {
            int lin = tid + i * 256;
            int r = lin >> 4, kk = lin & 15;
            int gr = row0 + r;
            As[kk][r] = (gr < Mrows) ? A[gr * K + k0 + kk] : 0.f;
        }
#pragma unroll
        for (int i = 0; i < 4; i++) {
            int lin = tid + i * 256;
            int kk = lin >> 6, n = lin & 63;
            Bms[kk][n] = Bm[(k0 + kk) * 64 + n];
            Bcs[kk][n] = Bc[(k0 + kk) * 64 + n];
        }
        __syncthreads();
#pragma unroll
        for (int kk = 0; kk < 16; kk++) {
            float4 bmv = *(const float4*)&Bms[kk][tx * 4];
            float4 bcv = *(const float4*)&Bcs[kk][tx * 4];
            float av0 = As[kk][ty * 4 + 0];
            acc[0][0] += av0 * bmv.x; acc[0][1] += av0 * bmv.y;
            acc[0][2] += av0 * bmv.z; acc[0][3] += av0 * bmv.w;
#pragma unroll
            for (int r = 1; r < 4; r++) {
                float av = As[kk][ty * 4 + r];
                acc[r][0] += av * bcv.x; acc[r][1] += av * bcv.y;
                acc[r][2] += av * bcv.z; acc[r][3] += av * bcv.w;
            }
        }
        __syncthreads();
    }
#pragma unroll
    for (int r = 0; r < 4; r++) {
        int gr = row0 + ty * 4 + r;
        if (gr < Mrows) {
#pragma unroll
            for (int c = 0; c < 4; c++) {
                float bias = (r == 0) ? bm[tx * 4 + c] : bc[tx * 4 + c];
                C[gr * 64 + tx * 4 + c] = acc[r][c] + bias;
            }
        }
    }
}

// ---------------- TF32 tensor-core node GEMM ----------------
// C = f(A) @ B  (f optional BN->ReLU via ta/tb), optional GCN epilogue:
//   out2 = bias + dinv[i]^2 * C  (raw C also stored -- needed by the edge scatter)
// tile: 64 rows x 64 cols, 256 threads = 8 warps (warp grid 4x2), K chunks of 32.
__global__ __launch_bounds__(256) void gemm_tc(
    const float* __restrict__ A, const float* __restrict__ B, float* __restrict__ C,
    int M, int K, int Ncols,
    const float* __restrict__ ta, const float* __restrict__ tb,
    const float* __restrict__ bias, const float* __restrict__ dinv,
    float* __restrict__ out2)
{
    __shared__ unsigned As[64 * 36];   // stride 36 -> conflict-free frag loads
    __shared__ unsigned Bs[32 * 72];   // stride 72
    int tid = threadIdx.x;
    int lane = tid & 31, warp = tid >> 5;
    int wm = warp & 3, wn = warp >> 2;
    int gid = lane >> 2, tig = lane & 3;
    int row0 = blockIdx.x * 64;
    int col0 = blockIdx.y * 64;
    float acc[4][4] = {};
    for (int k0 = 0; k0 < K; k0 += 32) {
#pragma unroll
        for (int i = 0; i < 8; i++) {
            int lin = tid + i * 256;
            int r = lin >> 5, k = lin & 31;
            int gr = row0 + r;
            float v = 0.f;
            if (gr < M) {
                v = A[gr * K + k0 + k];
                if (ta) {
                    int kk = k0 + k;
                    v = fmaxf(ta[kk] * v + tb[kk], 0.f);
                }
            }
            As[r * 36 + k] = f2tf32(v);
        }
#pragma unroll
        for (int i = 0; i < 8; i++) {
            int lin = tid + i * 256;
            int k = lin >> 6, n = lin & 63;
            Bs[k * 72 + n] = f2tf32(B[(k0 + k) * Ncols + col0 + n]);
        }
        __syncthreads();
#pragma unroll
        for (int s = 0; s < 4; s++) {
            unsigned a[4];
            int ar = wm * 16 + gid;
            int ac = s * 8 + tig;
            a[0] = As[ar * 36 + ac];
            a[1] = As[(ar + 8) * 36 + ac];
            a[2] = As[ar * 36 + ac + 4];
            a[3] = As[(ar + 8) * 36 + ac + 4];
#pragma unroll
            for (int nt = 0; nt < 4; nt++) {
                unsigned b[2];
                int bc = wn * 32 + nt * 8 + gid;
                b[0] = Bs[(s * 8 + tig) * 72 + bc];
                b[1] = Bs[(s * 8 + tig + 4) * 72 + bc];
                mma_tf32(acc[nt], a, b);
            }
        }
        __syncthreads();
    }
#pragma unroll
    for (int half = 0; half < 2; half++) {
        int gr = row0 + wm * 16 + gid + half * 8;
        if (gr < M) {
            float di2 = 0.f;
            if (out2) { float di = dinv[gr]; di2 = di * di; }
#pragma unroll
            for (int nt = 0; nt < 4; nt++) {
                int col = col0 + wn * 32 + nt * 8 + tig * 2;
                float v0 = acc[nt][half * 2 + 0];
                float v1 = acc[nt][half * 2 + 1];
                C[gr * Ncols + col] = v0;
                C[gr * Ncols + col + 1] = v1;
                if (out2) {
                    out2[gr * Ncols + col]     = bias[col]     + di2 * v0;
                    out2[gr * Ncols + col + 1] = bias[col + 1] + di2 * v1;
                }
            }
        }
    }
}

// ---------------- GCN edge scatter: vectorized red.global.add.v4.f32 ----------------
__global__ void gcn_edge_v4(const float* __restrict__ h, const int* __restrict__ src,
                            const int* __restrict__ dstv, const float* __restrict__ dinv,
                            float* __restrict__ out, int E, int lc)
{
    int qpr = 1 << (lc - 2);                // float4s per row
    long long idx = (long long)blockIdx.x * 256 + threadIdx.x;
    if (idx >= (long long)E * qpr) return;
    int e  = (int)(idx >> (lc - 2));
    int j4 = ((int)idx & (qpr - 1)) << 2;
    int s = src[e], d = dstv[e];
    float coef = dinv[s] * dinv[d];
    float4 hv = *(const float4*)&h[((long long)s << lc) + j4];
    float* ptr = &out[((long long)d << lc) + j4];
    asm volatile("red.global.add.v4.f32 [%0], {%1,%2,%3,%4};"
                 :: "l"(ptr), "f"(hv.x * coef), "f"(hv.y * coef),
                    "f"(hv.z * coef), "f"(hv.w * coef) : "memory");
}

// ---------------- EdgeConv edge GEMM (TF32 mma) + atomicMax scatter ----------------
// Per edge: q[k] = relu(a2[k]*(g[src,k]-g[dst,k])+b2[k]);  m = q @ Wb [C x 128]
// tile: 64 edges x 128 cols, 256 threads (warp grid 4x2, 16 edges x 64 cols per warp)
__global__ __launch_bounds__(256) void edgeconv_tc(
    const float* __restrict__ g, const int* __restrict__ src, const int* __restrict__ dstv,
    const float* __restrict__ a2, const float* __restrict__ b2,
    const float* __restrict__ Wb, unsigned* __restrict__ Mout, int E, int C)
{
    __shared__ unsigned qs[64 * 36];     // stride 36
    __shared__ unsigned ws[32 * 136];    // stride 136 -> conflict-free B frag loads
    __shared__ int ss[64], sd[64];
    int tid = threadIdx.x;
    int e0 = blockIdx.x * 64;
    if (tid < 64) {
        int e = e0 + tid;
        if (e >= E) e = E - 1;
        ss[tid] = src[e];
        sd[tid] = dstv[e];
    }
    __syncthreads();
    int lane = tid & 31, warp = tid >> 5;
    int wm = warp & 3, wn = warp >> 2;
    int gid = lane >> 2, tig = lane & 3;
    float acc[8][4] = {};
    for (int k0 = 0; k0 < C; k0 += 32) {
#pragma unroll
        for (int i = 0; i < 8; i++) {
            int lin = tid + i * 256;
            int e = lin >> 5, k = lin & 31;
            int kk = k0 + k;
            float gs = g[ss[e] * C + kk];
            float gd = g[sd[e] * C + kk];
            float q = fmaxf(a2[kk] * (gs - gd) + b2[kk], 0.f);
            qs[e * 36 + k] = f2tf32(q);
        }
#pragma unroll
        for (int i = 0; i < 16; i++) {
            int lin = tid + i * 256;
            int k = lin >> 7, n = lin & 127;
            ws[k * 136 + n] = f2tf32(Wb[(k0 + k) * 128 + n]);
        }
        __syncthreads();
#pragma unroll
        for (int s = 0; s < 4; s++) {
            unsigned a[4];
            int ar = wm * 16 + gid;
            int ac = s * 8 + tig;
            a[0] = qs[ar * 36 + ac];
            a[1] = qs[(ar + 8) * 36 + ac];
            a[2] = qs[ar * 36 + ac + 4];
            a[3] = qs[(ar + 8) * 36 + ac + 4];
#pragma unroll
            for (int nt = 0; nt < 8; nt++) {
                unsigned b[2];
                int bc = wn * 64 + nt * 8 + gid;
                b[0] = ws[(s * 8 + tig) * 136 + bc];
                b[1] = ws[(s * 8 + tig + 4) * 136 + bc];
                mma_tf32(acc[nt], a, b);
            }
        }
        __syncthreads();
    }
#pragma unroll
    for (int half = 0; half < 2; half++) {
        int el = wm * 16 + gid + half * 8;
        int e = e0 + el;
        if (e < E) {
            unsigned* base = Mout + (long long)sd[el] * 128;
#pragma unroll
            for (int nt = 0; nt < 8; nt++) {
                int col = wn * 64 + nt * 8 + tig * 2;
                red_max_enc(base + col,     acc[nt][half * 2 + 0]);
                red_max_enc(base + col + 1, acc[nt][half * 2 + 1]);
            }
        }
    }
}

// ---------------- EdgeConv combine: out = indeg>0 ? P + decode(M) : 0 ----------------
__global__ void combine_kernel(const float* __restrict__ P, const unsigned* __restrict__ Mv,
                               const int* __restrict__ indeg, float* __restrict__ out, int N)
{
    int idx = blockIdx.x * 256 + threadIdx.x;
    if (idx >= N * 128) return;
    int i = idx >> 7;
    float v = 0.f;
    if (indeg[i] > 0) {
        unsigned k = Mv[idx];
        unsigned u = (k & 0x80000000u) ? (k & 0x7fffffffu) : ~k;
        v = P[idx] + __uint_as_float(u);
    }
    out[idx] = v;
}

// ---------------- final FC ----------------
__global__ void fc_kernel(const float* __restrict__ h, const float* __restrict__ W,
                          const float* __restrict__ b, float* __restrict__ out, int N)
{
    int warp = (blockIdx.x * 256 + threadIdx.x) >> 5;
    int lane = threadIdx.x & 31;
    if (warp >= N) return;
    float s = 0.f;
#pragma unroll
    for (int j = lane; j < 128; j += 32) s += h[warp * 128 + j] * W[j];
#pragma unroll
    for (int o = 16; o; o >>= 1) s += __shfl_down_sync(0xffffffffu, s, o);
    if (lane == 0) out[warp] = s + b[0];
}

// ---------------- launch ----------------
extern "C" void kernel_launch(void* const* d_in, const int* in_sizes, int n_in,
                              void* d_out, int out_size)
{
    const float* x   = (const float*)d_in[0];
    const int*   ei  = (const int*)d_in[1];
    const float* Wm  = (const float*)d_in[2];
    const float* bm  = (const float*)d_in[3];
    const float* Wc  = (const float*)d_in[4];
    const float* bc  = (const float*)d_in[5];
    const float* Wg1 = (const float*)d_in[6];
    const float* bg1 = (const float*)d_in[7];
    const float* Wg2 = (const float*)d_in[8];
    const float* bg2 = (const float*)d_in[9];
    const float* Wg3 = (const float*)d_in[10];
    const float* bg3 = (const float*)d_in[11];
    const float* e1g = (const float*)d_in[12];
    const float* e1b = (const float*)d_in[13];
    const float* e1m = (const float*)d_in[14];
    const float* e1v = (const float*)d_in[15];
    const float* e1W = (const float*)d_in[16];
    const float* e2g = (const float*)d_in[17];
    const float* e2b = (const float*)d_in[18];
    const float* e2m = (const float*)d_in[19];
    const float* e2v = (const float*)d_in[20];
    const float* e2W = (const float*)d_in[21];
    const float* e3g = (const float*)d_in[22];
    const float* e3b = (const float*)d_in[23];
    const float* e3m = (const float*)d_in[24];
    const float* e3v = (const float*)d_in[25];
    const float* e3W = (const float*)d_in[26];
    const float* Wfc = (const float*)d_in[27];
    const float* bfc = (const float*)d_in[28];

    int N = in_sizes[0] / 512;
    int E = in_sizes[1] / 2;
    const int* src = ei;
    const int* dst = ei + E;

    float *x0, *hbuf, *gA, *gB, *P, *dinv, *bna, *bnb;
    unsigned* Mx;
    int* indeg;
    cudaGetSymbolAddress((void**)&x0,   d_x0);
    cudaGetSymbolAddress((void**)&hbuf, d_hbuf);
    cudaGetSymbolAddress((void**)&gA,   d_gA);
    cudaGetSymbolAddress((void**)&gB,   d_gB);
    cudaGetSymbolAddress((void**)&P,    d_P);
    cudaGetSymbolAddress((void**)&Mx,   d_Mx);
    cudaGetSymbolAddress((void**)&dinv, d_dinv);
    cudaGetSymbolAddress((void**)&indeg,d_indeg);
    cudaGetSymbolAddress((void**)&bna,  d_bna);
    cudaGetSymbolAddress((void**)&bnb,  d_bnb);

    dim3 t256(256);
    int mb = (N + 63) / 64;

    // input projection (fused row-select), fp32
    proj_kernel<<<mb, t256>>>(x, Wm, bm, Wc, bc, x0, N);

    // degrees
    zero_i32<<<(N + 255) / 256, t256>>>(indeg, N);
    count_indeg<<<(E + 255) / 256, t256>>>(dst, indeg, E);
    compute_dinv<<<(N + 255) / 256, t256>>>(indeg, dinv, N);

    // GCN1: x0[N,64] @ Wg1[64,128] -> hbuf (raw), gA = bg1 + dinv^2*hbuf
    gemm_tc<<<dim3(mb, 2), t256>>>(x0, Wg1, hbuf, N, 64, 128, nullptr, nullptr, bg1, dinv, gA);
    gcn_edge_v4<<<(E * 32 + 255) / 256, t256>>>(hbuf, src, dst, dinv, gA, E, 7);

    // GCN2
    gemm_tc<<<dim3(mb, 2), t256>>>(gA, Wg2, hbuf, N, 128, 128, nullptr, nullptr, bg2, dinv, gB);
    gcn_edge_v4<<<(E * 32 + 255) / 256, t256>>>(hbuf, src, dst, dinv, gB, E, 7);

    // GCN3 (out 256)
    gemm_tc<<<dim3(mb, 4), t256>>>(gB, Wg3, hbuf, N, 128, 256, nullptr, nullptr, bg3, dinv, gA);
    gcn_edge_v4<<<(E * 64 + 255) / 256, t256>>>(hbuf, src, dst, dinv, gA, E, 8);

    // EdgeConv1: gA[N,256] -> gB[N,128]
    bn_coef<<<2, t256>>>(e1g, e1b, e1m, e1v, bna, bnb, 512);
    gemm_tc<<<dim3(mb, 2), t256>>>(gA, e1W, P, N, 256, 128, bna, bnb, nullptr, nullptr, nullptr);
    zero_u32<<<(N * 128 + 255) / 256, t256>>>(Mx, N * 128);
    edgeconv_tc<<<(E + 63) / 64, t256>>>(gA, src, dst, bna + 256, bnb + 256,
                                         e1W + 256 * 128, Mx, E, 256);
    combine_kernel<<<(N * 128 + 255) / 256, t256>>>(P, Mx, indeg, gB, N);

    // EdgeConv2: gB[N,128] -> gA[N,128]
    bn_coef<<<1, t256>>>(e2g, e2b, e2m, e2v, bna, bnb, 256);
    gemm_tc<<<dim3(mb, 2), t256>>>(gB, e2W, P, N, 128, 128, bna, bnb, nullptr, nullptr, nullptr);
    zero_u32<<<(N * 128 + 255) / 256, t256>>>(Mx, N * 128);
    edgeconv_tc<<<(E + 63) / 64, t256>>>(gB, src, dst, bna + 128, bnb + 128,
                                         e2W + 128 * 128, Mx, E, 128);
    combine_kernel<<<(N * 128 + 255) / 256, t256>>>(P, Mx, indeg, gA, N);

    // EdgeConv3: gA[N,128] -> gB[N,128]
    bn_coef<<<1, t256>>>(e3g, e3b, e3m, e3v, bna, bnb, 256);
    gemm_tc<<<dim3(mb, 2), t256>>>(gA, e3W, P, N, 128, 128, bna, bnb, nullptr, nullptr, nullptr);
    zero_u32<<<(N * 128 + 255) / 256, t256>>>(Mx, N * 128);
    edgeconv_tc<<<(E + 63) / 64, t256>>>(gA, src, dst, bna + 128, bnb + 128,
                                         e3W + 128 * 128, Mx, E, 128);
    combine_kernel<<<(N * 128 + 255) / 256, t256>>>(P, Mx, indeg, gB, N);

    // final FC -> d_out [N,1]
    fc_kernel<<<(N + 7) / 8, t256>>>(gB, Wfc, bfc, (float*)d_out, N);
}

// round 3
// speedup vs baseline: 1.8925x; 1.1896x over previous
#include <cuda_runtime.h>
#include <math.h>

#define NCAP 20000
#define ECAP 320000

// ---------------- static scratch (no allocation allowed) ----------------
static __device__ float    d_x0  [NCAP * 64];
static __device__ float    d_hbuf[NCAP * 256];
static __device__ float    d_gA  [NCAP * 256];
static __device__ float    d_gB  [NCAP * 256];
static __device__ float    d_P   [NCAP * 128];
static __device__ unsigned d_Mx  [NCAP * 128];
static __device__ float    d_dinv[NCAP];
static __device__ int      d_indeg[NCAP];
static __device__ int      d_start[NCAP + 1];
static __device__ int      d_cnt  [NCAP];
static __device__ int      d_ssrc [ECAP];
static __device__ int      d_sdst [ECAP];
static __device__ float    d_bna [512];
static __device__ float    d_bnb [512];

// ---------------- helpers ----------------
__device__ __forceinline__ unsigned f2tf32(float x) {
    unsigned y;
    asm("cvt.rna.tf32.f32 %0, %1;" : "=r"(y) : "f"(x));
    return y;
}

__device__ __forceinline__ void mma_tf32(float* d, const unsigned* a, const unsigned* b) {
    asm volatile(
        "mma.sync.aligned.m16n8k8.row.col.f32.tf32.tf32.f32 "
        "{%0,%1,%2,%3}, {%4,%5,%6,%7}, {%8,%9}, {%0,%1,%2,%3};"
        : "+f"(d[0]), "+f"(d[1]), "+f"(d[2]), "+f"(d[3])
        : "r"(a[0]), "r"(a[1]), "r"(a[2]), "r"(a[3]), "r"(b[0]), "r"(b[1]));
}

__device__ __forceinline__ void red_max_enc(unsigned* p, float v) {
    unsigned u = __float_as_uint(v);
    unsigned key = (u & 0x80000000u) ? ~u : (u | 0x80000000u);
    asm volatile("red.global.max.u32 [%0], %1;" :: "l"(p), "r"(key) : "memory");
}

// ---------------- small elementwise kernels ----------------
__global__ void zero_i32(int* p, int n) {
    int i = blockIdx.x * 256 + threadIdx.x;
    if (i < n) p[i] = 0;
}
__global__ void zero_u32(unsigned* p, int n) {
    int i = blockIdx.x * 256 + threadIdx.x;
    if (i < n) p[i] = 0u;
}
__global__ void count_indeg(const int* __restrict__ dstv, int* __restrict__ indeg, int E) {
    int e = blockIdx.x * 256 + threadIdx.x;
    if (e < E) atomicAdd(&indeg[dstv[e]], 1);
}
__global__ void compute_dinv(const int* __restrict__ indeg, float* __restrict__ dinv, int N) {
    int i = blockIdx.x * 256 + threadIdx.x;
    if (i < N) dinv[i] = rsqrtf((float)indeg[i] + 1.0f);
}
__global__ void bn_coef(const float* __restrict__ g, const float* __restrict__ be,
                        const float* __restrict__ me, const float* __restrict__ va,
                        float* __restrict__ a, float* __restrict__ b, int n) {
    int i = blockIdx.x * 256 + threadIdx.x;
    if (i < n) {
        float ai = g[i] * rsqrtf(va[i] + 1e-5f);
        a[i] = ai;
        b[i] = be[i] - me[i] * ai;
    }
}

// ---------------- exclusive scan over indeg -> start (single block, 1024 thr) ----------------
__global__ __launch_bounds__(1024) void scan_kernel(const int* __restrict__ indeg,
                                                    int* __restrict__ start, int N) {
    __shared__ int wsum[32];
    int t = threadIdx.x;
    int chunk = (N + 1023) / 1024;
    int lo = t * chunk;
    int hi = lo + chunk; if (hi > N) hi = N; if (lo > N) lo = N;
    int s = 0;
    for (int i = lo; i < hi; i++) s += indeg[i];
    int lane = t & 31, w = t >> 5;
    int v = s;
#pragma unroll
    for (int o = 1; o < 32; o <<= 1) {
        int u = __shfl_up_sync(0xffffffffu, v, o);
        if (lane >= o) v += u;
    }
    if (lane == 31) wsum[w] = v;
    __syncthreads();
    if (w == 0) {
        int x = wsum[lane];
#pragma unroll
        for (int o = 1; o < 32; o <<= 1) {
            int u = __shfl_up_sync(0xffffffffu, x, o);
            if (lane >= o) x += u;
        }
        wsum[lane] = x;
    }
    __syncthreads();
    int excl = (v - s) + (w > 0 ? wsum[w - 1] : 0);
    int run = excl;
    for (int i = lo; i < hi; i++) { start[i] = run; run += indeg[i]; }
    if (t == 1023) start[N] = run;
}

// ---------------- counting-sort scatter: edges sorted by dst ----------------
__global__ void scatter_edges(const int* __restrict__ src, const int* __restrict__ dstv,
                              const int* __restrict__ start, int* __restrict__ cnt,
                              int* __restrict__ ssrc, int* __restrict__ sdst, int E) {
    int e = blockIdx.x * 256 + threadIdx.x;
    if (e < E) {
        int d = dstv[e];
        int p = start[d] + atomicAdd(&cnt[d], 1);
        ssrc[p] = src[e];
        sdst[p] = d;
    }
}

// ---------------- fused dual-projection GEMM (fp32 SIMT) ----------------
__global__ __launch_bounds__(256) void proj_kernel(
    const float* __restrict__ A,
    const float* __restrict__ Bm, const float* __restrict__ bm,
    const float* __restrict__ Bc, const float* __restrict__ bc,
    float* __restrict__ C, int Mrows)
{
    const int K = 512;
    __shared__ float As[16][65];
    __shared__ float Bms[16][64];
    __shared__ float Bcs[16][64];
    int tid = threadIdx.x;
    int tx = tid & 15, ty = tid >> 4;
    int row0 = blockIdx.x * 64;
    float acc[4][4] = {};
    for (int k0 = 0; k0 < K; k0 += 16) {
#pragma unroll
        for (int i = 0; i < 4; i++) {
            int lin = tid + i * 256;
            int r = lin >> 4, kk = lin & 15;
            int gr = row0 + r;
            As[kk][r] = (gr < Mrows) ? A[gr * K + k0 + kk] : 0.f;
        }
#pragma unroll
        for (int i = 0; i < 4; i++) {
            int lin = tid + i * 256;
            int kk = lin >> 6, n = lin & 63;
            Bms[kk][n] = Bm[(k0 + kk) * 64 + n];
            Bcs[kk][n] = Bc[(k0 + kk) * 64 + n];
        }
        __syncthreads();
#pragma unroll
        for (int kk = 0; kk < 16; kk++) {
            float4 bmv = *(const float4*)&Bms[kk][tx * 4];
            float4 bcv = *(const float4*)&Bcs[kk][tx * 4];
            float av0 = As[kk][ty * 4 + 0];
            acc[0][0] += av0 * bmv.x; acc[0][1] += av0 * bmv.y;
            acc[0][2] += av0 * bmv.z; acc[0][3] += av0 * bmv.w;
#pragma unroll
            for (int r = 1; r < 4; r++) {
                float av = As[kk][ty * 4 + r];
                acc[r][0] += av * bcv.x; acc[r][1] += av * bcv.y;
                acc[r][2] += av * bcv.z; acc[r][3] += av * bcv.w;
            }
        }
        __syncthreads();
    }
#pragma unroll
    for (int r = 0; r < 4; r++) {
        int gr = row0 + ty * 4 + r;
        if (gr < Mrows) {
#pragma unroll
            for (int c = 0; c < 4; c++) {
                float bias = (r == 0) ? bm[tx * 4 + c] : bc[tx * 4 + c];
                C[gr * 64 + tx * 4 + c] = acc[r][c] + bias;
            }
        }
    }
}

// ---------------- TF32 tensor-core node GEMM: C = f(A) @ B ----------------
__global__ __launch_bounds__(256) void gemm_tc(
    const float* __restrict__ A, const float* __restrict__ B, float* __restrict__ C,
    int M, int K, int Ncols,
    const float* __restrict__ ta, const float* __restrict__ tb)
{
    __shared__ unsigned As[64 * 36];
    __shared__ unsigned Bs[32 * 72];
    int tid = threadIdx.x;
    int lane = tid & 31, warp = tid >> 5;
    int wm = warp & 3, wn = warp >> 2;
    int gid = lane >> 2, tig = lane & 3;
    int row0 = blockIdx.x * 64;
    int col0 = blockIdx.y * 64;
    float acc[4][4] = {};
    for (int k0 = 0; k0 < K; k0 += 32) {
#pragma unroll
        for (int i = 0; i < 8; i++) {
            int lin = tid + i * 256;
            int r = lin >> 5, k = lin & 31;
            int gr = row0 + r;
            float v = 0.f;
            if (gr < M) {
                v = A[gr * K + k0 + k];
                if (ta) {
                    int kk = k0 + k;
                    v = fmaxf(ta[kk] * v + tb[kk], 0.f);
                }
            }
            As[r * 36 + k] = f2tf32(v);
        }
#pragma unroll
        for (int i = 0; i < 8; i++) {
            int lin = tid + i * 256;
            int k = lin >> 6, n = lin & 63;
            Bs[k * 72 + n] = f2tf32(B[(k0 + k) * Ncols + col0 + n]);
        }
        __syncthreads();
#pragma unroll
        for (int s = 0; s < 4; s++) {
            unsigned a[4];
            int ar = wm * 16 + gid;
            int ac = s * 8 + tig;
            a[0] = As[ar * 36 + ac];
            a[1] = As[(ar + 8) * 36 + ac];
            a[2] = As[ar * 36 + ac + 4];
            a[3] = As[(ar + 8) * 36 + ac + 4];
#pragma unroll
            for (int nt = 0; nt < 4; nt++) {
                unsigned b[2];
                int bc = wn * 32 + nt * 8 + gid;
                b[0] = Bs[(s * 8 + tig) * 72 + bc];
                b[1] = Bs[(s * 8 + tig + 4) * 72 + bc];
                mma_tf32(acc[nt], a, b);
            }
        }
        __syncthreads();
    }
#pragma unroll
    for (int half = 0; half < 2; half++) {
        int gr = row0 + wm * 16 + gid + half * 8;
        if (gr < M) {
#pragma unroll
            for (int nt = 0; nt < 4; nt++) {
                int col = col0 + wn * 32 + nt * 8 + tig * 2;
                C[gr * Ncols + col]     = acc[nt][half * 2 + 0];
                C[gr * Ncols + col + 1] = acc[nt][half * 2 + 1];
            }
        }
    }
}

// ---------------- GCN aggregation: gather over CSR (no atomics) ----------------
// out[i] = bias + dinv[i]^2 * h[i] + sum_{e in in(i)} dinv[s]*dinv[i] * h[s]
__global__ __launch_bounds__(256) void gcn_gather(
    const float* __restrict__ h, const int* __restrict__ ssrc,
    const int* __restrict__ start, const float* __restrict__ dinv,
    const float* __restrict__ bias, float* __restrict__ out, int N, int lc)
{
    int node = blockIdx.x * 8 + (threadIdx.x >> 5);
    int lane = threadIdx.x & 31;
    if (node >= N) return;
    int groups = 1 << (lc - 7);          // 1 (128 cols) or 2 (256 cols)
    float di = dinv[node];
    float di2 = di * di;
    float4 acc[2];
#pragma unroll
    for (int j = 0; j < 2; j++) {
        if (j < groups) {
            int col = j * 128 + lane * 4;
            float4 hv = *(const float4*)&h[((long long)node << lc) + col];
            float4 bv = *(const float4*)&bias[col];
            acc[j].x = bv.x + di2 * hv.x;
            acc[j].y = bv.y + di2 * hv.y;
            acc[j].z = bv.z + di2 * hv.z;
            acc[j].w = bv.w + di2 * hv.w;
        }
    }
    int s0 = start[node], s1 = start[node + 1];
    for (int e = s0; e < s1; e++) {
        int s = ssrc[e];
        float coef = dinv[s] * di;
        const float* hrow = &h[(long long)s << lc];
#pragma unroll
        for (int j = 0; j < 2; j++) {
            if (j < groups) {
                float4 hv = *(const float4*)&hrow[j * 128 + lane * 4];
                acc[j].x += coef * hv.x;
                acc[j].y += coef * hv.y;
                acc[j].z += coef * hv.z;
                acc[j].w += coef * hv.w;
            }
        }
    }
#pragma unroll
    for (int j = 0; j < 2; j++) {
        if (j < groups)
            *(float4*)&out[((long long)node << lc) + j * 128 + lane * 4] = acc[j];
    }
}

// ---------------- EdgeConv edge GEMM (TF32) over dst-sorted edges + segmented max ----------------
// smem: sh = qs [64*36] ++ ws [32*136]; reused as sacc [32*132] for the reduce passes.
__global__ __launch_bounds__(256) void edgeconv_tc(
    const float* __restrict__ g, const int* __restrict__ ssrc, const int* __restrict__ sdstv,
    const float* __restrict__ a2, const float* __restrict__ b2,
    const float* __restrict__ Wb, unsigned* __restrict__ Mout, int E, int C)
{
    __shared__ unsigned sh[64 * 36 + 32 * 136];
    __shared__ int ss[64], sd[64];
    unsigned* qs = sh;
    unsigned* ws = sh + 64 * 36;
    float* sacc = (float*)sh;           // 32*132 floats, reused after mma loop
    int tid = threadIdx.x;
    int e0 = blockIdx.x * 64;
    if (tid < 64) {
        int e = e0 + tid;
        if (e >= E) e = E - 1;
        ss[tid] = ssrc[e];
        sd[tid] = sdstv[e];
    }
    __syncthreads();
    int lane = tid & 31, warp = tid >> 5;
    int wm = warp & 3, wn = warp >> 2;
    int gid = lane >> 2, tig = lane & 3;
    float acc[8][4] = {};
    for (int k0 = 0; k0 < C; k0 += 32) {
#pragma unroll
        for (int i = 0; i < 8; i++) {
            int lin = tid + i * 256;
            int e = lin >> 5, k = lin & 31;
            int kk = k0 + k;
            float gs = g[ss[e] * C + kk];
            float gd = g[sd[e] * C + kk];
            float q = fmaxf(a2[kk] * (gs - gd) + b2[kk], 0.f);
            qs[e * 36 + k] = f2tf32(q);
        }
#pragma unroll
        for (int i = 0; i < 16; i++) {
            int lin = tid + i * 256;
            int k = lin >> 7, n = lin & 127;
            ws[k * 136 + n] = f2tf32(Wb[(k0 + k) * 128 + n]);
        }
        __syncthreads();
#pragma unroll
        for (int s = 0; s < 4; s++) {
            unsigned a[4];
            int ar = wm * 16 + gid;
            int ac = s * 8 + tig;
            a[0] = qs[ar * 36 + ac];
            a[1] = qs[(ar + 8) * 36 + ac];
            a[2] = qs[ar * 36 + ac + 4];
            a[3] = qs[(ar + 8) * 36 + ac + 4];
#pragma unroll
            for (int nt = 0; nt < 8; nt++) {
                unsigned b[2];
                int bc = wn * 64 + nt * 8 + gid;
                b[0] = ws[(s * 8 + tig) * 136 + bc];
                b[1] = ws[(s * 8 + tig + 4) * 136 + bc];
                mma_tf32(acc[nt], a, b);
            }
        }
        __syncthreads();
    }
    // segmented max over dst-sorted rows, two passes of 32 rows (smem reuse)
#pragma unroll
    for (int pass = 0; pass < 2; pass++) {
        if ((wm >> 1) == pass) {
#pragma unroll
            for (int half = 0; half < 2; half++) {
                int rl = (wm & 1) * 16 + gid + half * 8;    // 0..31
#pragma unroll
                for (int nt = 0; nt < 8; nt++) {
                    int col = wn * 64 + nt * 8 + tig * 2;
                    sacc[rl * 132 + col]     = acc[nt][half * 2 + 0];
                    sacc[rl * 132 + col + 1] = acc[nt][half * 2 + 1];
                }
            }
        }
        __syncthreads();
        {
            int col = tid & 127;
            int rh = tid >> 7;                  // 0..1
            int r0 = rh * 16, r1 = r0 + 16;
            int cur = sd[pass * 32 + r0];
            float m = sacc[r0 * 132 + col];
            for (int r = r0 + 1; r < r1; r++) {
                int d = sd[pass * 32 + r];
                float v = sacc[r * 132 + col];
                if (d != cur) {
                    red_max_enc(&Mout[(long long)cur * 128 + col], m);
                    cur = d;
                    m = v;
                } else {
                    m = fmaxf(m, v);
                }
            }
            red_max_enc(&Mout[(long long)cur * 128 + col], m);
        }
        __syncthreads();
    }
}

// ---------------- EdgeConv combine: out = indeg>0 ? P + decode(M) : 0 ----------------
__global__ void combine_kernel(const float* __restrict__ P, const unsigned* __restrict__ Mv,
                               const int* __restrict__ indeg, float* __restrict__ out, int N)
{
    int idx = blockIdx.x * 256 + threadIdx.x;
    if (idx >= N * 128) return;
    int i = idx >> 7;
    float v = 0.f;
    if (indeg[i] > 0) {
        unsigned k = Mv[idx];
        unsigned u = (k & 0x80000000u) ? (k & 0x7fffffffu) : ~k;
        v = P[idx] + __uint_as_float(u);
    }
    out[idx] = v;
}

// ---------------- final FC ----------------
__global__ void fc_kernel(const float* __restrict__ h, const float* __restrict__ W,
                          const float* __restrict__ b, float* __restrict__ out, int N)
{
    int warp = (blockIdx.x * 256 + threadIdx.x) >> 5;
    int lane = threadIdx.x & 31;
    if (warp >= N) return;
    float s = 0.f;
#pragma unroll
    for (int j = lane; j < 128; j += 32) s += h[warp * 128 + j] * W[j];
#pragma unroll
    for (int o = 16; o; o >>= 1) s += __shfl_down_sync(0xffffffffu, s, o);
    if (lane == 0) out[warp] = s + b[0];
}

// ---------------- launch ----------------
extern "C" void kernel_launch(void* const* d_in, const int* in_sizes, int n_in,
                              void* d_out, int out_size)
{
    const float* x   = (const float*)d_in[0];
    const int*   ei  = (const int*)d_in[1];
    const float* Wm  = (const float*)d_in[2];
    const float* bm  = (const float*)d_in[3];
    const float* Wc  = (const float*)d_in[4];
    const float* bc  = (const float*)d_in[5];
    const float* Wg1 = (const float*)d_in[6];
    const float* bg1 = (const float*)d_in[7];
    const float* Wg2 = (const float*)d_in[8];
    const float* bg2 = (const float*)d_in[9];
    const float* Wg3 = (const float*)d_in[10];
    const float* bg3 = (const float*)d_in[11];
    const float* e1g = (const float*)d_in[12];
    const float* e1b = (const float*)d_in[13];
    const float* e1m = (const float*)d_in[14];
    const float* e1v = (const float*)d_in[15];
    const float* e1W = (const float*)d_in[16];
    const float* e2g = (const float*)d_in[17];
    const float* e2b = (const float*)d_in[18];
    const float* e2m = (const float*)d_in[19];
    const float* e2v = (const float*)d_in[20];
    const float* e2W = (const float*)d_in[21];
    const float* e3g = (const float*)d_in[22];
    const float* e3b = (const float*)d_in[23];
    const float* e3m = (const float*)d_in[24];
    const float* e3v = (const float*)d_in[25];
    const float* e3W = (const float*)d_in[26];
    const float* Wfc = (const float*)d_in[27];
    const float* bfc = (const float*)d_in[28];

    int N = in_sizes[0] / 512;
    int E = in_sizes[1] / 2;
    const int* src = ei;
    const int* dst = ei + E;

    float *x0, *hbuf, *gA, *gB, *P, *dinv, *bna, *bnb;
    unsigned* Mx;
    int *indeg, *startp, *cnt, *ssrc, *sdst;
    cudaGetSymbolAddress((void**)&x0,    d_x0);
    cudaGetSymbolAddress((void**)&hbuf,  d_hbuf);
    cudaGetSymbolAddress((void**)&gA,    d_gA);
    cudaGetSymbolAddress((void**)&gB,    d_gB);
    cudaGetSymbolAddress((void**)&P,     d_P);
    cudaGetSymbolAddress((void**)&Mx,    d_Mx);
    cudaGetSymbolAddress((void**)&dinv,  d_dinv);
    cudaGetSymbolAddress((void**)&indeg, d_indeg);
    cudaGetSymbolAddress((void**)&startp,d_start);
    cudaGetSymbolAddress((void**)&cnt,   d_cnt);
    cudaGetSymbolAddress((void**)&ssrc,  d_ssrc);
    cudaGetSymbolAddress((void**)&sdst,  d_sdst);
    cudaGetSymbolAddress((void**)&bna,   d_bna);
    cudaGetSymbolAddress((void**)&bnb,   d_bnb);

    dim3 t256(256);
    int mb = (N + 63) / 64;

    // input projection (fused row-select), fp32
    proj_kernel<<<mb, t256>>>(x, Wm, bm, Wc, bc, x0, N);

    // degrees + CSR sort by dst
    zero_i32<<<(N + 255) / 256, t256>>>(indeg, N);
    count_indeg<<<(E + 255) / 256, t256>>>(dst, indeg, E);
    compute_dinv<<<(N + 255) / 256, t256>>>(indeg, dinv, N);
    scan_kernel<<<1, 1024>>>(indeg, startp, N);
    zero_i32<<<(N + 255) / 256, t256>>>(cnt, N);
    scatter_edges<<<(E + 255) / 256, t256>>>(src, dst, startp, cnt, ssrc, sdst, E);

    // GCN1: x0[N,64] @ Wg1[64,128] -> hbuf; gather -> gA
    gemm_tc<<<dim3(mb, 2), t256>>>(x0, Wg1, hbuf, N, 64, 128, nullptr, nullptr);
    gcn_gather<<<(N + 7) / 8, t256>>>(hbuf, ssrc, startp, dinv, bg1, gA, N, 7);

    // GCN2
    gemm_tc<<<dim3(mb, 2), t256>>>(gA, Wg2, hbuf, N, 128, 128, nullptr, nullptr);
    gcn_gather<<<(N + 7) / 8, t256>>>(hbuf, ssrc, startp, dinv, bg2, gB, N, 7);

    // GCN3 (out 256)
    gemm_tc<<<dim3(mb, 4), t256>>>(gB, Wg3, hbuf, N, 128, 256, nullptr, nullptr);
    gcn_gather<<<(N + 7) / 8, t256>>>(hbuf, ssrc, startp, dinv, bg3, gA, N, 8);

    // EdgeConv1: gA[N,256] -> gB[N,128]
    bn_coef<<<2, t256>>>(e1g, e1b, e1m, e1v, bna, bnb, 512);
    gemm_tc<<<dim3(mb, 2), t256>>>(gA, e1W, P, N, 256, 128, bna, bnb);
    zero_u32<<<(N * 128 + 255) / 256, t256>>>(Mx, N * 128);
    edgeconv_tc<<<(E + 63) / 64, t256>>>(gA, ssrc, sdst, bna + 256, bnb + 256,
                                         e1W + 256 * 128, Mx, E, 256);
    combine_kernel<<<(N * 128 + 255) / 256, t256>>>(P, Mx, indeg, gB, N);

    // EdgeConv2: gB[N,128] -> gA[N,128]
    bn_coef<<<1, t256>>>(e2g, e2b, e2m, e2v, bna, bnb, 256);
    gemm_tc<<<dim3(mb, 2), t256>>>(gB, e2W, P, N, 128, 128, bna, bnb);
    zero_u32<<<(N * 128 + 255) / 256, t256>>>(Mx, N * 128);
    edgeconv_tc<<<(E + 63) / 64, t256>>>(gB, ssrc, sdst, bna + 128, bnb + 128,
                                         e2W + 128 * 128, Mx, E, 128);
    combine_kernel<<<(N * 128 + 255) / 256, t256>>>(P, Mx, indeg, gA, N);

    // EdgeConv3: gA[N,128] -> gB[N,128]
    bn_coef<<<1, t256>>>(e3g, e3b, e3m, e3v, bna, bnb, 256);
    gemm_tc<<<dim3(mb, 2), t256>>>(gA, e3W, P, N, 128, 128, bna, bnb);
    zero_u32<<<(N * 128 + 255) / 256, t256>>>(Mx, N * 128);
    edgeconv_tc<<<(E + 63) / 64, t256>>>(gA, ssrc, sdst, bna + 128, bnb + 128,
                                         e3W + 128 * 128, Mx, E, 128);
    combine_kernel<<<(N * 128 + 255) / 256, t256>>>(P, Mx, indeg, gB, N);

    // final FC -> d_out [N,1]
    fc_kernel<<<(N + 7) / 8, t256>>>(gB, Wfc, bfc, (float*)d_out, N);
}

// round 6
// speedup vs baseline: 2.7104x; 1.4322x over previous
#include <cuda_runtime.h>
#include <math.h>

#define NCAP 20000
#define ECAP 320000

// ---------------- static scratch (no allocation allowed) ----------------
static __device__ float    d_x0  [NCAP * 64];
static __device__ float    d_hbuf[NCAP * 256];
static __device__ float    d_gA  [NCAP * 256];
static __device__ float    d_gB  [NCAP * 256];
static __device__ float    d_P   [NCAP * 128];
static __device__ unsigned d_Mx  [NCAP * 128];
static __device__ float    d_dinv[NCAP];
static __device__ int      d_indeg[NCAP];
static __device__ int      d_start[NCAP + 1];
static __device__ int      d_cnt  [NCAP];
static __device__ int      d_ssrc [ECAP];
static __device__ int      d_sdst [ECAP];
static __device__ float    d_ecoef[ECAP];
static __device__ float    d_bna [512];
static __device__ float    d_bnb [512];

// ---------------- helpers ----------------
__device__ __forceinline__ unsigned f2tf32(float x) {
    unsigned y;
    asm("cvt.rna.tf32.f32 %0, %1;" : "=r"(y) : "f"(x));
    return y;
}

__device__ __forceinline__ void mma_tf32(float* d, const unsigned* a, const unsigned* b) {
    asm volatile(
        "mma.sync.aligned.m16n8k8.row.col.f32.tf32.tf32.f32 "
        "{%0,%1,%2,%3}, {%4,%5,%6,%7}, {%8,%9}, {%0,%1,%2,%3};"
        : "+f"(d[0]), "+f"(d[1]), "+f"(d[2]), "+f"(d[3])
        : "r"(a[0]), "r"(a[1]), "r"(a[2]), "r"(a[3]), "r"(b[0]), "r"(b[1]));
}

__device__ __forceinline__ void red_max_enc(unsigned* p, float v) {
    unsigned u = __float_as_uint(v);
    unsigned key = (u & 0x80000000u) ? ~u : (u | 0x80000000u);
    asm volatile("red.global.max.u32 [%0], %1;" :: "l"(p), "r"(key) : "memory");
}

// ---------------- small elementwise kernels ----------------
__global__ void zero_i32(int* p, int n) {
    int i = blockIdx.x * 256 + threadIdx.x;
    if (i < n) p[i] = 0;
}
__global__ void zero_u32(unsigned* p, int n) {
    int i = blockIdx.x * 256 + threadIdx.x;
    if (i < n) p[i] = 0u;
}
__global__ void count_indeg(const int* __restrict__ dstv, int* __restrict__ indeg, int E) {
    int e = blockIdx.x * 256 + threadIdx.x;
    if (e < E) atomicAdd(&indeg[dstv[e]], 1);
}
__global__ void compute_dinv(const int* __restrict__ indeg, float* __restrict__ dinv, int N) {
    int i = blockIdx.x * 256 + threadIdx.x;
    if (i < N) dinv[i] = rsqrtf((float)indeg[i] + 1.0f);
}
__global__ void bn_coef(const float* __restrict__ g, const float* __restrict__ be,
                        const float* __restrict__ me, const float* __restrict__ va,
                        float* __restrict__ a, float* __restrict__ b, int n) {
    int i = blockIdx.x * 256 + threadIdx.x;
    if (i < n) {
        float ai = g[i] * rsqrtf(va[i] + 1e-5f);
        a[i] = ai;
        b[i] = be[i] - me[i] * ai;
    }
}

// ---------------- exclusive scan over indeg -> start (single block, 1024 thr) ----------------
__global__ __launch_bounds__(1024) void scan_kernel(const int* __restrict__ indeg,
                                                    int* __restrict__ start, int N) {
    __shared__ int wsum[32];
    int t = threadIdx.x;
    int chunk = (N + 1023) / 1024;
    int lo = t * chunk;
    int hi = lo + chunk; if (hi > N) hi = N; if (lo > N) lo = N;
    int s = 0;
    for (int i = lo; i < hi; i++) s += indeg[i];
    int lane = t & 31, w = t >> 5;
    int v = s;
#pragma unroll
    for (int o = 1; o < 32; o <<= 1) {
        int u = __shfl_up_sync(0xffffffffu, v, o);
        if (lane >= o) v += u;
    }
    if (lane == 31) wsum[w] = v;
    __syncthreads();
    if (w == 0) {
        int x = wsum[lane];
#pragma unroll
        for (int o = 1; o < 32; o <<= 1) {
            int u = __shfl_up_sync(0xffffffffu, x, o);
            if (lane >= o) x += u;
        }
        wsum[lane] = x;
    }
    __syncthreads();
    int excl = (v - s) + (w > 0 ? wsum[w - 1] : 0);
    int run = excl;
    for (int i = lo; i < hi; i++) { start[i] = run; run += indeg[i]; }
    if (t == 1023) start[N] = run;
}

// ---------------- counting-sort scatter: edges sorted by dst (+ per-edge GCN coef) ----------------
__global__ void scatter_edges(const int* __restrict__ src, const int* __restrict__ dstv,
                              const int* __restrict__ start, int* __restrict__ cnt,
                              const float* __restrict__ dinv,
                              int* __restrict__ ssrc, int* __restrict__ sdst,
                              float* __restrict__ ecoef, int E) {
    int e = blockIdx.x * 256 + threadIdx.x;
    if (e < E) {
        int s = src[e], d = dstv[e];
        int p = start[d] + atomicAdd(&cnt[d], 1);
        ssrc[p] = s;
        sdst[p] = d;
        ecoef[p] = dinv[s] * dinv[d];
    }
}

// ---------------- fused dual-projection GEMM (fp32 SIMT) ----------------
__global__ __launch_bounds__(256) void proj_kernel(
    const float* __restrict__ A,
    const float* __restrict__ Bm, const float* __restrict__ bm,
    const float* __restrict__ Bc, const float* __restrict__ bc,
    float* __restrict__ C, int Mrows)
{
    const int K = 512;
    __shared__ float As[16][65];
    __shared__ float Bms[16][64];
    __shared__ float Bcs[16][64];
    int tid = threadIdx.x;
    int tx = tid & 15, ty = tid >> 4;
    int row0 = blockIdx.x * 64;
    float acc[4][4] = {};
    for (int k0 = 0; k0 < K; k0 += 16) {
#pragma unroll
        for (int i = 0; i < 4; i++) {
            int lin = tid + i * 256;
            int r = lin >> 4, kk = lin & 15;
            int gr = row0 + r;
            As[kk][r] = (gr < Mrows) ? A[gr * K + k0 + kk] : 0.f;
        }
#pragma unroll
        for (int i = 0; i < 4; i++) {
            int lin = tid + i * 256;
            int kk = lin >> 6, n = lin & 63;
            Bms[kk][n] = Bm[(k0 + kk) * 64 + n];
            Bcs[kk][n] = Bc[(k0 + kk) * 64 + n];
        }
        __syncthreads();
#pragma unroll
        for (int kk = 0; kk < 16; kk++) {
            float4 bmv = *(const float4*)&Bms[kk][tx * 4];
            float4 bcv = *(const float4*)&Bcs[kk][tx * 4];
            float av0 = As[kk][ty * 4 + 0];
            acc[0][0] += av0 * bmv.x; acc[0][1] += av0 * bmv.y;
            acc[0][2] += av0 * bmv.z; acc[0][3] += av0 * bmv.w;
#pragma unroll
            for (int r = 1; r < 4; r++) {
                float av = As[kk][ty * 4 + r];
                acc[r][0] += av * bcv.x; acc[r][1] += av * bcv.y;
                acc[r][2] += av * bcv.z; acc[r][3] += av * bcv.w;
            }
        }
        __syncthreads();
    }
#pragma unroll
    for (int r = 0; r < 4; r++) {
        int gr = row0 + ty * 4 + r;
        if (gr < Mrows) {
#pragma unroll
            for (int c = 0; c < 4; c++) {
                float bias = (r == 0) ? bm[tx * 4 + c] : bc[tx * 4 + c];
                C[gr * 64 + tx * 4 + c] = acc[r][c] + bias;
            }
        }
    }
}

// ---------------- TF32 tensor-core node GEMM: C = f(A) @ B (float4 fills) ----------------
__global__ __launch_bounds__(256) void gemm_tc(
    const float* __restrict__ A, const float* __restrict__ B, float* __restrict__ C,
    int M, int K, int Ncols,
    const float* __restrict__ ta, const float* __restrict__ tb)
{
    __shared__ unsigned As[64 * 36];
    __shared__ unsigned Bs[32 * 72];
    int tid = threadIdx.x;
    int lane = tid & 31, warp = tid >> 5;
    int wm = warp & 3, wn = warp >> 2;
    int gid = lane >> 2, tig = lane & 3;
    int row0 = blockIdx.x * 64;
    int col0 = blockIdx.y * 64;
    float acc[4][4] = {};
    for (int k0 = 0; k0 < K; k0 += 32) {
#pragma unroll
        for (int i = 0; i < 2; i++) {
            int lin = tid + i * 256;          // 0..511
            int r = lin >> 3;                 // 0..63
            int k4 = (lin & 7) * 4;
            int gr = row0 + r;
            float4 v = make_float4(0.f, 0.f, 0.f, 0.f);
            if (gr < M) {
                v = *(const float4*)&A[(long long)gr * K + k0 + k4];
                if (ta) {
                    float4 a4 = *(const float4*)&ta[k0 + k4];
                    float4 b4 = *(const float4*)&tb[k0 + k4];
                    v.x = fmaxf(a4.x * v.x + b4.x, 0.f);
                    v.y = fmaxf(a4.y * v.y + b4.y, 0.f);
                    v.z = fmaxf(a4.z * v.z + b4.z, 0.f);
                    v.w = fmaxf(a4.w * v.w + b4.w, 0.f);
                }
            }
            *(uint4*)&As[r * 36 + k4] =
                make_uint4(f2tf32(v.x), f2tf32(v.y), f2tf32(v.z), f2tf32(v.w));
        }
#pragma unroll
        for (int i = 0; i < 2; i++) {
            int lin = tid + i * 256;
            int k = lin >> 4;                 // 0..31
            int n4 = (lin & 15) * 4;
            float4 w4 = *(const float4*)&B[(long long)(k0 + k) * Ncols + col0 + n4];
            *(uint4*)&Bs[k * 72 + n4] =
                make_uint4(f2tf32(w4.x), f2tf32(w4.y), f2tf32(w4.z), f2tf32(w4.w));
        }
        __syncthreads();
#pragma unroll
        for (int s = 0; s < 4; s++) {
            unsigned a[4];
            int ar = wm * 16 + gid;
            int ac = s * 8 + tig;
            a[0] = As[ar * 36 + ac];
            a[1] = As[(ar + 8) * 36 + ac];
            a[2] = As[ar * 36 + ac + 4];
            a[3] = As[(ar + 8) * 36 + ac + 4];
#pragma unroll
            for (int nt = 0; nt < 4; nt++) {
                unsigned b[2];
                int bc = wn * 32 + nt * 8 + gid;
                b[0] = Bs[(s * 8 + tig) * 72 + bc];
                b[1] = Bs[(s * 8 + tig + 4) * 72 + bc];
                mma_tf32(acc[nt], a, b);
            }
        }
        __syncthreads();
    }
#pragma unroll
    for (int half = 0; half < 2; half++) {
        int gr = row0 + wm * 16 + gid + half * 8;
        if (gr < M) {
#pragma unroll
            for (int nt = 0; nt < 4; nt++) {
                int col = col0 + wn * 32 + nt * 8 + tig * 2;
                C[gr * Ncols + col]     = acc[nt][half * 2 + 0];
                C[gr * Ncols + col + 1] = acc[nt][half * 2 + 1];
            }
        }
    }
}

// ---------------- GCN aggregation: CSR gather, warp-batched indices + precomputed coef ----------------
// out[i] = bias + dinv[i]^2 * h[i] + sum_{e in in(i)} ecoef[e] * h[src[e]]
__global__ __launch_bounds__(256) void gcn_gather(
    const float* __restrict__ h, const int* __restrict__ ssrc,
    const float* __restrict__ ecoef, const int* __restrict__ start,
    const float* __restrict__ dinv, const float* __restrict__ bias,
    float* __restrict__ out, int N, int lc)
{
    int node = blockIdx.x * 8 + (threadIdx.x >> 5);
    int lane = threadIdx.x & 31;
    if (node >= N) return;
    int groups = 1 << (lc - 7);          // 1 (128 cols) or 2 (256 cols)
    float di = dinv[node];
    float di2 = di * di;
    float4 acc[2];
#pragma unroll
    for (int j = 0; j < 2; j++) {
        if (j < groups) {
            int col = j * 128 + lane * 4;
            float4 hv = *(const float4*)&h[((long long)node << lc) + col];
            float4 bv = *(const float4*)&bias[col];
            acc[j].x = bv.x + di2 * hv.x;
            acc[j].y = bv.y + di2 * hv.y;
            acc[j].z = bv.z + di2 * hv.z;
            acc[j].w = bv.w + di2 * hv.w;
        }
    }
    int s0 = start[node], s1 = start[node + 1];
    for (int base = s0; base < s1; base += 32) {
        int e = base + lane;
        int sidx = 0; float cf = 0.f;
        if (e < s1) { sidx = ssrc[e]; cf = ecoef[e]; }
        int cnt = s1 - base; if (cnt > 32) cnt = 32;
        for (int j = 0; j < cnt; j++) {
            int s = __shfl_sync(0xffffffffu, sidx, j);
            float coef = __shfl_sync(0xffffffffu, cf, j);
            const float* hrow = &h[(long long)s << lc];
#pragma unroll
            for (int g = 0; g < 2; g++) {
                if (g < groups) {
                    float4 hv = *(const float4*)&hrow[g * 128 + lane * 4];
                    acc[g].x += coef * hv.x;
                    acc[g].y += coef * hv.y;
                    acc[g].z += coef * hv.z;
                    acc[g].w += coef * hv.w;
                }
            }
        }
    }
#pragma unroll
    for (int j = 0; j < 2; j++) {
        if (j < groups)
            *(float4*)&out[((long long)node << lc) + j * 128 + lane * 4] = acc[j];
    }
}

// ---------------- EdgeConv: 128-edge TF32 tiles over dst-sorted edges + segmented max ----------------
__global__ __launch_bounds__(256) void edgeconv_tc(
    const float* __restrict__ g, const int* __restrict__ ssrc, const int* __restrict__ sdstv,
    const float* __restrict__ a2, const float* __restrict__ b2,
    const float* __restrict__ Wb, unsigned* __restrict__ Mout, int E, int C)
{
    __shared__ unsigned qs[128 * 36];    // 18 KB; reused as sacc (32*132 floats) in epilogue
    __shared__ unsigned ws[32 * 136];    // 17 KB
    __shared__ int ss[128], sd[128];
    int tid = threadIdx.x;
    int e0 = blockIdx.x * 128;
    if (tid < 128) {
        int e = e0 + tid;
        if (e >= E) e = E - 1;
        ss[tid] = ssrc[e];
        sd[tid] = sdstv[e];
    }
    __syncthreads();
    int lane = tid & 31, warp = tid >> 5;
    int wm = warp & 3, wn = warp >> 2;
    int gid = lane >> 2, tig = lane & 3;
    float acc[2][8][4] = {};
    for (int k0 = 0; k0 < C; k0 += 32) {
        // fill qs: 128 edges x 32 k (float4 everywhere)
#pragma unroll
        for (int i = 0; i < 4; i++) {
            int lin = tid + i * 256;          // 0..1023
            int e = lin >> 3;                 // 0..127
            int k4 = (lin & 7) * 4;
            int kk = k0 + k4;
            float4 gs = *(const float4*)&g[(long long)ss[e] * C + kk];
            float4 gd = *(const float4*)&g[(long long)sd[e] * C + kk];
            float4 av = *(const float4*)&a2[kk];
            float4 bv = *(const float4*)&b2[kk];
            unsigned q0 = f2tf32(fmaxf(av.x * (gs.x - gd.x) + bv.x, 0.f));
            unsigned q1 = f2tf32(fmaxf(av.y * (gs.y - gd.y) + bv.y, 0.f));
            unsigned q2 = f2tf32(fmaxf(av.z * (gs.z - gd.z) + bv.z, 0.f));
            unsigned q3 = f2tf32(fmaxf(av.w * (gs.w - gd.w) + bv.w, 0.f));
            *(uint4*)&qs[e * 36 + k4] = make_uint4(q0, q1, q2, q3);
        }
        // fill ws: 32 k x 128 n
#pragma unroll
        for (int i = 0; i < 4; i++) {
            int lin = tid + i * 256;
            int k = lin >> 5;                 // 0..31
            int n4 = (lin & 31) * 4;
            float4 w4 = *(const float4*)&Wb[(long long)(k0 + k) * 128 + n4];
            *(uint4*)&ws[k * 136 + n4] =
                make_uint4(f2tf32(w4.x), f2tf32(w4.y), f2tf32(w4.z), f2tf32(w4.w));
        }
        __syncthreads();
#pragma unroll
        for (int s = 0; s < 4; s++) {
            int ac = s * 8 + tig;
#pragma unroll
            for (int mt = 0; mt < 2; mt++) {
                unsigned a[4];
                int ar = wm * 32 + mt * 16 + gid;
                a[0] = qs[ar * 36 + ac];
                a[1] = qs[(ar + 8) * 36 + ac];
                a[2] = qs[ar * 36 + ac + 4];
                a[3] = qs[(ar + 8) * 36 + ac + 4];
#pragma unroll
                for (int nt = 0; nt < 8; nt++) {
                    unsigned b[2];
                    int bc = wn * 64 + nt * 8 + gid;
                    b[0] = ws[(s * 8 + tig) * 136 + bc];
                    b[1] = ws[(s * 8 + tig + 4) * 136 + bc];
                    mma_tf32(acc[mt][nt], a, b);
                }
            }
        }
        __syncthreads();
    }
    // segmented max: 4 passes of 32 rows (dst-sorted); smem reuse
    float* sacc = (float*)qs;
#pragma unroll
    for (int pass = 0; pass < 4; pass++) {
        if (wm == pass) {
#pragma unroll
            for (int mt = 0; mt < 2; mt++) {
#pragma unroll
                for (int half = 0; half < 2; half++) {
                    int rl = mt * 16 + gid + half * 8;   // 0..31
#pragma unroll
                    for (int nt = 0; nt < 8; nt++) {
                        int col = wn * 64 + nt * 8 + tig * 2;
                        sacc[rl * 132 + col]     = acc[mt][nt][half * 2 + 0];
                        sacc[rl * 132 + col + 1] = acc[mt][nt][half * 2 + 1];
                    }
                }
            }
        }
        __syncthreads();
        {
            int col = tid & 127;
            int rh = tid >> 7;                  // 0..1
            int r0 = rh * 16, r1 = r0 + 16;
            int base = pass * 32;
            int cur = sd[base + r0];
            float m = sacc[r0 * 132 + col];
            for (int r = r0 + 1; r < r1; r++) {
                int d = sd[base + r];
                float v = sacc[r * 132 + col];
                if (d != cur) {
                    red_max_enc(&Mout[(long long)cur * 128 + col], m);
                    cur = d;
                    m = v;
                } else {
                    m = fmaxf(m, v);
                }
            }
            red_max_enc(&Mout[(long long)cur * 128 + col], m);
        }
        __syncthreads();
    }
}

// ---------------- EdgeConv combine: out = indeg>0 ? P + decode(M) : 0 ; resets M to 0 ----------------
__global__ void combine_kernel(const float* __restrict__ P, unsigned* __restrict__ Mv,
                               const int* __restrict__ indeg, float* __restrict__ out, int N)
{
    int idx4 = blockIdx.x * 256 + threadIdx.x;
    if (idx4 >= N * 32) return;
    int i = idx4 >> 5;
    uint4 kv = *(uint4*)&Mv[idx4 * 4];
    float4 pv = *(const float4*)&P[idx4 * 4];
    float4 o = make_float4(0.f, 0.f, 0.f, 0.f);
    if (indeg[i] > 0) {
        unsigned u0 = (kv.x & 0x80000000u) ? (kv.x & 0x7fffffffu) : ~kv.x;
        unsigned u1 = (kv.y & 0x80000000u) ? (kv.y & 0x7fffffffu) : ~kv.y;
        unsigned u2 = (kv.z & 0x80000000u) ? (kv.z & 0x7fffffffu) : ~kv.z;
        unsigned u3 = (kv.w & 0x80000000u) ? (kv.w & 0x7fffffffu) : ~kv.w;
        o.x = pv.x + __uint_as_float(u0);
        o.y = pv.y + __uint_as_float(u1);
        o.z = pv.z + __uint_as_float(u2);
        o.w = pv.w + __uint_as_float(u3);
    }
    *(uint4*)&Mv[idx4 * 4] = make_uint4(0u, 0u, 0u, 0u);   // re-zero for next layer
    *(float4*)&out[idx4 * 4] = o;
}

// ---------------- final FC ----------------
__global__ void fc_kernel(const float* __restrict__ h, const float* __restrict__ W,
                          const float* __restrict__ b, float* __restrict__ out, int N)
{
    int warp = (blockIdx.x * 256 + threadIdx.x) >> 5;
    int lane = threadIdx.x & 31;
    if (warp >= N) return;
    float s = 0.f;
#pragma unroll
    for (int j = lane; j < 128; j += 32) s += h[warp * 128 + j] * W[j];
#pragma unroll
    for (int o = 16; o; o >>= 1) s += __shfl_down_sync(0xffffffffu, s, o);
    if (lane == 0) out[warp] = s + b[0];
}

// ---------------- launch ----------------
extern "C" void kernel_launch(void* const* d_in, const int* in_sizes, int n_in,
                              void* d_out, int out_size)
{
    const float* x   = (const float*)d_in[0];
    const int*   ei  = (const int*)d_in[1];
    const float* Wm  = (const float*)d_in[2];
    const float* bm  = (const float*)d_in[3];
    const float* Wc  = (const float*)d_in[4];
    const float* bc  = (const float*)d_in[5];
    const float* Wg1 = (const float*)d_in[6];
    const float* bg1 = (const float*)d_in[7];
    const float* Wg2 = (const float*)d_in[8];
    const float* bg2 = (const float*)d_in[9];
    const float* Wg3 = (const float*)d_in[10];
    const float* bg3 = (const float*)d_in[11];
    const float* e1g = (const float*)d_in[12];
    const float* e1b = (const float*)d_in[13];
    const float* e1m = (const float*)d_in[14];
    const float* e1v = (const float*)d_in[15];
    const float* e1W = (const float*)d_in[16];
    const float* e2g = (const float*)d_in[17];
    const float* e2b = (const float*)d_in[18];
    const float* e2m = (const float*)d_in[19];
    const float* e2v = (const float*)d_in[20];
    const float* e2W = (const float*)d_in[21];
    const float* e3g = (const float*)d_in[22];
    const float* e3b = (const float*)d_in[23];
    const float* e3m = (const float*)d_in[24];
    const float* e3v = (const float*)d_in[25];
    const float* e3W = (const float*)d_in[26];
    const float* Wfc = (const float*)d_in[27];
    const float* bfc = (const float*)d_in[28];

    int N = in_sizes[0] / 512;
    int E = in_sizes[1] / 2;
    const int* src = ei;
    const int* dst = ei + E;

    float *x0, *hbuf, *gA, *gB, *P, *dinv, *bna, *bnb, *ecoef;
    unsigned* Mx;
    int *indeg, *startp, *cnt, *ssrc, *sdst;
    cudaGetSymbolAddress((void**)&x0,    d_x0);
    cudaGetSymbolAddress((void**)&hbuf,  d_hbuf);
    cudaGetSymbolAddress((void**)&gA,    d_gA);
    cudaGetSymbolAddress((void**)&gB,    d_gB);
    cudaGetSymbolAddress((void**)&P,     d_P);
    cudaGetSymbolAddress((void**)&Mx,    d_Mx);
    cudaGetSymbolAddress((void**)&dinv,  d_dinv);
    cudaGetSymbolAddress((void**)&indeg, d_indeg);
    cudaGetSymbolAddress((void**)&startp,d_start);
    cudaGetSymbolAddress((void**)&cnt,   d_cnt);
    cudaGetSymbolAddress((void**)&ssrc,  d_ssrc);
    cudaGetSymbolAddress((void**)&sdst,  d_sdst);
    cudaGetSymbolAddress((void**)&ecoef, d_ecoef);
    cudaGetSymbolAddress((void**)&bna,   d_bna);
    cudaGetSymbolAddress((void**)&bnb,   d_bnb);

    dim3 t256(256);
    int mb = (N + 63) / 64;

    // input projection (fused row-select), fp32
    proj_kernel<<<mb, t256>>>(x, Wm, bm, Wc, bc, x0, N);

    // degrees + CSR sort by dst (+ per-edge coef)
    zero_i32<<<(N + 255) / 256, t256>>>(indeg, N);
    count_indeg<<<(E + 255) / 256, t256>>>(dst, indeg, E);
    compute_dinv<<<(N + 255) / 256, t256>>>(indeg, dinv, N);
    scan_kernel<<<1, 1024>>>(indeg, startp, N);
    zero_i32<<<(N + 255) / 256, t256>>>(cnt, N);
    scatter_edges<<<(E + 255) / 256, t256>>>(src, dst, startp, cnt, dinv, ssrc, sdst, ecoef, E);

    // GCN1: x0[N,64] @ Wg1[64,128] -> hbuf; gather -> gA
    gemm_tc<<<dim3(mb, 2), t256>>>(x0, Wg1, hbuf, N, 64, 128, nullptr, nullptr);
    gcn_gather<<<(N + 7) / 8, t256>>>(hbuf, ssrc, ecoef, startp, dinv, bg1, gA, N, 7);

    // GCN2
    gemm_tc<<<dim3(mb, 2), t256>>>(gA, Wg2, hbuf, N, 128, 128, nullptr, nullptr);
    gcn_gather<<<(N + 7) / 8, t256>>>(hbuf, ssrc, ecoef, startp, dinv, bg2, gB, N, 7);

    // GCN3 (out 256)
    gemm_tc<<<dim3(mb, 4), t256>>>(gB, Wg3, hbuf, N, 128, 256, nullptr, nullptr);
    gcn_gather<<<(N + 7) / 8, t256>>>(hbuf, ssrc, ecoef, startp, dinv, bg3, gA, N, 8);

    // EdgeConv1: gA[N,256] -> gB[N,128]
    bn_coef<<<2, t256>>>(e1g, e1b, e1m, e1v, bna, bnb, 512);
    gemm_tc<<<dim3(mb, 2), t256>>>(gA, e1W, P, N, 256, 128, bna, bnb);
    zero_u32<<<(N * 128 + 255) / 256, t256>>>(Mx, N * 128);
    edgeconv_tc<<<(E + 127) / 128, t256>>>(gA, ssrc, sdst, bna + 256, bnb + 256,
                                           e1W + 256 * 128, Mx, E, 256);
    combine_kernel<<<(N * 32 + 255) / 256, t256>>>(P, Mx, indeg, gB, N);

    // EdgeConv2: gB[N,128] -> gA[N,128]  (Mx re-zeroed by previous combine)
    bn_coef<<<1, t256>>>(e2g, e2b, e2m, e2v, bna, bnb, 256);
    gemm_tc<<<dim3(mb, 2), t256>>>(gB, e2W, P, N, 128, 128, bna, bnb);
    edgeconv_tc<<<(E + 127) / 128, t256>>>(gB, ssrc, sdst, bna + 128, bnb + 128,
                                           e2W + 128 * 128, Mx, E, 128);
    combine_kernel<<<(N * 32 + 255) / 256, t256>>>(P, Mx, indeg, gA, N);

    // EdgeConv3: gA[N,128] -> gB[N,128]
    bn_coef<<<1, t256>>>(e3g, e3b, e3m, e3v, bna, bnb, 256);
    gemm_tc<<<dim3(mb, 2), t256>>>(gA, e3W, P, N, 128, 128, bna, bnb);
    edgeconv_tc<<<(E + 127) / 128, t256>>>(gA, ssrc, sdst, bna + 128, bnb + 128,
                                           e3W + 128 * 128, Mx, E, 128);
    combine_kernel<<<(N * 32 + 255) / 256, t256>>>(P, Mx, indeg, gB, N);

    // final FC -> d_out [N,1]
    fc_kernel<<<(N + 7) / 8, t256>>>(gB, Wfc, bfc, (float*)d_out, N);
}

// round 8
// speedup vs baseline: 2.9951x; 1.1050x over previous
#include <cuda_runtime.h>
#include <cuda_fp16.h>
#include <math.h>

#define NCAP 20000
#define ECAP 320000

// ---------------- static scratch (no allocation allowed) ----------------
static __device__ float    d_x0  [NCAP * 64];
static __device__ float    d_hbuf[NCAP * 256];
static __device__ float    d_gA  [NCAP * 256];
static __device__ float    d_gB  [NCAP * 256];
static __device__ float    d_P   [NCAP * 128];
static __device__ unsigned d_Mx  [NCAP * 128];
static __device__ float    d_dinv[NCAP];
static __device__ int      d_indeg[NCAP];
static __device__ int      d_start[NCAP + 1];
static __device__ int      d_cnt  [NCAP];
static __device__ int      d_ssrc [ECAP];
static __device__ int      d_sdst [ECAP];
static __device__ float    d_ecoef[ECAP];
static __device__ float    d_bna [512];
static __device__ float    d_bnb [512];

// ---------------- helpers ----------------
__device__ __forceinline__ unsigned f2tf32(float x) {
    unsigned y;
    asm("cvt.rna.tf32.f32 %0, %1;" : "=r"(y) : "f"(x));
    return y;
}

__device__ __forceinline__ unsigned pack_h2(float lo, float hi) {
    __half2 h = __floats2half2_rn(lo, hi);
    return *(unsigned*)&h;
}

__device__ __forceinline__ void mma_tf32(float* d, const unsigned* a, const unsigned* b) {
    asm volatile(
        "mma.sync.aligned.m16n8k8.row.col.f32.tf32.tf32.f32 "
        "{%0,%1,%2,%3}, {%4,%5,%6,%7}, {%8,%9}, {%0,%1,%2,%3};"
        : "+f"(d[0]), "+f"(d[1]), "+f"(d[2]), "+f"(d[3])
        : "r"(a[0]), "r"(a[1]), "r"(a[2]), "r"(a[3]), "r"(b[0]), "r"(b[1]));
}

__device__ __forceinline__ void mma_f16(float* d, const unsigned* a, const unsigned* b) {
    asm volatile(
        "mma.sync.aligned.m16n8k16.row.col.f32.f16.f16.f32 "
        "{%0,%1,%2,%3}, {%4,%5,%6,%7}, {%8,%9}, {%0,%1,%2,%3};"
        : "+f"(d[0]), "+f"(d[1]), "+f"(d[2]), "+f"(d[3])
        : "r"(a[0]), "r"(a[1]), "r"(a[2]), "r"(a[3]), "r"(b[0]), "r"(b[1]));
}

__device__ __forceinline__ void red_max_enc(unsigned* p, float v) {
    unsigned u = __float_as_uint(v);
    unsigned key = (u & 0x80000000u) ? ~u : (u | 0x80000000u);
    asm volatile("red.global.max.u32 [%0], %1;" :: "l"(p), "r"(key) : "memory");
}

// ---------------- small elementwise kernels ----------------
__global__ void zero_i32(int* p, int n) {
    int i = blockIdx.x * 256 + threadIdx.x;
    if (i < n) p[i] = 0;
}
__global__ void zero_u32(unsigned* p, int n) {
    int i = blockIdx.x * 256 + threadIdx.x;
    if (i < n) p[i] = 0u;
}
__global__ void count_indeg(const int* __restrict__ dstv, int* __restrict__ indeg, int E) {
    int e = blockIdx.x * 256 + threadIdx.x;
    if (e < E) atomicAdd(&indeg[dstv[e]], 1);
}
__global__ void compute_dinv(const int* __restrict__ indeg, float* __restrict__ dinv, int N) {
    int i = blockIdx.x * 256 + threadIdx.x;
    if (i < N) dinv[i] = rsqrtf((float)indeg[i] + 1.0f);
}
__global__ void bn_coef(const float* __restrict__ g, const float* __restrict__ be,
                        const float* __restrict__ me, const float* __restrict__ va,
                        float* __restrict__ a, float* __restrict__ b, int n) {
    int i = blockIdx.x * 256 + threadIdx.x;
    if (i < n) {
        float ai = g[i] * rsqrtf(va[i] + 1e-5f);
        a[i] = ai;
        b[i] = be[i] - me[i] * ai;
    }
}

// ---------------- exclusive scan over indeg -> start (single block, 1024 thr) ----------------
__global__ __launch_bounds__(1024) void scan_kernel(const int* __restrict__ indeg,
                                                    int* __restrict__ start, int N) {
    __shared__ int wsum[32];
    int t = threadIdx.x;
    int chunk = (N + 1023) / 1024;
    int lo = t * chunk;
    int hi = lo + chunk; if (hi > N) hi = N; if (lo > N) lo = N;
    int s = 0;
    for (int i = lo; i < hi; i++) s += indeg[i];
    int lane = t & 31, w = t >> 5;
    int v = s;
#pragma unroll
    for (int o = 1; o < 32; o <<= 1) {
        int u = __shfl_up_sync(0xffffffffu, v, o);
        if (lane >= o) v += u;
    }
    if (lane == 31) wsum[w] = v;
    __syncthreads();
    if (w == 0) {
        int x = wsum[lane];
#pragma unroll
        for (int o = 1; o < 32; o <<= 1) {
            int u = __shfl_up_sync(0xffffffffu, x, o);
            if (lane >= o) x += u;
        }
        wsum[lane] = x;
    }
    __syncthreads();
    int excl = (v - s) + (w > 0 ? wsum[w - 1] : 0);
    int run = excl;
    for (int i = lo; i < hi; i++) { start[i] = run; run += indeg[i]; }
    if (t == 1023) start[N] = run;
}

// ---------------- counting-sort scatter: edges sorted by dst (+ per-edge GCN coef) ----------------
__global__ void scatter_edges(const int* __restrict__ src, const int* __restrict__ dstv,
                              const int* __restrict__ start, int* __restrict__ cnt,
                              const float* __restrict__ dinv,
                              int* __restrict__ ssrc, int* __restrict__ sdst,
                              float* __restrict__ ecoef, int E) {
    int e = blockIdx.x * 256 + threadIdx.x;
    if (e < E) {
        int s = src[e], d = dstv[e];
        int p = start[d] + atomicAdd(&cnt[d], 1);
        ssrc[p] = s;
        sdst[p] = d;
        ecoef[p] = dinv[s] * dinv[d];
    }
}

// ---------------- fused dual-projection GEMM (fp32 SIMT) ----------------
__global__ __launch_bounds__(256) void proj_kernel(
    const float* __restrict__ A,
    const float* __restrict__ Bm, const float* __restrict__ bm,
    const float* __restrict__ Bc, const float* __restrict__ bc,
    float* __restrict__ C, int Mrows)
{
    const int K = 512;
    __shared__ float As[16][65];
    __shared__ float Bms[16][64];
    __shared__ float Bcs[16][64];
    int tid = threadIdx.x;
    int tx = tid & 15, ty = tid >> 4;
    int row0 = blockIdx.x * 64;
    float acc[4][4] = {};
    for (int k0 = 0; k0 < K; k0 += 16) {
#pragma unroll
        for (int i = 0; i < 4; i++) {
            int lin = tid + i * 256;
            int r = lin >> 4, kk = lin & 15;
            int gr = row0 + r;
            As[kk][r] = (gr < Mrows) ? A[gr * K + k0 + kk] : 0.f;
        }
#pragma unroll
        for (int i = 0; i < 4; i++) {
            int lin = tid + i * 256;
            int kk = lin >> 6, n = lin & 63;
            Bms[kk][n] = Bm[(k0 + kk) * 64 + n];
            Bcs[kk][n] = Bc[(k0 + kk) * 64 + n];
        }
        __syncthreads();
#pragma unroll
        for (int kk = 0; kk < 16; kk++) {
            float4 bmv = *(const float4*)&Bms[kk][tx * 4];
            float4 bcv = *(const float4*)&Bcs[kk][tx * 4];
            float av0 = As[kk][ty * 4 + 0];
            acc[0][0] += av0 * bmv.x; acc[0][1] += av0 * bmv.y;
            acc[0][2] += av0 * bmv.z; acc[0][3] += av0 * bmv.w;
#pragma unroll
            for (int r = 1; r < 4; r++) {
                float av = As[kk][ty * 4 + r];
                acc[r][0] += av * bcv.x; acc[r][1] += av * bcv.y;
                acc[r][2] += av * bcv.z; acc[r][3] += av * bcv.w;
            }
        }
        __syncthreads();
    }
#pragma unroll
    for (int r = 0; r < 4; r++) {
        int gr = row0 + ty * 4 + r;
        if (gr < Mrows) {
#pragma unroll
            for (int c = 0; c < 4; c++) {
                float bias = (r == 0) ? bm[tx * 4 + c] : bc[tx * 4 + c];
                C[gr * 64 + tx * 4 + c] = acc[r][c] + bias;
            }
        }
    }
}

// ---------------- TF32 tensor-core node GEMM: C = f(A) @ B (float4 fills) ----------------
__global__ __launch_bounds__(256) void gemm_tc(
    const float* __restrict__ A, const float* __restrict__ B, float* __restrict__ C,
    int M, int K, int Ncols,
    const float* __restrict__ ta, const float* __restrict__ tb)
{
    __shared__ unsigned As[64 * 36];
    __shared__ unsigned Bs[32 * 72];
    int tid = threadIdx.x;
    int lane = tid & 31, warp = tid >> 5;
    int wm = warp & 3, wn = warp >> 2;
    int gid = lane >> 2, tig = lane & 3;
    int row0 = blockIdx.x * 64;
    int col0 = blockIdx.y * 64;
    float acc[4][4] = {};
    for (int k0 = 0; k0 < K; k0 += 32) {
#pragma unroll
        for (int i = 0; i < 2; i++) {
            int lin = tid + i * 256;          // 0..511
            int r = lin >> 3;                 // 0..63
            int k4 = (lin & 7) * 4;
            int gr = row0 + r;
            float4 v = make_float4(0.f, 0.f, 0.f, 0.f);
            if (gr < M) {
                v = *(const float4*)&A[(long long)gr * K + k0 + k4];
                if (ta) {
                    float4 a4 = *(const float4*)&ta[k0 + k4];
                    float4 b4 = *(const float4*)&tb[k0 + k4];
                    v.x = fmaxf(a4.x * v.x + b4.x, 0.f);
                    v.y = fmaxf(a4.y * v.y + b4.y, 0.f);
                    v.z = fmaxf(a4.z * v.z + b4.z, 0.f);
                    v.w = fmaxf(a4.w * v.w + b4.w, 0.f);
                }
            }
            *(uint4*)&As[r * 36 + k4] =
                make_uint4(f2tf32(v.x), f2tf32(v.y), f2tf32(v.z), f2tf32(v.w));
        }
#pragma unroll
        for (int i = 0; i < 2; i++) {
            int lin = tid + i * 256;
            int k = lin >> 4;                 // 0..31
            int n4 = (lin & 15) * 4;
            float4 w4 = *(const float4*)&B[(long long)(k0 + k) * Ncols + col0 + n4];
            *(uint4*)&Bs[k * 72 + n4] =
                make_uint4(f2tf32(w4.x), f2tf32(w4.y), f2tf32(w4.z), f2tf32(w4.w));
        }
        __syncthreads();
#pragma unroll
        for (int s = 0; s < 4; s++) {
            unsigned a[4];
            int ar = wm * 16 + gid;
            int ac = s * 8 + tig;
            a[0] = As[ar * 36 + ac];
            a[1] = As[(ar + 8) * 36 + ac];
            a[2] = As[ar * 36 + ac + 4];
            a[3] = As[(ar + 8) * 36 + ac + 4];
#pragma unroll
            for (int nt = 0; nt < 4; nt++) {
                unsigned b[2];
                int bc = wn * 32 + nt * 8 + gid;
                b[0] = Bs[(s * 8 + tig) * 72 + bc];
                b[1] = Bs[(s * 8 + tig + 4) * 72 + bc];
                mma_tf32(acc[nt], a, b);
            }
        }
        __syncthreads();
    }
#pragma unroll
    for (int half = 0; half < 2; half++) {
        int gr = row0 + wm * 16 + gid + half * 8;
        if (gr < M) {
#pragma unroll
            for (int nt = 0; nt < 4; nt++) {
                int col = col0 + wn * 32 + nt * 8 + tig * 2;
                C[gr * Ncols + col]     = acc[nt][half * 2 + 0];
                C[gr * Ncols + col + 1] = acc[nt][half * 2 + 1];
            }
        }
    }
}

// ---------------- GCN aggregation: CSR gather, warp-batched indices + precomputed coef ----------------
// out[i] = bias + dinv[i]^2 * h[i] + sum_{e in in(i)} ecoef[e] * h[src[e]]
__global__ __launch_bounds__(256) void gcn_gather(
    const float* __restrict__ h, const int* __restrict__ ssrc,
    const float* __restrict__ ecoef, const int* __restrict__ start,
    const float* __restrict__ dinv, const float* __restrict__ bias,
    float* __restrict__ out, int N, int lc)
{
    int node = blockIdx.x * 8 + (threadIdx.x >> 5);
    int lane = threadIdx.x & 31;
    if (node >= N) return;
    int groups = 1 << (lc - 7);          // 1 (128 cols) or 2 (256 cols)
    float di = dinv[node];
    float di2 = di * di;
    float4 acc[2];
#pragma unroll
    for (int j = 0; j < 2; j++) {
        if (j < groups) {
            int col = j * 128 + lane * 4;
            float4 hv = *(const float4*)&h[((long long)node << lc) + col];
            float4 bv = *(const float4*)&bias[col];
            acc[j].x = bv.x + di2 * hv.x;
            acc[j].y = bv.y + di2 * hv.y;
            acc[j].z = bv.z + di2 * hv.z;
            acc[j].w = bv.w + di2 * hv.w;
        }
    }
    int s0 = start[node], s1 = start[node + 1];
    for (int base = s0; base < s1; base += 32) {
        int e = base + lane;
        int sidx = 0; float cf = 0.f;
        if (e < s1) { sidx = ssrc[e]; cf = ecoef[e]; }
        int cnt = s1 - base; if (cnt > 32) cnt = 32;
        for (int j = 0; j < cnt; j++) {
            int s = __shfl_sync(0xffffffffu, sidx, j);
            float coef = __shfl_sync(0xffffffffu, cf, j);
            const float* hrow = &h[(long long)s << lc];
#pragma unroll
            for (int g = 0; g < 2; g++) {
                if (g < groups) {
                    float4 hv = *(const float4*)&hrow[g * 128 + lane * 4];
                    acc[g].x += coef * hv.x;
                    acc[g].y += coef * hv.y;
                    acc[g].z += coef * hv.z;
                    acc[g].w += coef * hv.w;
                }
            }
        }
    }
#pragma unroll
    for (int j = 0; j < 2; j++) {
        if (j < groups)
            *(float4*)&out[((long long)node << lc) + j * 128 + lane * 4] = acc[j];
    }
}

// ---------------- EdgeConv: 128-edge FP16 m16n8k16 tiles over dst-sorted edges + segmented max ----------------
// smem (unsigned units): qh 128 rows x stride 20 (16 half2 + pad) = 2560
//                        wh 16 k2-rows x stride 136 = 2176; total 4736 (18.9 KB)
// sacc overlay needs 32*132 = 4224 floats -> fits.
__global__ __launch_bounds__(256) void edgeconv_tc(
    const float* __restrict__ g, const int* __restrict__ ssrc, const int* __restrict__ sdstv,
    const float* __restrict__ a2, const float* __restrict__ b2,
    const float* __restrict__ Wb, unsigned* __restrict__ Mout, int E, int C)
{
    __shared__ unsigned sh[128 * 20 + 16 * 136];
    __shared__ int ss[128], sd[128];
    unsigned* qh = sh;                 // half2, [edge][k2], stride 20
    unsigned* wh = sh + 128 * 20;      // half2, [k2][n], stride 136
    int tid = threadIdx.x;
    int e0 = blockIdx.x * 128;
    if (tid < 128) {
        int e = e0 + tid;
        if (e >= E) e = E - 1;
        ss[tid] = ssrc[e];
        sd[tid] = sdstv[e];
    }
    __syncthreads();
    int lane = tid & 31, warp = tid >> 5;
    int wm = warp & 3, wn = warp >> 2;
    int gid = lane >> 2, tig = lane & 3;
    float acc[2][8][4] = {};
    for (int k0 = 0; k0 < C; k0 += 32) {
        // fill qh: 128 edges x 32 k -> 16 half2 per edge
#pragma unroll
        for (int i = 0; i < 4; i++) {
            int lin = tid + i * 256;          // 0..1023
            int e = lin >> 3;                 // 0..127
            int k4 = (lin & 7) * 4;           // float offset within chunk
            int kk = k0 + k4;
            float4 gs = *(const float4*)&g[(long long)ss[e] * C + kk];
            float4 gd = *(const float4*)&g[(long long)sd[e] * C + kk];
            float4 av = *(const float4*)&a2[kk];
            float4 bv = *(const float4*)&b2[kk];
            float q0 = fmaxf(av.x * (gs.x - gd.x) + bv.x, 0.f);
            float q1 = fmaxf(av.y * (gs.y - gd.y) + bv.y, 0.f);
            float q2 = fmaxf(av.z * (gs.z - gd.z) + bv.z, 0.f);
            float q3 = fmaxf(av.w * (gs.w - gd.w) + bv.w, 0.f);
            *(uint2*)&qh[e * 20 + (lin & 7) * 2] =
                make_uint2(pack_h2(q0, q1), pack_h2(q2, q3));
        }
        // fill wh: interleave consecutive-k rows into half2 along k
#pragma unroll
        for (int i = 0; i < 2; i++) {
            int lin = tid + i * 256;          // 0..511
            int k2 = lin >> 5;                // 0..15
            int n4 = (lin & 31) * 4;
            const float* w0 = &Wb[(long long)(k0 + 2 * k2) * 128 + n4];
            const float* w1 = &Wb[(long long)(k0 + 2 * k2 + 1) * 128 + n4];
            float4 wa = *(const float4*)w0;
            float4 wb = *(const float4*)w1;
            *(uint4*)&wh[k2 * 136 + n4] =
                make_uint4(pack_h2(wa.x, wb.x), pack_h2(wa.y, wb.y),
                           pack_h2(wa.z, wb.z), pack_h2(wa.w, wb.w));
        }
        __syncthreads();
#pragma unroll
        for (int s = 0; s < 2; s++) {          // two k16 steps per 32-chunk
            int ac = s * 8 + tig;              // half2 index
#pragma unroll
            for (int mt = 0; mt < 2; mt++) {
                unsigned a[4];
                int ar = wm * 32 + mt * 16 + gid;
                a[0] = qh[ar * 20 + ac];
                a[1] = qh[(ar + 8) * 20 + ac];
                a[2] = qh[ar * 20 + ac + 4];
                a[3] = qh[(ar + 8) * 20 + ac + 4];
#pragma unroll
                for (int nt = 0; nt < 8; nt++) {
                    unsigned b[2];
                    int bc = wn * 64 + nt * 8 + gid;
                    b[0] = wh[(s * 8 + tig) * 136 + bc];
                    b[1] = wh[(s * 8 + tig + 4) * 136 + bc];
                    mma_f16(acc[mt][nt], a, b);
                }
            }
        }
        __syncthreads();
    }
    // segmented max: 4 passes of 32 rows (dst-sorted); smem reuse
    float* sacc = (float*)sh;
#pragma unroll
    for (int pass = 0; pass < 4; pass++) {
        if (wm == pass) {
#pragma unroll
            for (int mt = 0; mt < 2; mt++) {
#pragma unroll
                for (int half = 0; half < 2; half++) {
                    int rl = mt * 16 + gid + half * 8;   // 0..31
#pragma unroll
                    for (int nt = 0; nt < 8; nt++) {
                        int col = wn * 64 + nt * 8 + tig * 2;
                        sacc[rl * 132 + col]     = acc[mt][nt][half * 2 + 0];
                        sacc[rl * 132 + col + 1] = acc[mt][nt][half * 2 + 1];
                    }
                }
            }
        }
        __syncthreads();
        {
            int col = tid & 127;
            int rh = tid >> 7;                  // 0..1
            int r0 = rh * 16, r1 = r0 + 16;
            int base = pass * 32;
            int cur = sd[base + r0];
            float m = sacc[r0 * 132 + col];
            for (int r = r0 + 1; r < r1; r++) {
                int d = sd[base + r];
                float v = sacc[r * 132 + col];
                if (d != cur) {
                    red_max_enc(&Mout[(long long)cur * 128 + col], m);
                    cur = d;
                    m = v;
                } else {
                    m = fmaxf(m, v);
                }
            }
            red_max_enc(&Mout[(long long)cur * 128 + col], m);
        }
        __syncthreads();
    }
}

// ---------------- EdgeConv combine: out = indeg>0 ? P + decode(M) : 0 ; resets M to 0 ----------------
__global__ void combine_kernel(const float* __restrict__ P, unsigned* __restrict__ Mv,
                               const int* __restrict__ indeg, float* __restrict__ out, int N)
{
    int idx4 = blockIdx.x * 256 + threadIdx.x;
    if (idx4 >= N * 32) return;
    int i = idx4 >> 5;
    uint4 kv = *(uint4*)&Mv[idx4 * 4];
    float4 pv = *(const float4*)&P[idx4 * 4];
    float4 o = make_float4(0.f, 0.f, 0.f, 0.f);
    if (indeg[i] > 0) {
        unsigned u0 = (kv.x & 0x80000000u) ? (kv.x & 0x7fffffffu) : ~kv.x;
        unsigned u1 = (kv.y & 0x80000000u) ? (kv.y & 0x7fffffffu) : ~kv.y;
        unsigned u2 = (kv.z & 0x80000000u) ? (kv.z & 0x7fffffffu) : ~kv.z;
        unsigned u3 = (kv.w & 0x80000000u) ? (kv.w & 0x7fffffffu) : ~kv.w;
        o.x = pv.x + __uint_as_float(u0);
        o.y = pv.y + __uint_as_float(u1);
        o.z = pv.z + __uint_as_float(u2);
        o.w = pv.w + __uint_as_float(u3);
    }
    *(uint4*)&Mv[idx4 * 4] = make_uint4(0u, 0u, 0u, 0u);   // re-zero for next layer
    *(float4*)&out[idx4 * 4] = o;
}

// ---------------- final FC ----------------
__global__ void fc_kernel(const float* __restrict__ h, const float* __restrict__ W,
                          const float* __restrict__ b, float* __restrict__ out, int N)
{
    int warp = (blockIdx.x * 256 + threadIdx.x) >> 5;
    int lane = threadIdx.x & 31;
    if (warp >= N) return;
    float s = 0.f;
#pragma unroll
    for (int j = lane; j < 128; j += 32) s += h[warp * 128 + j] * W[j];
#pragma unroll
    for (int o = 16; o; o >>= 1) s += __shfl_down_sync(0xffffffffu, s, o);
    if (lane == 0) out[warp] = s + b[0];
}

// ---------------- launch ----------------
extern "C" void kernel_launch(void* const* d_in, const int* in_sizes, int n_in,
                              void* d_out, int out_size)
{
    const float* x   = (const float*)d_in[0];
    const int*   ei  = (const int*)d_in[1];
    const float* Wm  = (const float*)d_in[2];
    const float* bm  = (const float*)d_in[3];
    const float* Wc  = (const float*)d_in[4];
    const float* bc  = (const float*)d_in[5];
    const float* Wg1 = (const float*)d_in[6];
    const float* bg1 = (const float*)d_in[7];
    const float* Wg2 = (const float*)d_in[8];
    const float* bg2 = (const float*)d_in[9];
    const float* Wg3 = (const float*)d_in[10];
    const float* bg3 = (const float*)d_in[11];
    const float* e1g = (const float*)d_in[12];
    const float* e1b = (const float*)d_in[13];
    const float* e1m = (const float*)d_in[14];
    const float* e1v = (const float*)d_in[15];
    const float* e1W = (const float*)d_in[16];
    const float* e2g = (const float*)d_in[17];
    const float* e2b = (const float*)d_in[18];
    const float* e2m = (const float*)d_in[19];
    const float* e2v = (const float*)d_in[20];
    const float* e2W = (const float*)d_in[21];
    const float* e3g = (const float*)d_in[22];
    const float* e3b = (const float*)d_in[23];
    const float* e3m = (const float*)d_in[24];
    const float* e3v = (const float*)d_in[25];
    const float* e3W = (const float*)d_in[26];
    const float* Wfc = (const float*)d_in[27];
    const float* bfc = (const float*)d_in[28];

    int N = in_sizes[0] / 512;
    int E = in_sizes[1] / 2;
    const int* src = ei;
    const int* dst = ei + E;

    float *x0, *hbuf, *gA, *gB, *P, *dinv, *bna, *bnb, *ecoef;
    unsigned* Mx;
    int *indeg, *startp, *cnt, *ssrc, *sdst;
    cudaGetSymbolAddress((void**)&x0,    d_x0);
    cudaGetSymbolAddress((void**)&hbuf,  d_hbuf);
    cudaGetSymbolAddress((void**)&gA,    d_gA);
    cudaGetSymbolAddress((void**)&gB,    d_gB);
    cudaGetSymbolAddress((void**)&P,     d_P);
    cudaGetSymbolAddress((void**)&Mx,    d_Mx);
    cudaGetSymbolAddress((void**)&dinv,  d_dinv);
    cudaGetSymbolAddress((void**)&indeg, d_indeg);
    cudaGetSymbolAddress((void**)&startp,d_start);
    cudaGetSymbolAddress((void**)&cnt,   d_cnt);
    cudaGetSymbolAddress((void**)&ssrc,  d_ssrc);
    cudaGetSymbolAddress((void**)&sdst,  d_sdst);
    cudaGetSymbolAddress((void**)&ecoef, d_ecoef);
    cudaGetSymbolAddress((void**)&bna,   d_bna);
    cudaGetSymbolAddress((void**)&bnb,   d_bnb);

    dim3 t256(256);
    int mb = (N + 63) / 64;

    // input projection (fused row-select), fp32
    proj_kernel<<<mb, t256>>>(x, Wm, bm, Wc, bc, x0, N);

    // degrees + CSR sort by dst (+ per-edge coef)
    zero_i32<<<(N + 255) / 256, t256>>>(indeg, N);
    count_indeg<<<(E + 255) / 256, t256>>>(dst, indeg, E);
    compute_dinv<<<(N + 255) / 256, t256>>>(indeg, dinv, N);
    scan_kernel<<<1, 1024>>>(indeg, startp, N);
    zero_i32<<<(N + 255) / 256, t256>>>(cnt, N);
    scatter_edges<<<(E + 255) / 256, t256>>>(src, dst, startp, cnt, dinv, ssrc, sdst, ecoef, E);

    // GCN1: x0[N,64] @ Wg1[64,128] -> hbuf; gather -> gA
    gemm_tc<<<dim3(mb, 2), t256>>>(x0, Wg1, hbuf, N, 64, 128, nullptr, nullptr);
    gcn_gather<<<(N + 7) / 8, t256>>>(hbuf, ssrc, ecoef, startp, dinv, bg1, gA, N, 7);

    // GCN2
    gemm_tc<<<dim3(mb, 2), t256>>>(gA, Wg2, hbuf, N, 128, 128, nullptr, nullptr);
    gcn_gather<<<(N + 7) / 8, t256>>>(hbuf, ssrc, ecoef, startp, dinv, bg2, gB, N, 7);

    // GCN3 (out 256)
    gemm_tc<<<dim3(mb, 4), t256>>>(gB, Wg3, hbuf, N, 128, 256, nullptr, nullptr);
    gcn_gather<<<(N + 7) / 8, t256>>>(hbuf, ssrc, ecoef, startp, dinv, bg3, gA, N, 8);

    // EdgeConv1: gA[N,256] -> gB[N,128]
    bn_coef<<<2, t256>>>(e1g, e1b, e1m, e1v, bna, bnb, 512);
    gemm_tc<<<dim3(mb, 2), t256>>>(gA, e1W, P, N, 256, 128, bna, bnb);
    zero_u32<<<(N * 128 + 255) / 256, t256>>>(Mx, N * 128);
    edgeconv_tc<<<(E + 127) / 128, t256>>>(gA, ssrc, sdst, bna + 256, bnb + 256,
                                           e1W + 256 * 128, Mx, E, 256);
    combine_kernel<<<(N * 32 + 255) / 256, t256>>>(P, Mx, indeg, gB, N);

    // EdgeConv2: gB[N,128] -> gA[N,128]  (Mx re-zeroed by previous combine)
    bn_coef<<<1, t256>>>(e2g, e2b, e2m, e2v, bna, bnb, 256);
    gemm_tc<<<dim3(mb, 2), t256>>>(gB, e2W, P, N, 128, 128, bna, bnb);
    edgeconv_tc<<<(E + 127) / 128, t256>>>(gB, ssrc, sdst, bna + 128, bnb + 128,
                                           e2W + 128 * 128, Mx, E, 128);
    combine_kernel<<<(N * 32 + 255) / 256, t256>>>(P, Mx, indeg, gA, N);

    // EdgeConv3: gA[N,128] -> gB[N,128]
    bn_coef<<<1, t256>>>(e3g, e3b, e3m, e3v, bna, bnb, 256);
    gemm_tc<<<dim3(mb, 2), t256>>>(gA, e3W, P, N, 128, 128, bna, bnb);
    edgeconv_tc<<<(E + 127) / 128, t256>>>(gA, ssrc, sdst, bna + 128, bnb + 128,
                                           e3W + 128 * 128, Mx, E, 128);
    combine_kernel<<<(N * 32 + 255) / 256, t256>>>(P, Mx, indeg, gB, N);

    // final FC -> d_out [N,1]
    fc_kernel<<<(N + 7) / 8, t256>>>(gB, Wfc, bfc, (float*)d_out, N);
}

// round 9
// speedup vs baseline: 3.2470x; 1.0841x over previous
#include <cuda_runtime.h>
#include <cuda_fp16.h>
#include <math.h>

#define NCAP 20000
#define ECAP 320000

// ---------------- static scratch (no allocation allowed) ----------------
static __device__ float    d_x0  [NCAP * 64];
static __device__ float    d_hbuf[NCAP * 256];
static __device__ float    d_gA  [NCAP * 256];
static __device__ float    d_gB  [NCAP * 256];
static __device__ float    d_P   [NCAP * 128];
static __device__ unsigned d_Mx  [NCAP * 128];
static __device__ unsigned d_u16 [NCAP * 128];   // per-layer fp16-packed scaled node rows
static __device__ unsigned d_wh  [16384];        // per-layer fp16-interleaved weights
static __device__ unsigned d_bh  [128];          // per-layer fp16-packed BN offset
static __device__ float    d_dinv[NCAP];
static __device__ int      d_indeg[NCAP];
static __device__ int      d_start[NCAP + 1];
static __device__ int      d_cnt  [NCAP];
static __device__ int      d_ssrc [ECAP];
static __device__ int      d_sdst [ECAP];
static __device__ float    d_ecoef[ECAP];
static __device__ float    d_bna [512];
static __device__ float    d_bnb [512];

// ---------------- helpers ----------------
__device__ __forceinline__ unsigned f2tf32(float x) {
    unsigned y;
    asm("cvt.rna.tf32.f32 %0, %1;" : "=r"(y) : "f"(x));
    return y;
}

__device__ __forceinline__ unsigned pack_h2(float lo, float hi) {
    __half2 h = __floats2half2_rn(lo, hi);
    return *(unsigned*)&h;
}

__device__ __forceinline__ unsigned h2_q(unsigned us, unsigned ud, unsigned bb) {
    __half2 z = __floats2half2_rn(0.f, 0.f);
    __half2 r = __hmax2(__hadd2(__hsub2(*(__half2*)&us, *(__half2*)&ud), *(__half2*)&bb), z);
    return *(unsigned*)&r;
}

__device__ __forceinline__ void mma_tf32(float* d, const unsigned* a, const unsigned* b) {
    asm volatile(
        "mma.sync.aligned.m16n8k8.row.col.f32.tf32.tf32.f32 "
        "{%0,%1,%2,%3}, {%4,%5,%6,%7}, {%8,%9}, {%0,%1,%2,%3};"
        : "+f"(d[0]), "+f"(d[1]), "+f"(d[2]), "+f"(d[3])
        : "r"(a[0]), "r"(a[1]), "r"(a[2]), "r"(a[3]), "r"(b[0]), "r"(b[1]));
}

__device__ __forceinline__ void mma_f16(float* d, const unsigned* a, const unsigned* b) {
    asm volatile(
        "mma.sync.aligned.m16n8k16.row.col.f32.f16.f16.f32 "
        "{%0,%1,%2,%3}, {%4,%5,%6,%7}, {%8,%9}, {%0,%1,%2,%3};"
        : "+f"(d[0]), "+f"(d[1]), "+f"(d[2]), "+f"(d[3])
        : "r"(a[0]), "r"(a[1]), "r"(a[2]), "r"(a[3]), "r"(b[0]), "r"(b[1]));
}

__device__ __forceinline__ void red_max_enc(unsigned* p, float v) {
    unsigned u = __float_as_uint(v);
    unsigned key = (u & 0x80000000u) ? ~u : (u | 0x80000000u);
    asm volatile("red.global.max.u32 [%0], %1;" :: "l"(p), "r"(key) : "memory");
}

// ---------------- small elementwise kernels ----------------
__global__ void zero_i32(int* p, int n) {
    int i = blockIdx.x * 256 + threadIdx.x;
    if (i < n) p[i] = 0;
}
__global__ void zero_u32(unsigned* p, int n) {
    int i = blockIdx.x * 256 + threadIdx.x;
    if (i < n) p[i] = 0u;
}
__global__ void count_indeg(const int* __restrict__ dstv, int* __restrict__ indeg, int E) {
    int e = blockIdx.x * 256 + threadIdx.x;
    if (e < E) atomicAdd(&indeg[dstv[e]], 1);
}
__global__ void compute_dinv(const int* __restrict__ indeg, float* __restrict__ dinv, int N) {
    int i = blockIdx.x * 256 + threadIdx.x;
    if (i < N) dinv[i] = rsqrtf((float)indeg[i] + 1.0f);
}
__global__ void bn_coef(const float* __restrict__ g, const float* __restrict__ be,
                        const float* __restrict__ me, const float* __restrict__ va,
                        float* __restrict__ a, float* __restrict__ b, int n) {
    int i = blockIdx.x * 256 + threadIdx.x;
    if (i < n) {
        float ai = g[i] * rsqrtf(va[i] + 1e-5f);
        a[i] = ai;
        b[i] = be[i] - me[i] * ai;
    }
}

// ---------------- per-layer prep: u16 = fp16(a2 .* g), b16 packed ----------------
__global__ void prep_u16(const float* __restrict__ g, const float* __restrict__ a2,
                         const float* __restrict__ b2, unsigned* __restrict__ u16,
                         unsigned* __restrict__ b16, int N, int lc2)
{
    int idx = blockIdx.x * 256 + threadIdx.x;
    int C2 = 1 << lc2;
    if (idx < (N << lc2)) {
        int i = idx >> lc2, k2 = idx & (C2 - 1);
        float2 gv = *(const float2*)&g[((long long)i << (lc2 + 1)) + 2 * k2];
        float2 av = *(const float2*)&a2[2 * k2];
        u16[idx] = pack_h2(av.x * gv.x, av.y * gv.y);
    }
    if (idx < C2) {
        float2 bv = *(const float2*)&b2[2 * idx];
        b16[idx] = pack_h2(bv.x, bv.y);
    }
}

// ---------------- per-layer prep: Wh[k2*128+n] = half2(W[2k2][n], W[2k2+1][n]) ----------------
__global__ void prep_w16(const float* __restrict__ W, unsigned* __restrict__ Wh, int half_rows)
{
    int idx = blockIdx.x * 256 + threadIdx.x;
    if (idx < half_rows * 128) {
        int k2 = idx >> 7, n = idx & 127;
        Wh[idx] = pack_h2(W[(2 * k2) * 128 + n], W[(2 * k2 + 1) * 128 + n]);
    }
}

// ---------------- exclusive scan over indeg -> start (single block, 1024 thr) ----------------
__global__ __launch_bounds__(1024) void scan_kernel(const int* __restrict__ indeg,
                                                    int* __restrict__ start, int N) {
    __shared__ int wsum[32];
    int t = threadIdx.x;
    int chunk = (N + 1023) / 1024;
    int lo = t * chunk;
    int hi = lo + chunk; if (hi > N) hi = N; if (lo > N) lo = N;
    int s = 0;
    for (int i = lo; i < hi; i++) s += indeg[i];
    int lane = t & 31, w = t >> 5;
    int v = s;
#pragma unroll
    for (int o = 1; o < 32; o <<= 1) {
        int u = __shfl_up_sync(0xffffffffu, v, o);
        if (lane >= o) v += u;
    }
    if (lane == 31) wsum[w] = v;
    __syncthreads();
    if (w == 0) {
        int x = wsum[lane];
#pragma unroll
        for (int o = 1; o < 32; o <<= 1) {
            int u = __shfl_up_sync(0xffffffffu, x, o);
            if (lane >= o) x += u;
        }
        wsum[lane] = x;
    }
    __syncthreads();
    int excl = (v - s) + (w > 0 ? wsum[w - 1] : 0);
    int run = excl;
    for (int i = lo; i < hi; i++) { start[i] = run; run += indeg[i]; }
    if (t == 1023) start[N] = run;
}

// ---------------- counting-sort scatter: edges sorted by dst (+ per-edge GCN coef) ----------------
__global__ void scatter_edges(const int* __restrict__ src, const int* __restrict__ dstv,
                              const int* __restrict__ start, int* __restrict__ cnt,
                              const float* __restrict__ dinv,
                              int* __restrict__ ssrc, int* __restrict__ sdst,
                              float* __restrict__ ecoef, int E) {
    int e = blockIdx.x * 256 + threadIdx.x;
    if (e < E) {
        int s = src[e], d = dstv[e];
        int p = start[d] + atomicAdd(&cnt[d], 1);
        ssrc[p] = s;
        sdst[p] = d;
        ecoef[p] = dinv[s] * dinv[d];
    }
}

// ---------------- fused dual-projection GEMM (fp32 SIMT) ----------------
__global__ __launch_bounds__(256) void proj_kernel(
    const float* __restrict__ A,
    const float* __restrict__ Bm, const float* __restrict__ bm,
    const float* __restrict__ Bc, const float* __restrict__ bc,
    float* __restrict__ C, int Mrows)
{
    const int K = 512;
    __shared__ float As[16][65];
    __shared__ float Bms[16][64];
    __shared__ float Bcs[16][64];
    int tid = threadIdx.x;
    int tx = tid & 15, ty = tid >> 4;
    int row0 = blockIdx.x * 64;
    float acc[4][4] = {};
    for (int k0 = 0; k0 < K; k0 += 16) {
#pragma unroll
        for (int i = 0; i < 4; i++) {
            int lin = tid + i * 256;
            int r = lin >> 4, kk = lin & 15;
            int gr = row0 + r;
            As[kk][r] = (gr < Mrows) ? A[gr * K + k0 + kk] : 0.f;
        }
#pragma unroll
        for (int i = 0; i < 4; i++) {
            int lin = tid + i * 256;
            int kk = lin >> 6, n = lin & 63;
            Bms[kk][n] = Bm[(k0 + kk) * 64 + n];
            Bcs[kk][n] = Bc[(k0 + kk) * 64 + n];
        }
        __syncthreads();
#pragma unroll
        for (int kk = 0; kk < 16; kk++) {
            float4 bmv = *(const float4*)&Bms[kk][tx * 4];
            float4 bcv = *(const float4*)&Bcs[kk][tx * 4];
            float av0 = As[kk][ty * 4 + 0];
            acc[0][0] += av0 * bmv.x; acc[0][1] += av0 * bmv.y;
            acc[0][2] += av0 * bmv.z; acc[0][3] += av0 * bmv.w;
#pragma unroll
            for (int r = 1; r < 4; r++) {
                float av = As[kk][ty * 4 + r];
                acc[r][0] += av * bcv.x; acc[r][1] += av * bcv.y;
                acc[r][2] += av * bcv.z; acc[r][3] += av * bcv.w;
            }
        }
        __syncthreads();
    }
#pragma unroll
    for (int r = 0; r < 4; r++) {
        int gr = row0 + ty * 4 + r;
        if (gr < Mrows) {
#pragma unroll
            for (int c = 0; c < 4; c++) {
                float bias = (r == 0) ? bm[tx * 4 + c] : bc[tx * 4 + c];
                C[gr * 64 + tx * 4 + c] = acc[r][c] + bias;
            }
        }
    }
}

// ---------------- TF32 tensor-core node GEMM: C = f(A) @ B (float4 fills) ----------------
__global__ __launch_bounds__(256) void gemm_tc(
    const float* __restrict__ A, const float* __restrict__ B, float* __restrict__ C,
    int M, int K, int Ncols,
    const float* __restrict__ ta, const float* __restrict__ tb)
{
    __shared__ unsigned As[64 * 36];
    __shared__ unsigned Bs[32 * 72];
    int tid = threadIdx.x;
    int lane = tid & 31, warp = tid >> 5;
    int wm = warp & 3, wn = warp >> 2;
    int gid = lane >> 2, tig = lane & 3;
    int row0 = blockIdx.x * 64;
    int col0 = blockIdx.y * 64;
    float acc[4][4] = {};
    for (int k0 = 0; k0 < K; k0 += 32) {
#pragma unroll
        for (int i = 0; i < 2; i++) {
            int lin = tid + i * 256;          // 0..511
            int r = lin >> 3;                 // 0..63
            int k4 = (lin & 7) * 4;
            int gr = row0 + r;
            float4 v = make_float4(0.f, 0.f, 0.f, 0.f);
            if (gr < M) {
                v = *(const float4*)&A[(long long)gr * K + k0 + k4];
                if (ta) {
                    float4 a4 = *(const float4*)&ta[k0 + k4];
                    float4 b4 = *(const float4*)&tb[k0 + k4];
                    v.x = fmaxf(a4.x * v.x + b4.x, 0.f);
                    v.y = fmaxf(a4.y * v.y + b4.y, 0.f);
                    v.z = fmaxf(a4.z * v.z + b4.z, 0.f);
                    v.w = fmaxf(a4.w * v.w + b4.w, 0.f);
                }
            }
            *(uint4*)&As[r * 36 + k4] =
                make_uint4(f2tf32(v.x), f2tf32(v.y), f2tf32(v.z), f2tf32(v.w));
        }
#pragma unroll
        for (int i = 0; i < 2; i++) {
            int lin = tid + i * 256;
            int k = lin >> 4;                 // 0..31
            int n4 = (lin & 15) * 4;
            float4 w4 = *(const float4*)&B[(long long)(k0 + k) * Ncols + col0 + n4];
            *(uint4*)&Bs[k * 72 + n4] =
                make_uint4(f2tf32(w4.x), f2tf32(w4.y), f2tf32(w4.z), f2tf32(w4.w));
        }
        __syncthreads();
#pragma unroll
        for (int s = 0; s < 4; s++) {
            unsigned a[4];
            int ar = wm * 16 + gid;
            int ac = s * 8 + tig;
            a[0] = As[ar * 36 + ac];
            a[1] = As[(ar + 8) * 36 + ac];
            a[2] = As[ar * 36 + ac + 4];
            a[3] = As[(ar + 8) * 36 + ac + 4];
#pragma unroll
            for (int nt = 0; nt < 4; nt++) {
                unsigned b[2];
                int bc = wn * 32 + nt * 8 + gid;
                b[0] = Bs[(s * 8 + tig) * 72 + bc];
                b[1] = Bs[(s * 8 + tig + 4) * 72 + bc];
                mma_tf32(acc[nt], a, b);
            }
        }
        __syncthreads();
    }
#pragma unroll
    for (int half = 0; half < 2; half++) {
        int gr = row0 + wm * 16 + gid + half * 8;
        if (gr < M) {
#pragma unroll
            for (int nt = 0; nt < 4; nt++) {
                int col = col0 + wn * 32 + nt * 8 + tig * 2;
                C[gr * Ncols + col]     = acc[nt][half * 2 + 0];
                C[gr * Ncols + col + 1] = acc[nt][half * 2 + 1];
            }
        }
    }
}

// ---------------- GCN aggregation: CSR gather, warp-batched indices + precomputed coef ----------------
__global__ __launch_bounds__(256) void gcn_gather(
    const float* __restrict__ h, const int* __restrict__ ssrc,
    const float* __restrict__ ecoef, const int* __restrict__ start,
    const float* __restrict__ dinv, const float* __restrict__ bias,
    float* __restrict__ out, int N, int lc)
{
    int node = blockIdx.x * 8 + (threadIdx.x >> 5);
    int lane = threadIdx.x & 31;
    if (node >= N) return;
    int groups = 1 << (lc - 7);          // 1 (128 cols) or 2 (256 cols)
    float di = dinv[node];
    float di2 = di * di;
    float4 acc[2];
#pragma unroll
    for (int j = 0; j < 2; j++) {
        if (j < groups) {
            int col = j * 128 + lane * 4;
            float4 hv = *(const float4*)&h[((long long)node << lc) + col];
            float4 bv = *(const float4*)&bias[col];
            acc[j].x = bv.x + di2 * hv.x;
            acc[j].y = bv.y + di2 * hv.y;
            acc[j].z = bv.z + di2 * hv.z;
            acc[j].w = bv.w + di2 * hv.w;
        }
    }
    int s0 = start[node], s1 = start[node + 1];
    for (int base = s0; base < s1; base += 32) {
        int e = base + lane;
        int sidx = 0; float cf = 0.f;
        if (e < s1) { sidx = ssrc[e]; cf = ecoef[e]; }
        int cnt = s1 - base; if (cnt > 32) cnt = 32;
        for (int j = 0; j < cnt; j++) {
            int s = __shfl_sync(0xffffffffu, sidx, j);
            float coef = __shfl_sync(0xffffffffu, cf, j);
            const float* hrow = &h[(long long)s << lc];
#pragma unroll
            for (int g = 0; g < 2; g++) {
                if (g < groups) {
                    float4 hv = *(const float4*)&hrow[g * 128 + lane * 4];
                    acc[g].x += coef * hv.x;
                    acc[g].y += coef * hv.y;
                    acc[g].z += coef * hv.z;
                    acc[g].w += coef * hv.w;
                }
            }
        }
    }
#pragma unroll
    for (int j = 0; j < 2; j++) {
        if (j < groups)
            *(float4*)&out[((long long)node << lc) + j * 128 + lane * 4] = acc[j];
    }
}

// ---------------- EdgeConv: 128-edge FP16 tiles, prepacked u16/Wh, half2 fill, segmented max ----------------
// smem (unsigned units): qh 128 x stride 20 = 2560; wh 16 x stride 136 = 2176; sacc overlay 32*132 fits.
__global__ __launch_bounds__(256) void edgeconv_tc(
    const unsigned* __restrict__ u16, const unsigned* __restrict__ b16,
    const unsigned* __restrict__ Whg,
    const int* __restrict__ ssrc, const int* __restrict__ sdstv,
    unsigned* __restrict__ Mout, int E, int lc2)   // lc2: log2(C/2) -> 6 or 7
{
    __shared__ unsigned sh[128 * 20 + 16 * 136];
    __shared__ int ss[128], sd[128];
    unsigned* qh = sh;                 // [edge][k2] stride 20
    unsigned* wh = sh + 128 * 20;      // [k2][n]  stride 136
    int tid = threadIdx.x;
    int e0 = blockIdx.x * 128;
    if (tid < 128) {
        int e = e0 + tid;
        if (e >= E) e = E - 1;
        ss[tid] = ssrc[e];
        sd[tid] = sdstv[e];
    }
    __syncthreads();
    int lane = tid & 31, warp = tid >> 5;
    int wm = warp & 3, wn = warp >> 2;
    int gid = lane >> 2, tig = lane & 3;
    int C2 = 1 << lc2;
    float acc[2][8][4] = {};
    for (int k20 = 0; k20 < C2; k20 += 16) {
        // qh fill: 128 edges x 16 half2 -> 512 uint4 items
#pragma unroll
        for (int i = 0; i < 2; i++) {
            int lin = tid + i * 256;          // 0..511
            int e = lin >> 2;                 // 0..127
            int q4 = (lin & 3) * 4;           // half2 offset
            int k2g = k20 + q4;
            uint4 us = *(const uint4*)&u16[(ss[e] << lc2) + k2g];
            uint4 ud = *(const uint4*)&u16[(sd[e] << lc2) + k2g];
            uint4 bb = *(const uint4*)&b16[k2g];
            uint4 r;
            r.x = h2_q(us.x, ud.x, bb.x);
            r.y = h2_q(us.y, ud.y, bb.y);
            r.z = h2_q(us.z, ud.z, bb.z);
            r.w = h2_q(us.w, ud.w, bb.w);
            *(uint4*)&qh[e * 20 + q4] = r;
        }
        // wh fill: raw copy of prepacked interleaved weights, 16 x 128 half2
#pragma unroll
        for (int i = 0; i < 2; i++) {
            int lin = tid + i * 256;
            int k2 = lin >> 5;                // 0..15
            int n4 = (lin & 31) * 4;
            *(uint4*)&wh[k2 * 136 + n4] =
                *(const uint4*)&Whg[(k20 + k2) * 128 + n4];
        }
        __syncthreads();
#pragma unroll
        for (int s = 0; s < 2; s++) {
            unsigned bf[8][2];
#pragma unroll
            for (int nt = 0; nt < 8; nt++) {
                int bc = wn * 64 + nt * 8 + gid;
                bf[nt][0] = wh[(s * 8 + tig) * 136 + bc];
                bf[nt][1] = wh[(s * 8 + tig + 4) * 136 + bc];
            }
            int ac = s * 8 + tig;
#pragma unroll
            for (int mt = 0; mt < 2; mt++) {
                unsigned a[4];
                int ar = wm * 32 + mt * 16 + gid;
                a[0] = qh[ar * 20 + ac];
                a[1] = qh[(ar + 8) * 20 + ac];
                a[2] = qh[ar * 20 + ac + 4];
                a[3] = qh[(ar + 8) * 20 + ac + 4];
#pragma unroll
                for (int nt = 0; nt < 8; nt++)
                    mma_f16(acc[mt][nt], a, bf[nt]);
            }
        }
        __syncthreads();
    }
    // segmented max: 4 passes of 32 rows (dst-sorted); smem reuse
    float* sacc = (float*)sh;
#pragma unroll
    for (int pass = 0; pass < 4; pass++) {
        if (wm == pass) {
#pragma unroll
            for (int mt = 0; mt < 2; mt++) {
#pragma unroll
                for (int half = 0; half < 2; half++) {
                    int rl = mt * 16 + gid + half * 8;   // 0..31
#pragma unroll
                    for (int nt = 0; nt < 8; nt++) {
                        int col = wn * 64 + nt * 8 + tig * 2;
                        sacc[rl * 132 + col]     = acc[mt][nt][half * 2 + 0];
                        sacc[rl * 132 + col + 1] = acc[mt][nt][half * 2 + 1];
                    }
                }
            }
        }
        __syncthreads();
        {
            int col = tid & 127;
            int rh = tid >> 7;                  // 0..1
            int r0 = rh * 16, r1 = r0 + 16;
            int base = pass * 32;
            int cur = sd[base + r0];
            float m = sacc[r0 * 132 + col];
            for (int r = r0 + 1; r < r1; r++) {
                int d = sd[base + r];
                float v = sacc[r * 132 + col];
                if (d != cur) {
                    red_max_enc(&Mout[(long long)cur * 128 + col], m);
                    cur = d;
                    m = v;
                } else {
                    m = fmaxf(m, v);
                }
            }
            red_max_enc(&Mout[(long long)cur * 128 + col], m);
        }
        __syncthreads();
    }
}

// ---------------- EdgeConv combine: out = indeg>0 ? P + decode(M) : 0 ; resets M to 0 ----------------
__global__ void combine_kernel(const float* __restrict__ P, unsigned* __restrict__ Mv,
                               const int* __restrict__ indeg, float* __restrict__ out, int N)
{
    int idx4 = blockIdx.x * 256 + threadIdx.x;
    if (idx4 >= N * 32) return;
    int i = idx4 >> 5;
    uint4 kv = *(uint4*)&Mv[idx4 * 4];
    float4 pv = *(const float4*)&P[idx4 * 4];
    float4 o = make_float4(0.f, 0.f, 0.f, 0.f);
    if (indeg[i] > 0) {
        unsigned u0 = (kv.x & 0x80000000u) ? (kv.x & 0x7fffffffu) : ~kv.x;
        unsigned u1 = (kv.y & 0x80000000u) ? (kv.y & 0x7fffffffu) : ~kv.y;
        unsigned u2 = (kv.z & 0x80000000u) ? (kv.z & 0x7fffffffu) : ~kv.z;
        unsigned u3 = (kv.w & 0x80000000u) ? (kv.w & 0x7fffffffu) : ~kv.w;
        o.x = pv.x + __uint_as_float(u0);
        o.y = pv.y + __uint_as_float(u1);
        o.z = pv.z + __uint_as_float(u2);
        o.w = pv.w + __uint_as_float(u3);
    }
    *(uint4*)&Mv[idx4 * 4] = make_uint4(0u, 0u, 0u, 0u);   // re-zero for next layer
    *(float4*)&out[idx4 * 4] = o;
}

// ---------------- final FC ----------------
__global__ void fc_kernel(const float* __restrict__ h, const float* __restrict__ W,
                          const float* __restrict__ b, float* __restrict__ out, int N)
{
    int warp = (blockIdx.x * 256 + threadIdx.x) >> 5;
    int lane = threadIdx.x & 31;
    if (warp >= N) return;
    float s = 0.f;
#pragma unroll
    for (int j = lane; j < 128; j += 32) s += h[warp * 128 + j] * W[j];
#pragma unroll
    for (int o = 16; o; o >>= 1) s += __shfl_down_sync(0xffffffffu, s, o);
    if (lane == 0) out[warp] = s + b[0];
}

// ---------------- launch ----------------
extern "C" void kernel_launch(void* const* d_in, const int* in_sizes, int n_in,
                              void* d_out, int out_size)
{
    const float* x   = (const float*)d_in[0];
    const int*   ei  = (const int*)d_in[1];
    const float* Wm  = (const float*)d_in[2];
    const float* bm  = (const float*)d_in[3];
    const float* Wc  = (const float*)d_in[4];
    const float* bc  = (const float*)d_in[5];
    const float* Wg1 = (const float*)d_in[6];
    const float* bg1 = (const float*)d_in[7];
    const float* Wg2 = (const float*)d_in[8];
    const float* bg2 = (const float*)d_in[9];
    const float* Wg3 = (const float*)d_in[10];
    const float* bg3 = (const float*)d_in[11];
    const float* e1g = (const float*)d_in[12];
    const float* e1b = (const float*)d_in[13];
    const float* e1m = (const float*)d_in[14];
    const float* e1v = (const float*)d_in[15];
    const float* e1W = (const float*)d_in[16];
    const float* e2g = (const float*)d_in[17];
    const float* e2b = (const float*)d_in[18];
    const float* e2m = (const float*)d_in[19];
    const float* e2v = (const float*)d_in[20];
    const float* e2W = (const float*)d_in[21];
    const float* e3g = (const float*)d_in[22];
    const float* e3b = (const float*)d_in[23];
    const float* e3m = (const float*)d_in[24];
    const float* e3v = (const float*)d_in[25];
    const float* e3W = (const float*)d_in[26];
    const float* Wfc = (const float*)d_in[27];
    const float* bfc = (const float*)d_in[28];

    int N = in_sizes[0] / 512;
    int E = in_sizes[1] / 2;
    const int* src = ei;
    const int* dst = ei + E;

    float *x0, *hbuf, *gA, *gB, *P, *dinv, *bna, *bnb, *ecoef;
    unsigned *Mx, *u16p, *whp, *bhp;
    int *indeg, *startp, *cnt, *ssrc, *sdst;
    cudaGetSymbolAddress((void**)&x0,    d_x0);
    cudaGetSymbolAddress((void**)&hbuf,  d_hbuf);
    cudaGetSymbolAddress((void**)&gA,    d_gA);
    cudaGetSymbolAddress((void**)&gB,    d_gB);
    cudaGetSymbolAddress((void**)&P,     d_P);
    cudaGetSymbolAddress((void**)&Mx,    d_Mx);
    cudaGetSymbolAddress((void**)&u16p,  d_u16);
    cudaGetSymbolAddress((void**)&whp,   d_wh);
    cudaGetSymbolAddress((void**)&bhp,   d_bh);
    cudaGetSymbolAddress((void**)&dinv,  d_dinv);
    cudaGetSymbolAddress((void**)&indeg, d_indeg);
    cudaGetSymbolAddress((void**)&startp,d_start);
    cudaGetSymbolAddress((void**)&cnt,   d_cnt);
    cudaGetSymbolAddress((void**)&ssrc,  d_ssrc);
    cudaGetSymbolAddress((void**)&sdst,  d_sdst);
    cudaGetSymbolAddress((void**)&ecoef, d_ecoef);
    cudaGetSymbolAddress((void**)&bna,   d_bna);
    cudaGetSymbolAddress((void**)&bnb,   d_bnb);

    dim3 t256(256);
    int mb = (N + 63) / 64;

    // input projection (fused row-select), fp32
    proj_kernel<<<mb, t256>>>(x, Wm, bm, Wc, bc, x0, N);

    // degrees + CSR sort by dst (+ per-edge coef)
    zero_i32<<<(N + 255) / 256, t256>>>(indeg, N);
    count_indeg<<<(E + 255) / 256, t256>>>(dst, indeg, E);
    compute_dinv<<<(N + 255) / 256, t256>>>(indeg, dinv, N);
    scan_kernel<<<1, 1024>>>(indeg, startp, N);
    zero_i32<<<(N + 255) / 256, t256>>>(cnt, N);
    scatter_edges<<<(E + 255) / 256, t256>>>(src, dst, startp, cnt, dinv, ssrc, sdst, ecoef, E);

    // GCN1: x0[N,64] @ Wg1[64,128] -> hbuf; gather -> gA
    gemm_tc<<<dim3(mb, 2), t256>>>(x0, Wg1, hbuf, N, 64, 128, nullptr, nullptr);
    gcn_gather<<<(N + 7) / 8, t256>>>(hbuf, ssrc, ecoef, startp, dinv, bg1, gA, N, 7);

    // GCN2
    gemm_tc<<<dim3(mb, 2), t256>>>(gA, Wg2, hbuf, N, 128, 128, nullptr, nullptr);
    gcn_gather<<<(N + 7) / 8, t256>>>(hbuf, ssrc, ecoef, startp, dinv, bg2, gB, N, 7);

    // GCN3 (out 256)
    gemm_tc<<<dim3(mb, 4), t256>>>(gB, Wg3, hbuf, N, 128, 256, nullptr, nullptr);
    gcn_gather<<<(N + 7) / 8, t256>>>(hbuf, ssrc, ecoef, startp, dinv, bg3, gA, N, 8);

    // EdgeConv1: gA[N,256] -> gB[N,128]
    bn_coef<<<2, t256>>>(e1g, e1b, e1m, e1v, bna, bnb, 512);
    gemm_tc<<<dim3(mb, 2), t256>>>(gA, e1W, P, N, 256, 128, bna, bnb);
    prep_u16<<<(N * 128 + 255) / 256, t256>>>(gA, bna + 256, bnb + 256, u16p, bhp, N, 7);
    prep_w16<<<(128 * 128 + 255) / 256, t256>>>(e1W + 256 * 128, whp, 128);
    zero_u32<<<(N * 128 + 255) / 256, t256>>>(Mx, N * 128);
    edgeconv_tc<<<(E + 127) / 128, t256>>>(u16p, bhp, whp, ssrc, sdst, Mx, E, 7);
    combine_kernel<<<(N * 32 + 255) / 256, t256>>>(P, Mx, indeg, gB, N);

    // EdgeConv2: gB[N,128] -> gA[N,128]  (Mx re-zeroed by previous combine)
    bn_coef<<<1, t256>>>(e2g, e2b, e2m, e2v, bna, bnb, 256);
    gemm_tc<<<dim3(mb, 2), t256>>>(gB, e2W, P, N, 128, 128, bna, bnb);
    prep_u16<<<(N * 64 + 255) / 256, t256>>>(gB, bna + 128, bnb + 128, u16p, bhp, N, 6);
    prep_w16<<<(64 * 128 + 255) / 256, t256>>>(e2W + 128 * 128, whp, 64);
    edgeconv_tc<<<(E + 127) / 128, t256>>>(u16p, bhp, whp, ssrc, sdst, Mx, E, 6);
    combine_kernel<<<(N * 32 + 255) / 256, t256>>>(P, Mx, indeg, gA, N);

    // EdgeConv3: gA[N,128] -> gB[N,128]
    bn_coef<<<1, t256>>>(e3g, e3b, e3m, e3v, bna, bnb, 256);
    gemm_tc<<<dim3(mb, 2), t256>>>(gA, e3W, P, N, 128, 128, bna, bnb);
    prep_u16<<<(N * 64 + 255) / 256, t256>>>(gA, bna + 128, bnb + 128, u16p, bhp, N, 6);
    prep_w16<<<(64 * 128 + 255) / 256, t256>>>(e3W + 128 * 128, whp, 64);
    edgeconv_tc<<<(E + 127) / 128, t256>>>(u16p, bhp, whp, ssrc, sdst, Mx, E, 6);
    combine_kernel<<<(N * 32 + 255) / 256, t256>>>(P, Mx, indeg, gB, N);

    // final FC -> d_out [N,1]
    fc_kernel<<<(N + 7) / 8, t256>>>(gB, Wfc, bfc, (float*)d_out, N);
}

// round 10
// speedup vs baseline: 3.3009x; 1.0166x over previous
#include <cuda_runtime.h>
#include <cuda_fp16.h>
#include <math.h>

#define NCAP 20000
#define ECAP 320000

// ---------------- static scratch (no allocation allowed) ----------------
static __device__ float    d_x0  [NCAP * 64];
static __device__ float    d_hbuf[NCAP * 256];
static __device__ float    d_gA  [NCAP * 256];
static __device__ float    d_gB  [NCAP * 256];
static __device__ float    d_P   [NCAP * 128];
static __device__ unsigned d_Mx  [NCAP * 128];
static __device__ unsigned d_u16 [NCAP * 128];   // per-layer fp16-packed scaled node rows
static __device__ unsigned d_wh  [32768];        // fp16-interleaved weights, ALL 3 edge layers
static __device__ unsigned d_bh  [256];          // fp16-packed BN offsets, ALL 3 edge layers
static __device__ float    d_dinv[NCAP];
static __device__ int      d_indeg[NCAP];
static __device__ int      d_start[NCAP + 1];
static __device__ int      d_cnt  [NCAP];
static __device__ int      d_ssrc [ECAP];
static __device__ int      d_sdst [ECAP];
static __device__ float    d_ecoef[ECAP];
static __device__ float    d_bna [1024];         // BN scale, layers at 0 / 512 / 768
static __device__ float    d_bnb [1024];         // BN offset

// ---------------- helpers ----------------
__device__ __forceinline__ unsigned f2tf32(float x) {
    unsigned y;
    asm("cvt.rna.tf32.f32 %0, %1;" : "=r"(y) : "f"(x));
    return y;
}

__device__ __forceinline__ unsigned pack_h2(float lo, float hi) {
    __half2 h = __floats2half2_rn(lo, hi);
    return *(unsigned*)&h;
}

__device__ __forceinline__ unsigned h2_q(unsigned us, unsigned ud, unsigned bb) {
    __half2 z = __floats2half2_rn(0.f, 0.f);
    __half2 r = __hmax2(__hadd2(__hsub2(*(__half2*)&us, *(__half2*)&ud), *(__half2*)&bb), z);
    return *(unsigned*)&r;
}

__device__ __forceinline__ void mma_tf32(float* d, const unsigned* a, const unsigned* b) {
    asm volatile(
        "mma.sync.aligned.m16n8k8.row.col.f32.tf32.tf32.f32 "
        "{%0,%1,%2,%3}, {%4,%5,%6,%7}, {%8,%9}, {%0,%1,%2,%3};"
        : "+f"(d[0]), "+f"(d[1]), "+f"(d[2]), "+f"(d[3])
        : "r"(a[0]), "r"(a[1]), "r"(a[2]), "r"(a[3]), "r"(b[0]), "r"(b[1]));
}

__device__ __forceinline__ void mma_f16(float* d, const unsigned* a, const unsigned* b) {
    asm volatile(
        "mma.sync.aligned.m16n8k16.row.col.f32.f16.f16.f32 "
        "{%0,%1,%2,%3}, {%4,%5,%6,%7}, {%8,%9}, {%0,%1,%2,%3};"
        : "+f"(d[0]), "+f"(d[1]), "+f"(d[2]), "+f"(d[3])
        : "r"(a[0]), "r"(a[1]), "r"(a[2]), "r"(a[3]), "r"(b[0]), "r"(b[1]));
}

__device__ __forceinline__ void red_max_enc(unsigned* p, float v) {
    unsigned u = __float_as_uint(v);
    unsigned key = (u & 0x80000000u) ? ~u : (u | 0x80000000u);
    asm volatile("red.global.max.u32 [%0], %1;" :: "l"(p), "r"(key) : "memory");
}

// ---------------- small kernels ----------------
__global__ void zero_i32(int* p, int n) {
    int i = blockIdx.x * 256 + threadIdx.x;
    if (i < n) p[i] = 0;
}
__global__ void count_indeg(const int* __restrict__ dstv, int* __restrict__ indeg, int E) {
    int e = blockIdx.x * 256 + threadIdx.x;
    if (e < E) atomicAdd(&indeg[dstv[e]], 1);
}
__global__ void compute_dinv(const int* __restrict__ indeg, float* __restrict__ dinv, int N) {
    int i = blockIdx.x * 256 + threadIdx.x;
    if (i < N) dinv[i] = rsqrtf((float)indeg[i] + 1.0f);
}

// ---------------- launch-invariant prep: Mx zero + packed weights + BN coefs (ONE kernel) ----------------
__global__ void const_prep(
    const float* __restrict__ w1, const float* __restrict__ w2, const float* __restrict__ w3,
    const float* __restrict__ g1, const float* __restrict__ b1,
    const float* __restrict__ m1, const float* __restrict__ v1,
    const float* __restrict__ g2, const float* __restrict__ b2,
    const float* __restrict__ m2, const float* __restrict__ v2,
    const float* __restrict__ g3, const float* __restrict__ b3,
    const float* __restrict__ m3, const float* __restrict__ v3,
    unsigned* __restrict__ Mx, unsigned* __restrict__ wh, unsigned* __restrict__ bh,
    float* __restrict__ bna, float* __restrict__ bnb, int N)
{
    int idx = blockIdx.x * 256 + threadIdx.x;
    if (idx < N * 128) Mx[idx] = 0u;
    if (idx < 32768) {
        const float* W; int k2n;
        if (idx < 16384)      { W = w1; k2n = idx; }
        else if (idx < 24576) { W = w2; k2n = idx - 16384; }
        else                  { W = w3; k2n = idx - 24576; }
        int k2 = k2n >> 7, n = k2n & 127;
        wh[idx] = pack_h2(W[(2 * k2) * 128 + n], W[(2 * k2 + 1) * 128 + n]);
    }
    if (idx < 1024) {
        const float *g, *be, *me, *va; int i;
        if (idx < 512)      { g = g1; be = b1; me = m1; va = v1; i = idx; }
        else if (idx < 768) { g = g2; be = b2; me = m2; va = v2; i = idx - 512; }
        else                { g = g3; be = b3; me = m3; va = v3; i = idx - 768; }
        float a = g[i] * rsqrtf(va[i] + 1e-5f);
        bna[idx] = a;
        bnb[idx] = be[i] - me[i] * a;
    }
    if (idx < 256) {
        const float *g, *be, *me, *va; int c;
        if (idx < 128)      { g = g1; be = b1; me = m1; va = v1; c = 256 + 2 * idx; }
        else if (idx < 192) { g = g2; be = b2; me = m2; va = v2; c = 128 + 2 * (idx - 128); }
        else                { g = g3; be = b3; me = m3; va = v3; c = 128 + 2 * (idx - 192); }
        float a0 = g[c] * rsqrtf(va[c] + 1e-5f);
        float a1 = g[c + 1] * rsqrtf(va[c + 1] + 1e-5f);
        bh[idx] = pack_h2(be[c] - me[c] * a0, be[c + 1] - me[c + 1] * a1);
    }
}

// ---------------- exclusive scan over indeg -> start (also zeros cnt) ----------------
__global__ __launch_bounds__(1024) void scan_kernel(const int* __restrict__ indeg,
                                                    int* __restrict__ start,
                                                    int* __restrict__ cnt, int N) {
    __shared__ int wsum[32];
    int t = threadIdx.x;
    int chunk = (N + 1023) / 1024;
    int lo = t * chunk;
    int hi = lo + chunk; if (hi > N) hi = N; if (lo > N) lo = N;
    int s = 0;
    for (int i = lo; i < hi; i++) s += indeg[i];
    int lane = t & 31, w = t >> 5;
    int v = s;
#pragma unroll
    for (int o = 1; o < 32; o <<= 1) {
        int u = __shfl_up_sync(0xffffffffu, v, o);
        if (lane >= o) v += u;
    }
    if (lane == 31) wsum[w] = v;
    __syncthreads();
    if (w == 0) {
        int x = wsum[lane];
#pragma unroll
        for (int o = 1; o < 32; o <<= 1) {
            int u = __shfl_up_sync(0xffffffffu, x, o);
            if (lane >= o) x += u;
        }
        wsum[lane] = x;
    }
    __syncthreads();
    int excl = (v - s) + (w > 0 ? wsum[w - 1] : 0);
    int run = excl;
    for (int i = lo; i < hi; i++) { start[i] = run; run += indeg[i]; cnt[i] = 0; }
    if (t == 1023) start[N] = run;
}

// ---------------- counting-sort scatter: edges sorted by dst (+ per-edge GCN coef) ----------------
__global__ void scatter_edges(const int* __restrict__ src, const int* __restrict__ dstv,
                              const int* __restrict__ start, int* __restrict__ cnt,
                              const float* __restrict__ dinv,
                              int* __restrict__ ssrc, int* __restrict__ sdst,
                              float* __restrict__ ecoef, int E) {
    int e = blockIdx.x * 256 + threadIdx.x;
    if (e < E) {
        int s = src[e], d = dstv[e];
        int p = start[d] + atomicAdd(&cnt[d], 1);
        ssrc[p] = s;
        sdst[p] = d;
        ecoef[p] = dinv[s] * dinv[d];
    }
}

// ---------------- fused dual-projection GEMM (fp32 SIMT) ----------------
__global__ __launch_bounds__(256) void proj_kernel(
    const float* __restrict__ A,
    const float* __restrict__ Bm, const float* __restrict__ bm,
    const float* __restrict__ Bc, const float* __restrict__ bc,
    float* __restrict__ C, int Mrows)
{
    const int K = 512;
    __shared__ float As[16][65];
    __shared__ float Bms[16][64];
    __shared__ float Bcs[16][64];
    int tid = threadIdx.x;
    int tx = tid & 15, ty = tid >> 4;
    int row0 = blockIdx.x * 64;
    float acc[4][4] = {};
    for (int k0 = 0; k0 < K; k0 += 16) {
#pragma unroll
        for (int i = 0; i < 4; i++) {
            int lin = tid + i * 256;
            int r = lin >> 4, kk = lin & 15;
            int gr = row0 + r;
            As[kk][r] = (gr < Mrows) ? A[gr * K + k0 + kk] : 0.f;
        }
#pragma unroll
        for (int i = 0; i < 4; i++) {
            int lin = tid + i * 256;
            int kk = lin >> 6, n = lin & 63;
            Bms[kk][n] = Bm[(k0 + kk) * 64 + n];
            Bcs[kk][n] = Bc[(k0 + kk) * 64 + n];
        }
        __syncthreads();
#pragma unroll
        for (int kk = 0; kk < 16; kk++) {
            float4 bmv = *(const float4*)&Bms[kk][tx * 4];
            float4 bcv = *(const float4*)&Bcs[kk][tx * 4];
            float av0 = As[kk][ty * 4 + 0];
            acc[0][0] += av0 * bmv.x; acc[0][1] += av0 * bmv.y;
            acc[0][2] += av0 * bmv.z; acc[0][3] += av0 * bmv.w;
#pragma unroll
            for (int r = 1; r < 4; r++) {
                float av = As[kk][ty * 4 + r];
                acc[r][0] += av * bcv.x; acc[r][1] += av * bcv.y;
                acc[r][2] += av * bcv.z; acc[r][3] += av * bcv.w;
            }
        }
        __syncthreads();
    }
#pragma unroll
    for (int r = 0; r < 4; r++) {
        int gr = row0 + ty * 4 + r;
        if (gr < Mrows) {
#pragma unroll
            for (int c = 0; c < 4; c++) {
                float bias = (r == 0) ? bm[tx * 4 + c] : bc[tx * 4 + c];
                C[gr * 64 + tx * 4 + c] = acc[r][c] + bias;
            }
        }
    }
}

// ---------------- TF32 tensor-core node GEMM: C = f(A) @ B (float4 fills) ----------------
__global__ __launch_bounds__(256) void gemm_tc(
    const float* __restrict__ A, const float* __restrict__ B, float* __restrict__ C,
    int M, int K, int Ncols,
    const float* __restrict__ ta, const float* __restrict__ tb)
{
    __shared__ unsigned As[64 * 36];
    __shared__ unsigned Bs[32 * 72];
    int tid = threadIdx.x;
    int lane = tid & 31, warp = tid >> 5;
    int wm = warp & 3, wn = warp >> 2;
    int gid = lane >> 2, tig = lane & 3;
    int row0 = blockIdx.x * 64;
    int col0 = blockIdx.y * 64;
    float acc[4][4] = {};
    for (int k0 = 0; k0 < K; k0 += 32) {
#pragma unroll
        for (int i = 0; i < 2; i++) {
            int lin = tid + i * 256;          // 0..511
            int r = lin >> 3;                 // 0..63
            int k4 = (lin & 7) * 4;
            int gr = row0 + r;
            float4 v = make_float4(0.f, 0.f, 0.f, 0.f);
            if (gr < M) {
                v = *(const float4*)&A[(long long)gr * K + k0 + k4];
                if (ta) {
                    float4 a4 = *(const float4*)&ta[k0 + k4];
                    float4 b4 = *(const float4*)&tb[k0 + k4];
                    v.x = fmaxf(a4.x * v.x + b4.x, 0.f);
                    v.y = fmaxf(a4.y * v.y + b4.y, 0.f);
                    v.z = fmaxf(a4.z * v.z + b4.z, 0.f);
                    v.w = fmaxf(a4.w * v.w + b4.w, 0.f);
                }
            }
            *(uint4*)&As[r * 36 + k4] =
                make_uint4(f2tf32(v.x), f2tf32(v.y), f2tf32(v.z), f2tf32(v.w));
        }
#pragma unroll
        for (int i = 0; i < 2; i++) {
            int lin = tid + i * 256;
            int k = lin >> 4;                 // 0..31
            int n4 = (lin & 15) * 4;
            float4 w4 = *(const float4*)&B[(long long)(k0 + k) * Ncols + col0 + n4];
            *(uint4*)&Bs[k * 72 + n4] =
                make_uint4(f2tf32(w4.x), f2tf32(w4.y), f2tf32(w4.z), f2tf32(w4.w));
        }
        __syncthreads();
#pragma unroll
        for (int s = 0; s < 4; s++) {
            unsigned a[4];
            int ar = wm * 16 + gid;
            int ac = s * 8 + tig;
            a[0] = As[ar * 36 + ac];
            a[1] = As[(ar + 8) * 36 + ac];
            a[2] = As[ar * 36 + ac + 4];
            a[3] = As[(ar + 8) * 36 + ac + 4];
#pragma unroll
            for (int nt = 0; nt < 4; nt++) {
                unsigned b[2];
                int bc = wn * 32 + nt * 8 + gid;
                b[0] = Bs[(s * 8 + tig) * 72 + bc];
                b[1] = Bs[(s * 8 + tig + 4) * 72 + bc];
                mma_tf32(acc[nt], a, b);
            }
        }
        __syncthreads();
    }
#pragma unroll
    for (int half = 0; half < 2; half++) {
        int gr = row0 + wm * 16 + gid + half * 8;
        if (gr < M) {
#pragma unroll
            for (int nt = 0; nt < 4; nt++) {
                int col = col0 + wn * 32 + nt * 8 + tig * 2;
                C[gr * Ncols + col]     = acc[nt][half * 2 + 0];
                C[gr * Ncols + col + 1] = acc[nt][half * 2 + 1];
            }
        }
    }
}

// ---------------- GCN aggregation: CSR gather, 4-way MLP unroll; optional fused u16 emit ----------------
// out[i] = bias + dinv[i]^2 * h[i] + sum_e ecoef[e] * h[src[e]]
// if a2u != null: also write u16[i] = fp16(a2u .* out[i])  (for the following EdgeConv layer)
__global__ __launch_bounds__(256) void gcn_gather(
    const float* __restrict__ h, const int* __restrict__ ssrc,
    const float* __restrict__ ecoef, const int* __restrict__ start,
    const float* __restrict__ dinv, const float* __restrict__ bias,
    float* __restrict__ out, int N, int lc,
    const float* __restrict__ a2u, unsigned* __restrict__ u16)
{
    int node = blockIdx.x * 8 + (threadIdx.x >> 5);
    int lane = threadIdx.x & 31;
    if (node >= N) return;
    int groups = 1 << (lc - 7);          // 1 (128 cols) or 2 (256 cols)
    float di = dinv[node];
    float di2 = di * di;
    float4 acc[2];
#pragma unroll
    for (int j = 0; j < 2; j++) {
        if (j < groups) {
            int col = j * 128 + lane * 4;
            float4 hv = *(const float4*)&h[((long long)node << lc) + col];
            float4 bv = *(const float4*)&bias[col];
            acc[j].x = bv.x + di2 * hv.x;
            acc[j].y = bv.y + di2 * hv.y;
            acc[j].z = bv.z + di2 * hv.z;
            acc[j].w = bv.w + di2 * hv.w;
        }
    }
    int s0 = start[node], s1 = start[node + 1];
    for (int base = s0; base < s1; base += 32) {
        int e = base + lane;
        int sidx = 0; float cf = 0.f;
        if (e < s1) { sidx = ssrc[e]; cf = ecoef[e]; }
        int cnt = s1 - base; if (cnt > 32) cnt = 32;
        int j = 0;
        for (; j + 4 <= cnt; j += 4) {
            int sa = __shfl_sync(0xffffffffu, sidx, j);
            int sb = __shfl_sync(0xffffffffu, sidx, j + 1);
            int sc = __shfl_sync(0xffffffffu, sidx, j + 2);
            int sdd = __shfl_sync(0xffffffffu, sidx, j + 3);
            float ca = __shfl_sync(0xffffffffu, cf, j);
            float cb = __shfl_sync(0xffffffffu, cf, j + 1);
            float cc = __shfl_sync(0xffffffffu, cf, j + 2);
            float cd = __shfl_sync(0xffffffffu, cf, j + 3);
            const float* ra = &h[(long long)sa << lc];
            const float* rb = &h[(long long)sb << lc];
            const float* rc = &h[(long long)sc << lc];
            const float* rd = &h[(long long)sdd << lc];
#pragma unroll
            for (int g = 0; g < 2; g++) {
                if (g < groups) {
                    int off = g * 128 + lane * 4;
                    float4 ha = *(const float4*)&ra[off];
                    float4 hb = *(const float4*)&rb[off];
                    float4 hc = *(const float4*)&rc[off];
                    float4 hd = *(const float4*)&rd[off];
                    acc[g].x += ca * ha.x + cb * hb.x + cc * hc.x + cd * hd.x;
                    acc[g].y += ca * ha.y + cb * hb.y + cc * hc.y + cd * hd.y;
                    acc[g].z += ca * ha.z + cb * hb.z + cc * hc.z + cd * hd.z;
                    acc[g].w += ca * ha.w + cb * hb.w + cc * hc.w + cd * hd.w;
                }
            }
        }
        for (; j < cnt; j++) {
            int s = __shfl_sync(0xffffffffu, sidx, j);
            float coef = __shfl_sync(0xffffffffu, cf, j);
            const float* hrow = &h[(long long)s << lc];
#pragma unroll
            for (int g = 0; g < 2; g++) {
                if (g < groups) {
                    float4 hv = *(const float4*)&hrow[g * 128 + lane * 4];
                    acc[g].x += coef * hv.x;
                    acc[g].y += coef * hv.y;
                    acc[g].z += coef * hv.z;
                    acc[g].w += coef * hv.w;
                }
            }
        }
    }
#pragma unroll
    for (int j = 0; j < 2; j++) {
        if (j < groups) {
            int col = j * 128 + lane * 4;
            *(float4*)&out[((long long)node << lc) + col] = acc[j];
            if (a2u) {
                float4 a4 = *(const float4*)&a2u[col];
                uint2 pk;
                pk.x = pack_h2(a4.x * acc[j].x, a4.y * acc[j].y);
                pk.y = pack_h2(a4.z * acc[j].z, a4.w * acc[j].w);
                // u16 row length = 2^(lc-1) u32; here only used with lc=8 -> node<<7
                *(uint2*)&u16[((long long)node << (lc - 1)) + j * 64 + lane * 2] = pk;
            }
        }
    }
}

// ---------------- EdgeConv: 128-edge FP16 tiles, prepacked u16/Wh, segmented max ----------------
__global__ __launch_bounds__(256) void edgeconv_tc(
    const unsigned* __restrict__ u16, const unsigned* __restrict__ b16,
    const unsigned* __restrict__ Whg,
    const int* __restrict__ ssrc, const int* __restrict__ sdstv,
    unsigned* __restrict__ Mout, int E, int lc2)   // lc2: log2(C/2) -> 6 or 7
{
    __shared__ unsigned sh[128 * 20 + 16 * 136];
    __shared__ int ss[128], sd[128];
    unsigned* qh = sh;                 // [edge][k2] stride 20
    unsigned* wh = sh + 128 * 20;      // [k2][n]  stride 136
    int tid = threadIdx.x;
    int e0 = blockIdx.x * 128;
    if (tid < 128) {
        int e = e0 + tid;
        if (e >= E) e = E - 1;
        ss[tid] = ssrc[e];
        sd[tid] = sdstv[e];
    }
    __syncthreads();
    int lane = tid & 31, warp = tid >> 5;
    int wm = warp & 3, wn = warp >> 2;
    int gid = lane >> 2, tig = lane & 3;
    int C2 = 1 << lc2;
    float acc[2][8][4] = {};
    for (int k20 = 0; k20 < C2; k20 += 16) {
#pragma unroll
        for (int i = 0; i < 2; i++) {
            int lin = tid + i * 256;          // 0..511
            int e = lin >> 2;                 // 0..127
            int q4 = (lin & 3) * 4;           // half2 offset
            int k2g = k20 + q4;
            uint4 us = *(const uint4*)&u16[(ss[e] << lc2) + k2g];
            uint4 ud = *(const uint4*)&u16[(sd[e] << lc2) + k2g];
            uint4 bb = *(const uint4*)&b16[k2g];
            uint4 r;
            r.x = h2_q(us.x, ud.x, bb.x);
            r.y = h2_q(us.y, ud.y, bb.y);
            r.z = h2_q(us.z, ud.z, bb.z);
            r.w = h2_q(us.w, ud.w, bb.w);
            *(uint4*)&qh[e * 20 + q4] = r;
        }
#pragma unroll
        for (int i = 0; i < 2; i++) {
            int lin = tid + i * 256;
            int k2 = lin >> 5;                // 0..15
            int n4 = (lin & 31) * 4;
            *(uint4*)&wh[k2 * 136 + n4] =
                *(const uint4*)&Whg[(k20 + k2) * 128 + n4];
        }
        __syncthreads();
#pragma unroll
        for (int s = 0; s < 2; s++) {
            unsigned bf[8][2];
#pragma unroll
            for (int nt = 0; nt < 8; nt++) {
                int bc = wn * 64 + nt * 8 + gid;
                bf[nt][0] = wh[(s * 8 + tig) * 136 + bc];
                bf[nt][1] = wh[(s * 8 + tig + 4) * 136 + bc];
            }
            int ac = s * 8 + tig;
#pragma unroll
            for (int mt = 0; mt < 2; mt++) {
                unsigned a[4];
                int ar = wm * 32 + mt * 16 + gid;
                a[0] = qh[ar * 20 + ac];
                a[1] = qh[(ar + 8) * 20 + ac];
                a[2] = qh[ar * 20 + ac + 4];
                a[3] = qh[(ar + 8) * 20 + ac + 4];
#pragma unroll
                for (int nt = 0; nt < 8; nt++)
                    mma_f16(acc[mt][nt], a, bf[nt]);
            }
        }
        __syncthreads();
    }
    // segmented max: 4 passes of 32 rows (dst-sorted); smem reuse
    float* sacc = (float*)sh;
#pragma unroll
    for (int pass = 0; pass < 4; pass++) {
        if (wm == pass) {
#pragma unroll
            for (int mt = 0; mt < 2; mt++) {
#pragma unroll
                for (int half = 0; half < 2; half++) {
                    int rl = mt * 16 + gid + half * 8;   // 0..31
#pragma unroll
                    for (int nt = 0; nt < 8; nt++) {
                        int col = wn * 64 + nt * 8 + tig * 2;
                        sacc[rl * 132 + col]     = acc[mt][nt][half * 2 + 0];
                        sacc[rl * 132 + col + 1] = acc[mt][nt][half * 2 + 1];
                    }
                }
            }
        }
        __syncthreads();
        {
            int col = tid & 127;
            int rh = tid >> 7;                  // 0..1
            int r0 = rh * 16, r1 = r0 + 16;
            int base = pass * 32;
            int cur = sd[base + r0];
            float m = sacc[r0 * 132 + col];
            for (int r = r0 + 1; r < r1; r++) {
                int d = sd[base + r];
                float v = sacc[r * 132 + col];
                if (d != cur) {
                    red_max_enc(&Mout[(long long)cur * 128 + col], m);
                    cur = d;
                    m = v;
                } else {
                    m = fmaxf(m, v);
                }
            }
            red_max_enc(&Mout[(long long)cur * 128 + col], m);
        }
        __syncthreads();
    }
}

// ---------------- EdgeConv combine (+ optional fused u16 emit for next layer); resets M ----------------
__global__ void combine_kernel(const float* __restrict__ P, unsigned* __restrict__ Mv,
                               const int* __restrict__ indeg, float* __restrict__ out, int N,
                               const float* __restrict__ a2u, unsigned* __restrict__ u16)
{
    int idx4 = blockIdx.x * 256 + threadIdx.x;
    if (idx4 >= N * 32) return;
    int i = idx4 >> 5;
    int colbase = (idx4 & 31) * 4;
    uint4 kv = *(uint4*)&Mv[idx4 * 4];
    float4 pv = *(const float4*)&P[idx4 * 4];
    float4 o = make_float4(0.f, 0.f, 0.f, 0.f);
    if (indeg[i] > 0) {
        unsigned u0 = (kv.x & 0x80000000u) ? (kv.x & 0x7fffffffu) : ~kv.x;
        unsigned u1 = (kv.y & 0x80000000u) ? (kv.y & 0x7fffffffu) : ~kv.y;
        unsigned u2 = (kv.z & 0x80000000u) ? (kv.z & 0x7fffffffu) : ~kv.z;
        unsigned u3 = (kv.w & 0x80000000u) ? (kv.w & 0x7fffffffu) : ~kv.w;
        o.x = pv.x + __uint_as_float(u0);
        o.y = pv.y + __uint_as_float(u1);
        o.z = pv.z + __uint_as_float(u2);
        o.w = pv.w + __uint_as_float(u3);
    }
    *(uint4*)&Mv[idx4 * 4] = make_uint4(0u, 0u, 0u, 0u);   // re-zero for next layer
    *(float4*)&out[idx4 * 4] = o;
    if (a2u) {
        float4 a4 = *(const float4*)&a2u[colbase];
        uint2 pk;
        pk.x = pack_h2(a4.x * o.x, a4.y * o.y);
        pk.y = pack_h2(a4.z * o.z, a4.w * o.w);
        *(uint2*)&u16[(i << 6) + (idx4 & 31) * 2] = pk;
    }
}

// ---------------- final FC ----------------
__global__ void fc_kernel(const float* __restrict__ h, const float* __restrict__ W,
                          const float* __restrict__ b, float* __restrict__ out, int N)
{
    int warp = (blockIdx.x * 256 + threadIdx.x) >> 5;
    int lane = threadIdx.x & 31;
    if (warp >= N) return;
    float s = 0.f;
#pragma unroll
    for (int j = lane; j < 128; j += 32) s += h[warp * 128 + j] * W[j];
#pragma unroll
    for (int o = 16; o; o >>= 1) s += __shfl_down_sync(0xffffffffu, s, o);
    if (lane == 0) out[warp] = s + b[0];
}

// ---------------- launch ----------------
extern "C" void kernel_launch(void* const* d_in, const int* in_sizes, int n_in,
                              void* d_out, int out_size)
{
    const float* x   = (const float*)d_in[0];
    const int*   ei  = (const int*)d_in[1];
    const float* Wm  = (const float*)d_in[2];
    const float* bm  = (const float*)d_in[3];
    const float* Wc  = (const float*)d_in[4];
    const float* bc  = (const float*)d_in[5];
    const float* Wg1 = (const float*)d_in[6];
    const float* bg1 = (const float*)d_in[7];
    const float* Wg2 = (const float*)d_in[8];
    const float* bg2 = (const float*)d_in[9];
    const float* Wg3 = (const float*)d_in[10];
    const float* bg3 = (const float*)d_in[11];
    const float* e1g = (const float*)d_in[12];
    const float* e1b = (const float*)d_in[13];
    const float* e1m = (const float*)d_in[14];
    const float* e1v = (const float*)d_in[15];
    const float* e1W = (const float*)d_in[16];
    const float* e2g = (const float*)d_in[17];
    const float* e2b = (const float*)d_in[18];
    const float* e2m = (const float*)d_in[19];
    const float* e2v = (const float*)d_in[20];
    const float* e2W = (const float*)d_in[21];
    const float* e3g = (const float*)d_in[22];
    const float* e3b = (const float*)d_in[23];
    const float* e3m = (const float*)d_in[24];
    const float* e3v = (const float*)d_in[25];
    const float* e3W = (const float*)d_in[26];
    const float* Wfc = (const float*)d_in[27];
    const float* bfc = (const float*)d_in[28];

    int N = in_sizes[0] / 512;
    int E = in_sizes[1] / 2;
    const int* src = ei;
    const int* dst = ei + E;

    float *x0, *hbuf, *gA, *gB, *P, *dinv, *bna, *bnb, *ecoef;
    unsigned *Mx, *u16p, *whp, *bhp;
    int *indeg, *startp, *cnt, *ssrc, *sdst;
    cudaGetSymbolAddress((void**)&x0,    d_x0);
    cudaGetSymbolAddress((void**)&hbuf,  d_hbuf);
    cudaGetSymbolAddress((void**)&gA,    d_gA);
    cudaGetSymbolAddress((void**)&gB,    d_gB);
    cudaGetSymbolAddress((void**)&P,     d_P);
    cudaGetSymbolAddress((void**)&Mx,    d_Mx);
    cudaGetSymbolAddress((void**)&u16p,  d_u16);
    cudaGetSymbolAddress((void**)&whp,   d_wh);
    cudaGetSymbolAddress((void**)&bhp,   d_bh);
    cudaGetSymbolAddress((void**)&dinv,  d_dinv);
    cudaGetSymbolAddress((void**)&indeg, d_indeg);
    cudaGetSymbolAddress((void**)&startp,d_start);
    cudaGetSymbolAddress((void**)&cnt,   d_cnt);
    cudaGetSymbolAddress((void**)&ssrc,  d_ssrc);
    cudaGetSymbolAddress((void**)&sdst,  d_sdst);
    cudaGetSymbolAddress((void**)&ecoef, d_ecoef);
    cudaGetSymbolAddress((void**)&bna,   d_bna);
    cudaGetSymbolAddress((void**)&bnb,   d_bnb);

    dim3 t256(256);
    int mb = (N + 63) / 64;

    // input projection (fused row-select), fp32
    proj_kernel<<<mb, t256>>>(x, Wm, bm, Wc, bc, x0, N);

    // degrees + CSR sort by dst (+ per-edge coef)
    zero_i32<<<(N + 255) / 256, t256>>>(indeg, N);
    count_indeg<<<(E + 255) / 256, t256>>>(dst, indeg, E);
    compute_dinv<<<(N + 255) / 256, t256>>>(indeg, dinv, N);
    scan_kernel<<<1, 1024>>>(indeg, startp, cnt, N);
    scatter_edges<<<(E + 255) / 256, t256>>>(src, dst, startp, cnt, dinv, ssrc, sdst, ecoef, E);

    // launch-invariant prep: Mx zero + packed fp16 weights/biases + BN coefs (all 3 edge layers)
    const_prep<<<(N * 128 + 255) / 256, t256>>>(
        e1W + 256 * 128, e2W + 128 * 128, e3W + 128 * 128,
        e1g, e1b, e1m, e1v, e2g, e2b, e2m, e2v, e3g, e3b, e3m, e3v,
        Mx, whp, bhp, bna, bnb, N);

    // GCN1: x0[N,64] @ Wg1[64,128] -> hbuf; gather -> gA
    gemm_tc<<<dim3(mb, 2), t256>>>(x0, Wg1, hbuf, N, 64, 128, nullptr, nullptr);
    gcn_gather<<<(N + 7) / 8, t256>>>(hbuf, ssrc, ecoef, startp, dinv, bg1, gA, N, 7,
                                      nullptr, nullptr);

    // GCN2
    gemm_tc<<<dim3(mb, 2), t256>>>(gA, Wg2, hbuf, N, 128, 128, nullptr, nullptr);
    gcn_gather<<<(N + 7) / 8, t256>>>(hbuf, ssrc, ecoef, startp, dinv, bg2, gB, N, 7,
                                      nullptr, nullptr);

    // GCN3 (out 256); fused u16 emit for EdgeConv1 (a2 = layer1 BN scale, cols 256..511)
    gemm_tc<<<dim3(mb, 4), t256>>>(gB, Wg3, hbuf, N, 128, 256, nullptr, nullptr);
    gcn_gather<<<(N + 7) / 8, t256>>>(hbuf, ssrc, ecoef, startp, dinv, bg3, gA, N, 8,
                                      bna + 256, u16p);

    // EdgeConv1: gA[N,256] -> gB[N,128]
    gemm_tc<<<dim3(mb, 2), t256>>>(gA, e1W, P, N, 256, 128, bna, bnb);
    edgeconv_tc<<<(E + 127) / 128, t256>>>(u16p, bhp, whp, ssrc, sdst, Mx, E, 7);
    combine_kernel<<<(N * 32 + 255) / 256, t256>>>(P, Mx, indeg, gB, N,
                                                   bna + 640, u16p);  // u16 for EdgeConv2

    // EdgeConv2: gB[N,128] -> gA[N,128]
    gemm_tc<<<dim3(mb, 2), t256>>>(gB, e2W, P, N, 128, 128, bna + 512, bnb + 512);
    edgeconv_tc<<<(E + 127) / 128, t256>>>(u16p, bhp + 128, whp + 16384, ssrc, sdst, Mx, E, 6);
    combine_kernel<<<(N * 32 + 255) / 256, t256>>>(P, Mx, indeg, gA, N,
                                                   bna + 896, u16p);  // u16 for EdgeConv3

    // EdgeConv3: gA[N,128] -> gB[N,128]
    gemm_tc<<<dim3(mb, 2), t256>>>(gA, e3W, P, N, 128, 128, bna + 768, bnb + 768);
    edgeconv_tc<<<(E + 127) / 128, t256>>>(u16p, bhp + 192, whp + 24576, ssrc, sdst, Mx, E, 6);
    combine_kernel<<<(N * 32 + 255) / 256, t256>>>(P, Mx, indeg, gB, N, nullptr, nullptr);

    // final FC -> d_out [N,1]
    fc_kernel<<<(N + 7) / 8, t256>>>(gB, Wfc, bfc, (float*)d_out, N);
}

// round 11
// speedup vs baseline: 3.6641x; 1.1100x over previous
#include <cuda_runtime.h>
#include <cuda_fp16.h>
#include <math.h>

#define NCAP 20000
#define ECAP 320000

// ---------------- static scratch (no allocation allowed) ----------------
static __device__ float    d_x0  [NCAP * 64];
static __device__ unsigned d_h16 [NCAP * 128];   // fp16-packed GCN linear outputs
static __device__ float    d_gA  [NCAP * 256];
static __device__ float    d_gB  [NCAP * 256];
static __device__ float    d_P   [NCAP * 128];
static __device__ unsigned d_Mx  [NCAP * 128];
static __device__ unsigned d_u16 [NCAP * 128];   // per-layer fp16-packed scaled node rows
static __device__ unsigned d_wh  [32768];        // fp16-interleaved weights, ALL 3 edge layers
static __device__ unsigned d_bh  [256];          // fp16-packed BN offsets, ALL 3 edge layers
static __device__ float    d_dinv[NCAP];
static __device__ int      d_indeg[NCAP];
static __device__ int      d_start[NCAP + 1];
static __device__ int      d_cnt  [NCAP];
static __device__ int      d_ssrc [ECAP];
static __device__ int      d_sdst [ECAP];
static __device__ float    d_ecoef[ECAP];
static __device__ float    d_bna [1024];         // BN scale, layers at 0 / 512 / 768
static __device__ float    d_bnb [1024];         // BN offset

// ---------------- helpers ----------------
__device__ __forceinline__ unsigned f2tf32(float x) {
    unsigned y;
    asm("cvt.rna.tf32.f32 %0, %1;" : "=r"(y) : "f"(x));
    return y;
}

__device__ __forceinline__ unsigned pack_h2(float lo, float hi) {
    __half2 h = __floats2half2_rn(lo, hi);
    return *(unsigned*)&h;
}

__device__ __forceinline__ unsigned h2_q(unsigned us, unsigned ud, unsigned bb) {
    __half2 z = __floats2half2_rn(0.f, 0.f);
    __half2 r = __hmax2(__hadd2(__hsub2(*(__half2*)&us, *(__half2*)&ud), *(__half2*)&bb), z);
    return *(unsigned*)&r;
}

__device__ __forceinline__ void mma_tf32(float* d, const unsigned* a, const unsigned* b) {
    asm volatile(
        "mma.sync.aligned.m16n8k8.row.col.f32.tf32.tf32.f32 "
        "{%0,%1,%2,%3}, {%4,%5,%6,%7}, {%8,%9}, {%0,%1,%2,%3};"
        : "+f"(d[0]), "+f"(d[1]), "+f"(d[2]), "+f"(d[3])
        : "r"(a[0]), "r"(a[1]), "r"(a[2]), "r"(a[3]), "r"(b[0]), "r"(b[1]));
}

__device__ __forceinline__ void mma_f16(float* d, const unsigned* a, const unsigned* b) {
    asm volatile(
        "mma.sync.aligned.m16n8k16.row.col.f32.f16.f16.f32 "
        "{%0,%1,%2,%3}, {%4,%5,%6,%7}, {%8,%9}, {%0,%1,%2,%3};"
        : "+f"(d[0]), "+f"(d[1]), "+f"(d[2]), "+f"(d[3])
        : "r"(a[0]), "r"(a[1]), "r"(a[2]), "r"(a[3]), "r"(b[0]), "r"(b[1]));
}

__device__ __forceinline__ void red_max_enc(unsigned* p, float v) {
    unsigned u = __float_as_uint(v);
    unsigned key = (u & 0x80000000u) ? ~u : (u | 0x80000000u);
    asm volatile("red.global.max.u32 [%0], %1;" :: "l"(p), "r"(key) : "memory");
}

// ---------------- small kernels ----------------
__global__ void zero_i32(int* p, int n) {
    int i = blockIdx.x * 256 + threadIdx.x;
    if (i < n) p[i] = 0;
}
__global__ void count_indeg(const int* __restrict__ dstv, int* __restrict__ indeg, int E) {
    int e = blockIdx.x * 256 + threadIdx.x;
    if (e < E) atomicAdd(&indeg[dstv[e]], 1);
}

// ---------------- exclusive scan over indeg -> start; also zeros cnt, computes dinv ----------------
__global__ __launch_bounds__(1024) void scan_kernel(const int* __restrict__ indeg,
                                                    int* __restrict__ start,
                                                    int* __restrict__ cnt,
                                                    float* __restrict__ dinv, int N) {
    __shared__ int wsum[32];
    int t = threadIdx.x;
    int chunk = (N + 1023) / 1024;
    int lo = t * chunk;
    int hi = lo + chunk; if (hi > N) hi = N; if (lo > N) lo = N;
    int s = 0;
    for (int i = lo; i < hi; i++) s += indeg[i];
    int lane = t & 31, w = t >> 5;
    int v = s;
#pragma unroll
    for (int o = 1; o < 32; o <<= 1) {
        int u = __shfl_up_sync(0xffffffffu, v, o);
        if (lane >= o) v += u;
    }
    if (lane == 31) wsum[w] = v;
    __syncthreads();
    if (w == 0) {
        int x = wsum[lane];
#pragma unroll
        for (int o = 1; o < 32; o <<= 1) {
            int u = __shfl_up_sync(0xffffffffu, x, o);
            if (lane >= o) x += u;
        }
        wsum[lane] = x;
    }
    __syncthreads();
    int excl = (v - s) + (w > 0 ? wsum[w - 1] : 0);
    int run = excl;
    for (int i = lo; i < hi; i++) {
        start[i] = run;
        run += indeg[i];
        cnt[i] = 0;
        dinv[i] = rsqrtf((float)indeg[i] + 1.0f);
    }
    if (t == 1023) start[N] = run;
}

// ---------------- prep_all: edge scatter + Mx zero + packed fp16 weights/biases + BN coefs ----------------
__global__ void prep_all(
    const int* __restrict__ src, const int* __restrict__ dstv,
    const int* __restrict__ start, int* __restrict__ cnt, const float* __restrict__ dinv,
    int* __restrict__ ssrc, int* __restrict__ sdst, float* __restrict__ ecoef, int E,
    const float* __restrict__ w1, const float* __restrict__ w2, const float* __restrict__ w3,
    const float* __restrict__ g1, const float* __restrict__ b1,
    const float* __restrict__ m1, const float* __restrict__ v1,
    const float* __restrict__ g2, const float* __restrict__ b2,
    const float* __restrict__ m2, const float* __restrict__ v2,
    const float* __restrict__ g3, const float* __restrict__ b3,
    const float* __restrict__ m3, const float* __restrict__ v3,
    unsigned* __restrict__ Mx, unsigned* __restrict__ wh, unsigned* __restrict__ bh,
    float* __restrict__ bna, float* __restrict__ bnb, int N)
{
    int idx = blockIdx.x * 256 + threadIdx.x;
    if (idx < E) {
        int s = src[idx], d = dstv[idx];
        int p = start[d] + atomicAdd(&cnt[d], 1);
        ssrc[p] = s;
        sdst[p] = d;
        ecoef[p] = dinv[s] * dinv[d];
    }
    if (idx < N * 128) Mx[idx] = 0u;
    if (idx < 32768) {
        const float* W; int k2n;
        if (idx < 16384)      { W = w1; k2n = idx; }
        else if (idx < 24576) { W = w2; k2n = idx - 16384; }
        else                  { W = w3; k2n = idx - 24576; }
        int k2 = k2n >> 7, n = k2n & 127;
        wh[idx] = pack_h2(W[(2 * k2) * 128 + n], W[(2 * k2 + 1) * 128 + n]);
    }
    if (idx < 1024) {
        const float *g, *be, *me, *va; int i;
        if (idx < 512)      { g = g1; be = b1; me = m1; va = v1; i = idx; }
        else if (idx < 768) { g = g2; be = b2; me = m2; va = v2; i = idx - 512; }
        else                { g = g3; be = b3; me = m3; va = v3; i = idx - 768; }
        float a = g[i] * rsqrtf(va[i] + 1e-5f);
        bna[idx] = a;
        bnb[idx] = be[i] - me[i] * a;
    }
    if (idx < 256) {
        const float *g, *be, *me, *va; int c;
        if (idx < 128)      { g = g1; be = b1; me = m1; va = v1; c = 256 + 2 * idx; }
        else if (idx < 192) { g = g2; be = b2; me = m2; va = v2; c = 128 + 2 * (idx - 128); }
        else                { g = g3; be = b3; me = m3; va = v3; c = 128 + 2 * (idx - 192); }
        float a0 = g[c] * rsqrtf(va[c] + 1e-5f);
        float a1 = g[c + 1] * rsqrtf(va[c + 1] + 1e-5f);
        bh[idx] = pack_h2(be[c] - me[c] * a0, be[c + 1] - me[c + 1] * a1);
    }
}

// ---------------- TF32 tensor-core node GEMM ----------------
// C[f32, optional] / outh[fp16-packed, optional] = f(A) @ B (+ bias), rows strided by rmul.
__global__ __launch_bounds__(256) void gemm_tc(
    const float* __restrict__ A, const float* __restrict__ B,
    float* __restrict__ C, unsigned* __restrict__ outh,
    int M, int K, int Ncols, int rmul,
    const float* __restrict__ ta, const float* __restrict__ tb,
    const float* __restrict__ bias)
{
    __shared__ unsigned As[64 * 36];
    __shared__ unsigned Bs[32 * 72];
    int tid = threadIdx.x;
    int lane = tid & 31, warp = tid >> 5;
    int wm = warp & 3, wn = warp >> 2;
    int gid = lane >> 2, tig = lane & 3;
    int row0 = blockIdx.x * 64;
    int col0 = blockIdx.y * 64;
    float acc[4][4] = {};
    for (int k0 = 0; k0 < K; k0 += 32) {
#pragma unroll
        for (int i = 0; i < 2; i++) {
            int lin = tid + i * 256;          // 0..511
            int r = lin >> 3;                 // 0..63
            int k4 = (lin & 7) * 4;
            int gr = row0 + r;
            float4 v = make_float4(0.f, 0.f, 0.f, 0.f);
            if (gr < M) {
                v = *(const float4*)&A[(long long)gr * rmul * K + k0 + k4];
                if (ta) {
                    float4 a4 = *(const float4*)&ta[k0 + k4];
                    float4 b4 = *(const float4*)&tb[k0 + k4];
                    v.x = fmaxf(a4.x * v.x + b4.x, 0.f);
                    v.y = fmaxf(a4.y * v.y + b4.y, 0.f);
                    v.z = fmaxf(a4.z * v.z + b4.z, 0.f);
                    v.w = fmaxf(a4.w * v.w + b4.w, 0.f);
                }
            }
            *(uint4*)&As[r * 36 + k4] =
                make_uint4(f2tf32(v.x), f2tf32(v.y), f2tf32(v.z), f2tf32(v.w));
        }
#pragma unroll
        for (int i = 0; i < 2; i++) {
            int lin = tid + i * 256;
            int k = lin >> 4;                 // 0..31
            int n4 = (lin & 15) * 4;
            float4 w4 = *(const float4*)&B[(long long)(k0 + k) * Ncols + col0 + n4];
            *(uint4*)&Bs[k * 72 + n4] =
                make_uint4(f2tf32(w4.x), f2tf32(w4.y), f2tf32(w4.z), f2tf32(w4.w));
        }
        __syncthreads();
#pragma unroll
        for (int s = 0; s < 4; s++) {
            unsigned a[4];
            int ar = wm * 16 + gid;
            int ac = s * 8 + tig;
            a[0] = As[ar * 36 + ac];
            a[1] = As[(ar + 8) * 36 + ac];
            a[2] = As[ar * 36 + ac + 4];
            a[3] = As[(ar + 8) * 36 + ac + 4];
#pragma unroll
            for (int nt = 0; nt < 4; nt++) {
                unsigned b[2];
                int bc = wn * 32 + nt * 8 + gid;
                b[0] = Bs[(s * 8 + tig) * 72 + bc];
                b[1] = Bs[(s * 8 + tig + 4) * 72 + bc];
                mma_tf32(acc[nt], a, b);
            }
        }
        __syncthreads();
    }
#pragma unroll
    for (int half = 0; half < 2; half++) {
        int gr = row0 + wm * 16 + gid + half * 8;
        if (gr < M) {
            long long prow = (long long)gr * rmul;
#pragma unroll
            for (int nt = 0; nt < 4; nt++) {
                int col = col0 + wn * 32 + nt * 8 + tig * 2;
                float v0 = acc[nt][half * 2 + 0];
                float v1 = acc[nt][half * 2 + 1];
                if (bias) { v0 += bias[col]; v1 += bias[col + 1]; }
                if (C) {
                    C[prow * Ncols + col]     = v0;
                    C[prow * Ncols + col + 1] = v1;
                }
                if (outh)
                    outh[prow * (Ncols >> 1) + (col >> 1)] = pack_h2(v0, v1);
            }
        }
    }
}

// ---------------- GCN aggregation: CSR gather over fp16 rows, 4-way unroll; optional u16 emit ----------------
// out[i] = bias + dinv[i]^2 * h[i] + sum_e ecoef[e] * h[src[e]]   (h stored fp16-packed)
__global__ __launch_bounds__(256) void gcn_gather(
    const unsigned* __restrict__ h16, const int* __restrict__ ssrc,
    const float* __restrict__ ecoef, const int* __restrict__ start,
    const float* __restrict__ dinv, const float* __restrict__ bias,
    float* __restrict__ out, int N, int lc,
    const float* __restrict__ a2u, unsigned* __restrict__ u16)
{
    int node = blockIdx.x * 8 + (threadIdx.x >> 5);
    int lane = threadIdx.x & 31;
    if (node >= N) return;
    int groups = 1 << (lc - 7);          // 1 (128 cols) or 2 (256 cols)
    int rowlen = 1 << (lc - 1);          // u32 per row
    float di = dinv[node];
    float di2 = di * di;
    float4 acc[2];
    const unsigned* self = &h16[(long long)node * rowlen];
#pragma unroll
    for (int j = 0; j < 2; j++) {
        if (j < groups) {
            uint2 hv = *(const uint2*)&self[j * 64 + lane * 2];
            float2 f0 = __half22float2(*(__half2*)&hv.x);
            float2 f1 = __half22float2(*(__half2*)&hv.y);
            float4 bv = *(const float4*)&bias[j * 128 + lane * 4];
            acc[j].x = bv.x + di2 * f0.x;
            acc[j].y = bv.y + di2 * f0.y;
            acc[j].z = bv.z + di2 * f1.x;
            acc[j].w = bv.w + di2 * f1.y;
        }
    }
    int s0 = start[node], s1 = start[node + 1];
    for (int base = s0; base < s1; base += 32) {
        int e = base + lane;
        int sidx = 0; float cf = 0.f;
        if (e < s1) { sidx = ssrc[e]; cf = ecoef[e]; }
        int cnt = s1 - base; if (cnt > 32) cnt = 32;
        int j = 0;
        for (; j + 4 <= cnt; j += 4) {
            int sa = __shfl_sync(0xffffffffu, sidx, j);
            int sb = __shfl_sync(0xffffffffu, sidx, j + 1);
            int sc = __shfl_sync(0xffffffffu, sidx, j + 2);
            int sdd = __shfl_sync(0xffffffffu, sidx, j + 3);
            float ca = __shfl_sync(0xffffffffu, cf, j);
            float cb = __shfl_sync(0xffffffffu, cf, j + 1);
            float cc = __shfl_sync(0xffffffffu, cf, j + 2);
            float cd = __shfl_sync(0xffffffffu, cf, j + 3);
            const unsigned* ra = &h16[(long long)sa * rowlen];
            const unsigned* rb = &h16[(long long)sb * rowlen];
            const unsigned* rc = &h16[(long long)sc * rowlen];
            const unsigned* rd = &h16[(long long)sdd * rowlen];
#pragma unroll
            for (int g = 0; g < 2; g++) {
                if (g < groups) {
                    int off = g * 64 + lane * 2;
                    uint2 ha = *(const uint2*)&ra[off];
                    uint2 hb = *(const uint2*)&rb[off];
                    uint2 hc = *(const uint2*)&rc[off];
                    uint2 hd = *(const uint2*)&rd[off];
                    float2 a0 = __half22float2(*(__half2*)&ha.x);
                    float2 a1 = __half22float2(*(__half2*)&ha.y);
                    float2 b0 = __half22float2(*(__half2*)&hb.x);
                    float2 b1 = __half22float2(*(__half2*)&hb.y);
                    float2 c0 = __half22float2(*(__half2*)&hc.x);
                    float2 c1 = __half22float2(*(__half2*)&hc.y);
                    float2 d0 = __half22float2(*(__half2*)&hd.x);
                    float2 d1 = __half22float2(*(__half2*)&hd.y);
                    acc[g].x += ca * a0.x + cb * b0.x + cc * c0.x + cd * d0.x;
                    acc[g].y += ca * a0.y + cb * b0.y + cc * c0.y + cd * d0.y;
                    acc[g].z += ca * a1.x + cb * b1.x + cc * c1.x + cd * d1.x;
                    acc[g].w += ca * a1.y + cb * b1.y + cc * c1.y + cd * d1.y;
                }
            }
        }
        for (; j < cnt; j++) {
            int s = __shfl_sync(0xffffffffu, sidx, j);
            float coef = __shfl_sync(0xffffffffu, cf, j);
            const unsigned* hr = &h16[(long long)s * rowlen];
#pragma unroll
            for (int g = 0; g < 2; g++) {
                if (g < groups) {
                    uint2 hv = *(const uint2*)&hr[g * 64 + lane * 2];
                    float2 f0 = __half22float2(*(__half2*)&hv.x);
                    float2 f1 = __half22float2(*(__half2*)&hv.y);
                    acc[g].x += coef * f0.x;
                    acc[g].y += coef * f0.y;
                    acc[g].z += coef * f1.x;
                    acc[g].w += coef * f1.y;
                }
            }
        }
    }
#pragma unroll
    for (int j = 0; j < 2; j++) {
        if (j < groups) {
            int col = j * 128 + lane * 4;
            *(float4*)&out[((long long)node << lc) + col] = acc[j];
            if (a2u) {
                float4 a4 = *(const float4*)&a2u[col];
                uint2 pk;
                pk.x = pack_h2(a4.x * acc[j].x, a4.y * acc[j].y);
                pk.y = pack_h2(a4.z * acc[j].z, a4.w * acc[j].w);
                *(uint2*)&u16[((long long)node << (lc - 1)) + j * 64 + lane * 2] = pk;
            }
        }
    }
}

// ---------------- EdgeConv: 128-edge FP16 tiles, prepacked u16/Wh, segmented max ----------------
__global__ __launch_bounds__(256) void edgeconv_tc(
    const unsigned* __restrict__ u16, const unsigned* __restrict__ b16,
    const unsigned* __restrict__ Whg,
    const int* __restrict__ ssrc, const int* __restrict__ sdstv,
    unsigned* __restrict__ Mout, int E, int lc2)   // lc2: log2(C/2) -> 6 or 7
{
    __shared__ unsigned sh[128 * 20 + 16 * 136];
    __shared__ int ss[128], sd[128];
    unsigned* qh = sh;                 // [edge][k2] stride 20
    unsigned* wh = sh + 128 * 20;      // [k2][n]  stride 136
    int tid = threadIdx.x;
    int e0 = blockIdx.x * 128;
    if (tid < 128) {
        int e = e0 + tid;
        if (e >= E) e = E - 1;
        ss[tid] = ssrc[e];
        sd[tid] = sdstv[e];
    }
    __syncthreads();
    int lane = tid & 31, warp = tid >> 5;
    int wm = warp & 3, wn = warp >> 2;
    int gid = lane >> 2, tig = lane & 3;
    int C2 = 1 << lc2;
    float acc[2][8][4] = {};
    for (int k20 = 0; k20 < C2; k20 += 16) {
#pragma unroll
        for (int i = 0; i < 2; i++) {
            int lin = tid + i * 256;          // 0..511
            int e = lin >> 2;                 // 0..127
            int q4 = (lin & 3) * 4;           // half2 offset
            int k2g = k20 + q4;
            uint4 us = *(const uint4*)&u16[(ss[e] << lc2) + k2g];
            uint4 ud = *(const uint4*)&u16[(sd[e] << lc2) + k2g];
            uint4 bb = *(const uint4*)&b16[k2g];
            uint4 r;
            r.x = h2_q(us.x, ud.x, bb.x);
            r.y = h2_q(us.y, ud.y, bb.y);
            r.z = h2_q(us.z, ud.z, bb.z);
            r.w = h2_q(us.w, ud.w, bb.w);
            *(uint4*)&qh[e * 20 + q4] = r;
        }
#pragma unroll
        for (int i = 0; i < 2; i++) {
            int lin = tid + i * 256;
            int k2 = lin >> 5;                // 0..15
            int n4 = (lin & 31) * 4;
            *(uint4*)&wh[k2 * 136 + n4] =
                *(const uint4*)&Whg[(k20 + k2) * 128 + n4];
        }
        __syncthreads();
#pragma unroll
        for (int s = 0; s < 2; s++) {
            unsigned bf[8][2];
#pragma unroll
            for (int nt = 0; nt < 8; nt++) {
                int bc = wn * 64 + nt * 8 + gid;
                bf[nt][0] = wh[(s * 8 + tig) * 136 + bc];
                bf[nt][1] = wh[(s * 8 + tig + 4) * 136 + bc];
            }
            int ac = s * 8 + tig;
#pragma unroll
            for (int mt = 0; mt < 2; mt++) {
                unsigned a[4];
                int ar = wm * 32 + mt * 16 + gid;
                a[0] = qh[ar * 20 + ac];
                a[1] = qh[(ar + 8) * 20 + ac];
                a[2] = qh[ar * 20 + ac + 4];
                a[3] = qh[(ar + 8) * 20 + ac + 4];
#pragma unroll
                for (int nt = 0; nt < 8; nt++)
                    mma_f16(acc[mt][nt], a, bf[nt]);
            }
        }
        __syncthreads();
    }
    // segmented max: 4 passes of 32 rows (dst-sorted); smem reuse
    float* sacc = (float*)sh;
#pragma unroll
    for (int pass = 0; pass < 4; pass++) {
        if (wm == pass) {
#pragma unroll
            for (int mt = 0; mt < 2; mt++) {
#pragma unroll
                for (int half = 0; half < 2; half++) {
                    int rl = mt * 16 + gid + half * 8;   // 0..31
#pragma unroll
                    for (int nt = 0; nt < 8; nt++) {
                        int col = wn * 64 + nt * 8 + tig * 2;
                        sacc[rl * 132 + col]     = acc[mt][nt][half * 2 + 0];
                        sacc[rl * 132 + col + 1] = acc[mt][nt][half * 2 + 1];
                    }
                }
            }
        }
        __syncthreads();
        {
            int col = tid & 127;
            int rh = tid >> 7;                  // 0..1
            int r0 = rh * 16, r1 = r0 + 16;
            int base = pass * 32;
            int cur = sd[base + r0];
            float m = sacc[r0 * 132 + col];
            for (int r = r0 + 1; r < r1; r++) {
                int d = sd[base + r];
                float v = sacc[r * 132 + col];
                if (d != cur) {
                    red_max_enc(&Mout[(long long)cur * 128 + col], m);
                    cur = d;
                    m = v;
                } else {
                    m = fmaxf(m, v);
                }
            }
            red_max_enc(&Mout[(long long)cur * 128 + col], m);
        }
        __syncthreads();
    }
}

// ---------------- EdgeConv combine (+ optional fused u16 emit for next layer); resets M ----------------
__global__ void combine_kernel(const float* __restrict__ P, unsigned* __restrict__ Mv,
                               const int* __restrict__ indeg, float* __restrict__ out, int N,
                               const float* __restrict__ a2u, unsigned* __restrict__ u16)
{
    int idx4 = blockIdx.x * 256 + threadIdx.x;
    if (idx4 >= N * 32) return;
    int i = idx4 >> 5;
    int colbase = (idx4 & 31) * 4;
    uint4 kv = *(uint4*)&Mv[idx4 * 4];
    float4 pv = *(const float4*)&P[idx4 * 4];
    float4 o = make_float4(0.f, 0.f, 0.f, 0.f);
    if (indeg[i] > 0) {
        unsigned u0 = (kv.x & 0x80000000u) ? (kv.x & 0x7fffffffu) : ~kv.x;
        unsigned u1 = (kv.y & 0x80000000u) ? (kv.y & 0x7fffffffu) : ~kv.y;
        unsigned u2 = (kv.z & 0x80000000u) ? (kv.z & 0x7fffffffu) : ~kv.z;
        unsigned u3 = (kv.w & 0x80000000u) ? (kv.w & 0x7fffffffu) : ~kv.w;
        o.x = pv.x + __uint_as_float(u0);
        o.y = pv.y + __uint_as_float(u1);
        o.z = pv.z + __uint_as_float(u2);
        o.w = pv.w + __uint_as_float(u3);
    }
    *(uint4*)&Mv[idx4 * 4] = make_uint4(0u, 0u, 0u, 0u);   // re-zero for next layer
    *(float4*)&out[idx4 * 4] = o;
    if (a2u) {
        float4 a4 = *(const float4*)&a2u[colbase];
        uint2 pk;
        pk.x = pack_h2(a4.x * o.x, a4.y * o.y);
        pk.y = pack_h2(a4.z * o.z, a4.w * o.w);
        *(uint2*)&u16[(i << 6) + (idx4 & 31) * 2] = pk;
    }
}

// ---------------- final: combine last EdgeConv + FC in one pass (warp per node) ----------------
__global__ void combine_fc(const float* __restrict__ P, const unsigned* __restrict__ Mv,
                           const int* __restrict__ indeg,
                           const float* __restrict__ W, const float* __restrict__ b,
                           float* __restrict__ out, int N)
{
    int node = blockIdx.x * 8 + (threadIdx.x >> 5);
    int lane = threadIdx.x & 31;
    if (node >= N) return;
    uint4 kv = *(const uint4*)&Mv[node * 128 + lane * 4];
    float4 pv = *(const float4*)&P[node * 128 + lane * 4];
    float4 o = make_float4(0.f, 0.f, 0.f, 0.f);
    if (indeg[node] > 0) {
        unsigned u0 = (kv.x & 0x80000000u) ? (kv.x & 0x7fffffffu) : ~kv.x;
        unsigned u1 = (kv.y & 0x80000000u) ? (kv.y & 0x7fffffffu) : ~kv.y;
        unsigned u2 = (kv.z & 0x80000000u) ? (kv.z & 0x7fffffffu) : ~kv.z;
        unsigned u3 = (kv.w & 0x80000000u) ? (kv.w & 0x7fffffffu) : ~kv.w;
        o.x = pv.x + __uint_as_float(u0);
        o.y = pv.y + __uint_as_float(u1);
        o.z = pv.z + __uint_as_float(u2);
        o.w = pv.w + __uint_as_float(u3);
    }
    float4 w = *(const float4*)&W[lane * 4];
    float s = o.x * w.x + o.y * w.y + o.z * w.z + o.w * w.w;
#pragma unroll
    for (int off = 16; off; off >>= 1) s += __shfl_down_sync(0xffffffffu, s, off);
    if (lane == 0) out[node] = s + b[0];
}

// ---------------- launch ----------------
extern "C" void kernel_launch(void* const* d_in, const int* in_sizes, int n_in,
                              void* d_out, int out_size)
{
    const float* x   = (const float*)d_in[0];
    const int*   ei  = (const int*)d_in[1];
    const float* Wm  = (const float*)d_in[2];
    const float* bm  = (const float*)d_in[3];
    const float* Wc  = (const float*)d_in[4];
    const float* bc  = (const float*)d_in[5];
    const float* Wg1 = (const float*)d_in[6];
    const float* bg1 = (const float*)d_in[7];
    const float* Wg2 = (const float*)d_in[8];
    const float* bg2 = (const float*)d_in[9];
    const float* Wg3 = (const float*)d_in[10];
    const float* bg3 = (const float*)d_in[11];
    const float* e1g = (const float*)d_in[12];
    const float* e1b = (const float*)d_in[13];
    const float* e1m = (const float*)d_in[14];
    const float* e1v = (const float*)d_in[15];
    const float* e1W = (const float*)d_in[16];
    const float* e2g = (const float*)d_in[17];
    const float* e2b = (const float*)d_in[18];
    const float* e2m = (const float*)d_in[19];
    const float* e2v = (const float*)d_in[20];
    const float* e2W = (const float*)d_in[21];
    const float* e3g = (const float*)d_in[22];
    const float* e3b = (const float*)d_in[23];
    const float* e3m = (const float*)d_in[24];
    const float* e3v = (const float*)d_in[25];
    const float* e3W = (const float*)d_in[26];
    const float* Wfc = (const float*)d_in[27];
    const float* bfc = (const float*)d_in[28];

    int N = in_sizes[0] / 512;
    int E = in_sizes[1] / 2;
    const int* src = ei;
    const int* dst = ei + E;

    float *x0, *gA, *gB, *P, *dinv, *bna, *bnb, *ecoef;
    unsigned *Mx, *u16p, *whp, *bhp, *h16;
    int *indeg, *startp, *cnt, *ssrc, *sdst;
    cudaGetSymbolAddress((void**)&x0,    d_x0);
    cudaGetSymbolAddress((void**)&h16,   d_h16);
    cudaGetSymbolAddress((void**)&gA,    d_gA);
    cudaGetSymbolAddress((void**)&gB,    d_gB);
    cudaGetSymbolAddress((void**)&P,     d_P);
    cudaGetSymbolAddress((void**)&Mx,    d_Mx);
    cudaGetSymbolAddress((void**)&u16p,  d_u16);
    cudaGetSymbolAddress((void**)&whp,   d_wh);
    cudaGetSymbolAddress((void**)&bhp,   d_bh);
    cudaGetSymbolAddress((void**)&dinv,  d_dinv);
    cudaGetSymbolAddress((void**)&indeg, d_indeg);
    cudaGetSymbolAddress((void**)&startp,d_start);
    cudaGetSymbolAddress((void**)&cnt,   d_cnt);
    cudaGetSymbolAddress((void**)&ssrc,  d_ssrc);
    cudaGetSymbolAddress((void**)&sdst,  d_sdst);
    cudaGetSymbolAddress((void**)&ecoef, d_ecoef);
    cudaGetSymbolAddress((void**)&bna,   d_bna);
    cudaGetSymbolAddress((void**)&bnb,   d_bnb);

    dim3 t256(256);
    int mb = (N + 63) / 64;
    int M4 = (N + 3) / 4;
    int mb4 = (M4 + 63) / 64;

    // input projection via TF32 tensor GEMMs: all rows x@Wc+bc, then rows %4==0 overwritten with x@Wm+bm
    gemm_tc<<<dim3(mb, 1), t256>>>(x, Wc, x0, nullptr, N, 512, 64, 1, nullptr, nullptr, bc);
    gemm_tc<<<dim3(mb4, 1), t256>>>(x, Wm, x0, nullptr, M4, 512, 64, 4, nullptr, nullptr, bm);

    // degrees + CSR sort by dst + launch-invariant prep
    zero_i32<<<(N + 255) / 256, t256>>>(indeg, N);
    count_indeg<<<(E + 255) / 256, t256>>>(dst, indeg, E);
    scan_kernel<<<1, 1024>>>(indeg, startp, cnt, dinv, N);
    prep_all<<<(N * 128 + 255) / 256, t256>>>(
        src, dst, startp, cnt, dinv, ssrc, sdst, ecoef, E,
        e1W + 256 * 128, e2W + 128 * 128, e3W + 128 * 128,
        e1g, e1b, e1m, e1v, e2g, e2b, e2m, e2v, e3g, e3b, e3m, e3v,
        Mx, whp, bhp, bna, bnb, N);

    // GCN1: x0[N,64] @ Wg1[64,128] -> h16; gather -> gA
    gemm_tc<<<dim3(mb, 2), t256>>>(x0, Wg1, nullptr, h16, N, 64, 128, 1, nullptr, nullptr, nullptr);
    gcn_gather<<<(N + 7) / 8, t256>>>(h16, ssrc, ecoef, startp, dinv, bg1, gA, N, 7,
                                      nullptr, nullptr);

    // GCN2
    gemm_tc<<<dim3(mb, 2), t256>>>(gA, Wg2, nullptr, h16, N, 128, 128, 1, nullptr, nullptr, nullptr);
    gcn_gather<<<(N + 7) / 8, t256>>>(h16, ssrc, ecoef, startp, dinv, bg2, gB, N, 7,
                                      nullptr, nullptr);

    // GCN3 (out 256); fused u16 emit for EdgeConv1 (a2 = layer1 BN scale, cols 256..511)
    gemm_tc<<<dim3(mb, 4), t256>>>(gB, Wg3, nullptr, h16, N, 128, 256, 1, nullptr, nullptr, nullptr);
    gcn_gather<<<(N + 7) / 8, t256>>>(h16, ssrc, ecoef, startp, dinv, bg3, gA, N, 8,
                                      bna + 256, u16p);

    // EdgeConv1: gA[N,256] -> gB[N,128]
    gemm_tc<<<dim3(mb, 2), t256>>>(gA, e1W, P, nullptr, N, 256, 128, 1, bna, bnb, nullptr);
    edgeconv_tc<<<(E + 127) / 128, t256>>>(u16p, bhp, whp, ssrc, sdst, Mx, E, 7);
    combine_kernel<<<(N * 32 + 255) / 256, t256>>>(P, Mx, indeg, gB, N,
                                                   bna + 640, u16p);  // u16 for EdgeConv2

    // EdgeConv2: gB[N,128] -> gA[N,128]
    gemm_tc<<<dim3(mb, 2), t256>>>(gB, e2W, P, nullptr, N, 128, 128, 1, bna + 512, bnb + 512, nullptr);
    edgeconv_tc<<<(E + 127) / 128, t256>>>(u16p, bhp + 128, whp + 16384, ssrc, sdst, Mx, E, 6);
    combine_kernel<<<(N * 32 + 255) / 256, t256>>>(P, Mx, indeg, gA, N,
                                                   bna + 896, u16p);  // u16 for EdgeConv3

    // EdgeConv3: gA[N,128] -> final combine fused with FC -> d_out [N,1]
    gemm_tc<<<dim3(mb, 2), t256>>>(gA, e3W, P, nullptr, N, 128, 128, 1, bna + 768, bnb + 768, nullptr);
    edgeconv_tc<<<(E + 127) / 128, t256>>>(u16p, bhp + 192, whp + 24576, ssrc, sdst, Mx, E, 6);
    combine_fc<<<(N + 7) / 8, t256>>>(P, Mx, indeg, Wfc, bfc, (float*)d_out, N);
}

// round 13
// speedup vs baseline: 3.8718x; 1.0567x over previous
#include <cuda_runtime.h>
#include <cuda_fp16.h>
#include <math.h>

#define NCAP 20000
#define ECAP 320000

// ---------------- static scratch (no allocation allowed) ----------------
static __device__ float    d_x0  [NCAP * 64];
static __device__ unsigned d_h16 [NCAP * 128];   // fp16-packed GCN linear outputs
static __device__ float    d_gA  [NCAP * 256];
static __device__ float    d_gB  [NCAP * 256];
static __device__ float    d_P   [NCAP * 128];
static __device__ unsigned d_Mx  [NCAP * 128];
static __device__ unsigned d_u16 [NCAP * 128];   // per-layer fp16-packed scaled node rows
static __device__ unsigned d_wh  [32768];        // fp16-interleaved weights, ALL 3 edge layers
static __device__ unsigned d_bh  [256];          // fp16-packed BN offsets, ALL 3 edge layers
static __device__ float    d_dinv[NCAP];
static __device__ int      d_indeg[NCAP];
static __device__ int      d_start[NCAP + 1];
static __device__ int      d_cnt  [NCAP];
static __device__ int      d_ssrc [ECAP];
static __device__ int      d_sdst [ECAP];
static __device__ float    d_ecoef[ECAP];
static __device__ float    d_bna [1024];         // BN scale, layers at 0 / 512 / 768
static __device__ float    d_bnb [1024];         // BN offset

// ---------------- helpers ----------------
__device__ __forceinline__ unsigned f2tf32(float x) {
    unsigned y;
    asm("cvt.rna.tf32.f32 %0, %1;" : "=r"(y) : "f"(x));
    return y;
}

__device__ __forceinline__ unsigned pack_h2(float lo, float hi) {
    __half2 h = __floats2half2_rn(lo, hi);
    return *(unsigned*)&h;
}

__device__ __forceinline__ unsigned h2_q(unsigned us, unsigned ud, unsigned bb) {
    __half2 z = __floats2half2_rn(0.f, 0.f);
    __half2 r = __hmax2(__hadd2(__hsub2(*(__half2*)&us, *(__half2*)&ud), *(__half2*)&bb), z);
    return *(unsigned*)&r;
}

__device__ __forceinline__ void mma_tf32(float* d, const unsigned* a, const unsigned* b) {
    asm volatile(
        "mma.sync.aligned.m16n8k8.row.col.f32.tf32.tf32.f32 "
        "{%0,%1,%2,%3}, {%4,%5,%6,%7}, {%8,%9}, {%0,%1,%2,%3};"
        : "+f"(d[0]), "+f"(d[1]), "+f"(d[2]), "+f"(d[3])
        : "r"(a[0]), "r"(a[1]), "r"(a[2]), "r"(a[3]), "r"(b[0]), "r"(b[1]));
}

__device__ __forceinline__ void mma_f16(float* d, const unsigned* a, const unsigned* b) {
    asm volatile(
        "mma.sync.aligned.m16n8k16.row.col.f32.f16.f16.f32 "
        "{%0,%1,%2,%3}, {%4,%5,%6,%7}, {%8,%9}, {%0,%1,%2,%3};"
        : "+f"(d[0]), "+f"(d[1]), "+f"(d[2]), "+f"(d[3])
        : "r"(a[0]), "r"(a[1]), "r"(a[2]), "r"(a[3]), "r"(b[0]), "r"(b[1]));
}

__device__ __forceinline__ void red_max_enc(unsigned* p, float v) {
    unsigned u = __float_as_uint(v);
    unsigned key = (u & 0x80000000u) ? ~u : (u | 0x80000000u);
    asm volatile("red.global.max.u32 [%0], %1;" :: "l"(p), "r"(key) : "memory");
}

// ---------------- small kernels ----------------
__global__ void count_indeg(const int* __restrict__ dstv, int* __restrict__ indeg, int E) {
    int e = blockIdx.x * 256 + threadIdx.x;
    if (e < E) atomicAdd(&indeg[dstv[e]], 1);
}

// ---------------- exclusive scan over indeg -> start; also zeros cnt, computes dinv ----------------
__global__ __launch_bounds__(1024) void scan_kernel(const int* __restrict__ indeg,
                                                    int* __restrict__ start,
                                                    int* __restrict__ cnt,
                                                    float* __restrict__ dinv, int N) {
    __shared__ int wsum[32];
    int t = threadIdx.x;
    int chunk = (N + 1023) / 1024;
    int lo = t * chunk;
    int hi = lo + chunk; if (hi > N) hi = N; if (lo > N) lo = N;
    int s = 0;
    for (int i = lo; i < hi; i++) s += indeg[i];
    int lane = t & 31, w = t >> 5;
    int v = s;
#pragma unroll
    for (int o = 1; o < 32; o <<= 1) {
        int u = __shfl_up_sync(0xffffffffu, v, o);
        if (lane >= o) v += u;
    }
    if (lane == 31) wsum[w] = v;
    __syncthreads();
    if (w == 0) {
        int x = wsum[lane];
#pragma unroll
        for (int o = 1; o < 32; o <<= 1) {
            int u = __shfl_up_sync(0xffffffffu, x, o);
            if (lane >= o) x += u;
        }
        wsum[lane] = x;
    }
    __syncthreads();
    int excl = (v - s) + (w > 0 ? wsum[w - 1] : 0);
    int run = excl;
    for (int i = lo; i < hi; i++) {
        start[i] = run;
        run += indeg[i];
        cnt[i] = 0;
        dinv[i] = rsqrtf((float)indeg[i] + 1.0f);
    }
    if (t == 1023) start[N] = run;
}

// ---------------- prep_all: edge scatter + Mx zero + packed fp16 weights/biases + BN coefs ----------------
__global__ void prep_all(
    const int* __restrict__ src, const int* __restrict__ dstv,
    const int* __restrict__ start, int* __restrict__ cnt, const float* __restrict__ dinv,
    int* __restrict__ ssrc, int* __restrict__ sdst, float* __restrict__ ecoef, int E,
    const float* __restrict__ w1, const float* __restrict__ w2, const float* __restrict__ w3,
    const float* __restrict__ g1, const float* __restrict__ b1,
    const float* __restrict__ m1, const float* __restrict__ v1,
    const float* __restrict__ g2, const float* __restrict__ b2,
    const float* __restrict__ m2, const float* __restrict__ v2,
    const float* __restrict__ g3, const float* __restrict__ b3,
    const float* __restrict__ m3, const float* __restrict__ v3,
    unsigned* __restrict__ Mx, unsigned* __restrict__ wh, unsigned* __restrict__ bh,
    float* __restrict__ bna, float* __restrict__ bnb, int N)
{
    int idx = blockIdx.x * 256 + threadIdx.x;
    if (idx < E) {
        int s = src[idx], d = dstv[idx];
        int p = start[d] + atomicAdd(&cnt[d], 1);
        ssrc[p] = s;
        sdst[p] = d;
        ecoef[p] = dinv[s] * dinv[d];
    }
    if (idx < N * 128) Mx[idx] = 0u;
    if (idx < 32768) {
        const float* W; int k2n;
        if (idx < 16384)      { W = w1; k2n = idx; }
        else if (idx < 24576) { W = w2; k2n = idx - 16384; }
        else                  { W = w3; k2n = idx - 24576; }
        int k2 = k2n >> 7, n = k2n & 127;
        wh[idx] = pack_h2(W[(2 * k2) * 128 + n], W[(2 * k2 + 1) * 128 + n]);
    }
    if (idx < 1024) {
        const float *g, *be, *me, *va; int i;
        if (idx < 512)      { g = g1; be = b1; me = m1; va = v1; i = idx; }
        else if (idx < 768) { g = g2; be = b2; me = m2; va = v2; i = idx - 512; }
        else                { g = g3; be = b3; me = m3; va = v3; i = idx - 768; }
        float a = g[i] * rsqrtf(va[i] + 1e-5f);
        bna[idx] = a;
        bnb[idx] = be[i] - me[i] * a;
    }
    if (idx < 256) {
        const float *g, *be, *me, *va; int c;
        if (idx < 128)      { g = g1; be = b1; me = m1; va = v1; c = 256 + 2 * idx; }
        else if (idx < 192) { g = g2; be = b2; me = m2; va = v2; c = 128 + 2 * (idx - 128); }
        else                { g = g3; be = b3; me = m3; va = v3; c = 128 + 2 * (idx - 192); }
        float a0 = g[c] * rsqrtf(va[c] + 1e-5f);
        float a1 = g[c + 1] * rsqrtf(va[c + 1] + 1e-5f);
        bh[idx] = pack_h2(be[c] - me[c] * a0, be[c + 1] - me[c + 1] * a1);
    }
}

// ---------------- TF32 GEMM tile body (shared by several kernels) ----------------
// C[f32, opt] / outh[fp16-packed, opt] = f(A) @ B (+ bias); rows strided by rmul.
// skip4: suppress stores on rows where gr % 4 == 0 (used by dual projection).
__device__ __forceinline__ void gemm_tile_body(
    const float* __restrict__ A, const float* __restrict__ B,
    float* __restrict__ C, unsigned* __restrict__ outh,
    int M, int K, int Ncols, int rmul, int skip4,
    const float* __restrict__ ta, const float* __restrict__ tb,
    const float* __restrict__ bias,
    int bx, int by, unsigned* As, unsigned* Bs)
{
    int tid = threadIdx.x;
    int lane = tid & 31, warp = tid >> 5;
    int wm = warp & 3, wn = warp >> 2;
    int gid = lane >> 2, tig = lane & 3;
    int row0 = bx * 64;
    int col0 = by * 64;
    float acc[4][4] = {};
    for (int k0 = 0; k0 < K; k0 += 32) {
#pragma unroll
        for (int i = 0; i < 2; i++) {
            int lin = tid + i * 256;          // 0..511
            int r = lin >> 3;                 // 0..63
            int k4 = (lin & 7) * 4;
            int gr = row0 + r;
            float4 v = make_float4(0.f, 0.f, 0.f, 0.f);
            if (gr < M) {
                v = *(const float4*)&A[(long long)gr * rmul * K + k0 + k4];
                if (ta) {
                    float4 a4 = *(const float4*)&ta[k0 + k4];
                    float4 b4 = *(const float4*)&tb[k0 + k4];
                    v.x = fmaxf(a4.x * v.x + b4.x, 0.f);
                    v.y = fmaxf(a4.y * v.y + b4.y, 0.f);
                    v.z = fmaxf(a4.z * v.z + b4.z, 0.f);
                    v.w = fmaxf(a4.w * v.w + b4.w, 0.f);
                }
            }
            *(uint4*)&As[r * 36 + k4] =
                make_uint4(f2tf32(v.x), f2tf32(v.y), f2tf32(v.z), f2tf32(v.w));
        }
#pragma unroll
        for (int i = 0; i < 2; i++) {
            int lin = tid + i * 256;
            int k = lin >> 4;                 // 0..31
            int n4 = (lin & 15) * 4;
            float4 w4 = *(const float4*)&B[(long long)(k0 + k) * Ncols + col0 + n4];
            *(uint4*)&Bs[k * 72 + n4] =
                make_uint4(f2tf32(w4.x), f2tf32(w4.y), f2tf32(w4.z), f2tf32(w4.w));
        }
        __syncthreads();
#pragma unroll
        for (int s = 0; s < 4; s++) {
            unsigned a[4];
            int ar = wm * 16 + gid;
            int ac = s * 8 + tig;
            a[0] = As[ar * 36 + ac];
            a[1] = As[(ar + 8) * 36 + ac];
            a[2] = As[ar * 36 + ac + 4];
            a[3] = As[(ar + 8) * 36 + ac + 4];
#pragma unroll
            for (int nt = 0; nt < 4; nt++) {
                unsigned b[2];
                int bc = wn * 32 + nt * 8 + gid;
                b[0] = Bs[(s * 8 + tig) * 72 + bc];
                b[1] = Bs[(s * 8 + tig + 4) * 72 + bc];
                mma_tf32(acc[nt], a, b);
            }
        }
        __syncthreads();
    }
#pragma unroll
    for (int half = 0; half < 2; half++) {
        int gr = row0 + wm * 16 + gid + half * 8;
        if (gr < M && !(skip4 && (gr & 3) == 0)) {
            long long prow = (long long)gr * rmul;
#pragma unroll
            for (int nt = 0; nt < 4; nt++) {
                int col = col0 + wn * 32 + nt * 8 + tig * 2;
                float v0 = acc[nt][half * 2 + 0];
                float v1 = acc[nt][half * 2 + 1];
                if (bias) { v0 += bias[col]; v1 += bias[col + 1]; }
                if (C) {
                    C[prow * Ncols + col]     = v0;
                    C[prow * Ncols + col + 1] = v1;
                }
                if (outh)
                    outh[prow * (Ncols >> 1) + (col >> 1)] = pack_h2(v0, v1);
            }
        }
    }
}

// ---------------- standalone GEMM kernel (GCN layers) ----------------
__global__ __launch_bounds__(256) void gemm_tc(
    const float* __restrict__ A, const float* __restrict__ B,
    float* __restrict__ C, unsigned* __restrict__ outh,
    int M, int K, int Ncols)
{
    __shared__ unsigned As[64 * 36];
    __shared__ unsigned Bs[32 * 72];
    gemm_tile_body(A, B, C, outh, M, K, Ncols, 1, 0, nullptr, nullptr, nullptr,
                   blockIdx.x, blockIdx.y, As, Bs);
}

// ---------------- fused dual projection + indeg zero ----------------
// blocks [0, mb): x@Wc+bc, store rows %4 != 0.  blocks [mb, mb+mb4): x@Wm+bm, rows 4k.
__global__ __launch_bounds__(256) void proj_fused(
    const float* __restrict__ x,
    const float* __restrict__ Wc, const float* __restrict__ bc,
    const float* __restrict__ Wm, const float* __restrict__ bm,
    float* __restrict__ x0, int* __restrict__ indeg, int N, int mb, int mb4)
{
    int gidx = blockIdx.x * 256 + threadIdx.x;
    if (gidx < N) indeg[gidx] = 0;
    __shared__ unsigned As[64 * 36];
    __shared__ unsigned Bs[32 * 72];
    if ((int)blockIdx.x < mb) {
        gemm_tile_body(x, Wc, x0, nullptr, N, 512, 64, 1, 1, nullptr, nullptr, bc,
                       blockIdx.x, 0, As, Bs);
    } else if ((int)blockIdx.x < mb + mb4) {
        gemm_tile_body(x, Wm, x0, nullptr, (N + 3) / 4, 512, 64, 4, 0, nullptr, nullptr, bm,
                       blockIdx.x - mb, 0, As, Bs);
    }
}

// ---------------- EdgeConv tile body ----------------
__device__ __forceinline__ void edgeconv_body(
    const unsigned* __restrict__ u16, const unsigned* __restrict__ b16,
    const unsigned* __restrict__ Whg,
    const int* __restrict__ ssrc, const int* __restrict__ sdstv,
    unsigned* __restrict__ Mout, int E, int lc2,
    int bid, unsigned* sh, int* ss, int* sd)
{
    unsigned* qh = sh;                 // [edge][k2] stride 20
    unsigned* wh = sh + 128 * 20;      // [k2][n]  stride 136
    int tid = threadIdx.x;
    int e0 = bid * 128;
    if (tid < 128) {
        int e = e0 + tid;
        if (e >= E) e = E - 1;
        ss[tid] = ssrc[e];
        sd[tid] = sdstv[e];
    }
    __syncthreads();
    int lane = tid & 31, warp = tid >> 5;
    int wm = warp & 3, wn = warp >> 2;
    int gid = lane >> 2, tig = lane & 3;
    int C2 = 1 << lc2;
    float acc[2][8][4] = {};
    for (int k20 = 0; k20 < C2; k20 += 16) {
#pragma unroll
        for (int i = 0; i < 2; i++) {
            int lin = tid + i * 256;          // 0..511
            int e = lin >> 2;                 // 0..127
            int q4 = (lin & 3) * 4;           // half2 offset
            int k2g = k20 + q4;
            uint4 us = *(const uint4*)&u16[(ss[e] << lc2) + k2g];
            uint4 ud = *(const uint4*)&u16[(sd[e] << lc2) + k2g];
            uint4 bb = *(const uint4*)&b16[k2g];
            uint4 r;
            r.x = h2_q(us.x, ud.x, bb.x);
            r.y = h2_q(us.y, ud.y, bb.y);
            r.z = h2_q(us.z, ud.z, bb.z);
            r.w = h2_q(us.w, ud.w, bb.w);
            *(uint4*)&qh[e * 20 + q4] = r;
        }
#pragma unroll
        for (int i = 0; i < 2; i++) {
            int lin = tid + i * 256;
            int k2 = lin >> 5;                // 0..15
            int n4 = (lin & 31) * 4;
            *(uint4*)&wh[k2 * 136 + n4] =
                *(const uint4*)&Whg[(k20 + k2) * 128 + n4];
        }
        __syncthreads();
#pragma unroll
        for (int s = 0; s < 2; s++) {
            unsigned bf[8][2];
#pragma unroll
            for (int nt = 0; nt < 8; nt++) {
                int bc = wn * 64 + nt * 8 + gid;
                bf[nt][0] = wh[(s * 8 + tig) * 136 + bc];
                bf[nt][1] = wh[(s * 8 + tig + 4) * 136 + bc];
            }
            int ac = s * 8 + tig;
#pragma unroll
            for (int mt = 0; mt < 2; mt++) {
                unsigned a[4];
                int ar = wm * 32 + mt * 16 + gid;
                a[0] = qh[ar * 20 + ac];
                a[1] = qh[(ar + 8) * 20 + ac];
                a[2] = qh[ar * 20 + ac + 4];
                a[3] = qh[(ar + 8) * 20 + ac + 4];
#pragma unroll
                for (int nt = 0; nt < 8; nt++)
                    mma_f16(acc[mt][nt], a, bf[nt]);
            }
        }
        __syncthreads();
    }
    // segmented max: 4 passes of 32 rows (dst-sorted); smem reuse
    float* sacc = (float*)sh;
#pragma unroll
    for (int pass = 0; pass < 4; pass++) {
        if (wm == pass) {
#pragma unroll
            for (int mt = 0; mt < 2; mt++) {
#pragma unroll
                for (int half = 0; half < 2; half++) {
                    int rl = mt * 16 + gid + half * 8;   // 0..31
#pragma unroll
                    for (int nt = 0; nt < 8; nt++) {
                        int col = wn * 64 + nt * 8 + tig * 2;
                        sacc[rl * 132 + col]     = acc[mt][nt][half * 2 + 0];
                        sacc[rl * 132 + col + 1] = acc[mt][nt][half * 2 + 1];
                    }
                }
            }
        }
        __syncthreads();
        {
            int col = tid & 127;
            int rh = tid >> 7;                  // 0..1
            int r0 = rh * 16, r1 = r0 + 16;
            int base = pass * 32;
            int cur = sd[base + r0];
            float m = sacc[r0 * 132 + col];
            for (int r = r0 + 1; r < r1; r++) {
                int d = sd[base + r];
                float v = sacc[r * 132 + col];
                if (d != cur) {
                    red_max_enc(&Mout[(long long)cur * 128 + col], m);
                    cur = d;
                    m = v;
                } else {
                    m = fmaxf(m, v);
                }
            }
            red_max_enc(&Mout[(long long)cur * 128 + col], m);
        }
        __syncthreads();
    }
}

// ---------------- fused per-layer kernel: edgeconv tiles + P-GEMM tiles in one launch ----------------
// blocks [0, eb): edgeconv;  blocks [eb, eb+pb): P = relu(BN(A)) @ B  (Ncols=128, pb = mbx*2)
__global__ __launch_bounds__(256) void edge_fused(
    const unsigned* __restrict__ u16, const unsigned* __restrict__ b16,
    const unsigned* __restrict__ Whg,
    const int* __restrict__ ssrc, const int* __restrict__ sdstv,
    unsigned* __restrict__ Mout, int E, int lc2, int eb,
    const float* __restrict__ A, const float* __restrict__ B, float* __restrict__ P,
    int M, int K, const float* __restrict__ ta, const float* __restrict__ tb, int mbx)
{
    __shared__ unsigned buf[128 * 20 + 16 * 136];   // 4736 u32 >= gemm's 4608
    __shared__ int ssA[128], sdA[128];
    if ((int)blockIdx.x < eb) {
        edgeconv_body(u16, b16, Whg, ssrc, sdstv, Mout, E, lc2, blockIdx.x, buf, ssA, sdA);
    } else {
        int b = blockIdx.x - eb;
        gemm_tile_body(A, B, P, nullptr, M, K, 128, 1, 0, ta, tb, nullptr,
                       b % mbx, b / mbx, buf, buf + 64 * 36);
    }
}

// ---------------- GCN aggregation: CSR gather over fp16 rows, 4-way unroll; optional u16 emit ----------------
__global__ __launch_bounds__(256) void gcn_gather(
    const unsigned* __restrict__ h16, const int* __restrict__ ssrc,
    const float* __restrict__ ecoef, const int* __restrict__ start,
    const float* __restrict__ dinv, const float* __restrict__ bias,
    float* __restrict__ out, int N, int lc,
    const float* __restrict__ a2u, unsigned* __restrict__ u16)
{
    int node = blockIdx.x * 8 + (threadIdx.x >> 5);
    int lane = threadIdx.x & 31;
    if (node >= N) return;
    int groups = 1 << (lc - 7);          // 1 (128 cols) or 2 (256 cols)
    int rowlen = 1 << (lc - 1);          // u32 per row
    float di = dinv[node];
    float di2 = di * di;
    float4 acc[2];
    const unsigned* self = &h16[(long long)node * rowlen];
#pragma unroll
    for (int j = 0; j < 2; j++) {
        if (j < groups) {
            uint2 hv = *(const uint2*)&self[j * 64 + lane * 2];
            float2 f0 = __half22float2(*(__half2*)&hv.x);
            float2 f1 = __half22float2(*(__half2*)&hv.y);
            float4 bv = *(const float4*)&bias[j * 128 + lane * 4];
            acc[j].x = bv.x + di2 * f0.x;
            acc[j].y = bv.y + di2 * f0.y;
            acc[j].z = bv.z + di2 * f1.x;
            acc[j].w = bv.w + di2 * f1.y;
        }
    }
    int s0 = start[node], s1 = start[node + 1];
    for (int base = s0; base < s1; base += 32) {
        int e = base + lane;
        int sidx = 0; float cf = 0.f;
        if (e < s1) { sidx = ssrc[e]; cf = ecoef[e]; }
        int cnt = s1 - base; if (cnt > 32) cnt = 32;
        int j = 0;
        for (; j + 4 <= cnt; j += 4) {
            int sa = __shfl_sync(0xffffffffu, sidx, j);
            int sb = __shfl_sync(0xffffffffu, sidx, j + 1);
            int sc = __shfl_sync(0xffffffffu, sidx, j + 2);
            int sdd = __shfl_sync(0xffffffffu, sidx, j + 3);
            float ca = __shfl_sync(0xffffffffu, cf, j);
            float cb = __shfl_sync(0xffffffffu, cf, j + 1);
            float cc = __shfl_sync(0xffffffffu, cf, j + 2);
            float cd = __shfl_sync(0xffffffffu, cf, j + 3);
            const unsigned* ra = &h16[(long long)sa * rowlen];
            const unsigned* rb = &h16[(long long)sb * rowlen];
            const unsigned* rc = &h16[(long long)sc * rowlen];
            const unsigned* rd = &h16[(long long)sdd * rowlen];
#pragma unroll
            for (int g = 0; g < 2; g++) {
                if (g < groups) {
                    int off = g * 64 + lane * 2;
                    uint2 ha = *(const uint2*)&ra[off];
                    uint2 hb = *(const uint2*)&rb[off];
                    uint2 hc = *(const uint2*)&rc[off];
                    uint2 hd = *(const uint2*)&rd[off];
                    float2 a0 = __half22float2(*(__half2*)&ha.x);
                    float2 a1 = __half22float2(*(__half2*)&ha.y);
                    float2 b0 = __half22float2(*(__half2*)&hb.x);
                    float2 b1 = __half22float2(*(__half2*)&hb.y);
                    float2 c0 = __half22float2(*(__half2*)&hc.x);
                    float2 c1 = __half22float2(*(__half2*)&hc.y);
                    float2 d0 = __half22float2(*(__half2*)&hd.x);
                    float2 d1 = __half22float2(*(__half2*)&hd.y);
                    acc[g].x += ca * a0.x + cb * b0.x + cc * c0.x + cd * d0.x;
                    acc[g].y += ca * a0.y + cb * b0.y + cc * c0.y + cd * d0.y;
                    acc[g].z += ca * a1.x + cb * b1.x + cc * c1.x + cd * d1.x;
                    acc[g].w += ca * a1.y + cb * b1.y + cc * c1.y + cd * d1.y;
                }
            }
        }
        for (; j < cnt; j++) {
            int s = __shfl_sync(0xffffffffu, sidx, j);
            float coef = __shfl_sync(0xffffffffu, cf, j);
            const unsigned* hr = &h16[(long long)s * rowlen];
#pragma unroll
            for (int g = 0; g < 2; g++) {
                if (g < groups) {
                    uint2 hv = *(const uint2*)&hr[g * 64 + lane * 2];
                    float2 f0 = __half22float2(*(__half2*)&hv.x);
                    float2 f1 = __half22float2(*(__half2*)&hv.y);
                    acc[g].x += coef * f0.x;
                    acc[g].y += coef * f0.y;
                    acc[g].z += coef * f1.x;
                    acc[g].w += coef * f1.y;
                }
            }
        }
    }
#pragma unroll
    for (int j = 0; j < 2; j++) {
        if (j < groups) {
            int col = j * 128 + lane * 4;
            *(float4*)&out[((long long)node << lc) + col] = acc[j];
            if (a2u) {
                float4 a4 = *(const float4*)&a2u[col];
                uint2 pk;
                pk.x = pack_h2(a4.x * acc[j].x, a4.y * acc[j].y);
                pk.y = pack_h2(a4.z * acc[j].z, a4.w * acc[j].w);
                *(uint2*)&u16[((long long)node << (lc - 1)) + j * 64 + lane * 2] = pk;
            }
        }
    }
}

// ---------------- EdgeConv combine (+ optional fused u16 emit for next layer); resets M ----------------
__global__ void combine_kernel(const float* __restrict__ P, unsigned* __restrict__ Mv,
                               const int* __restrict__ indeg, float* __restrict__ out, int N,
                               const float* __restrict__ a2u, unsigned* __restrict__ u16)
{
    int idx4 = blockIdx.x * 256 + threadIdx.x;
    if (idx4 >= N * 32) return;
    int i = idx4 >> 5;
    int colbase = (idx4 & 31) * 4;
    uint4 kv = *(uint4*)&Mv[idx4 * 4];
    float4 pv = *(const float4*)&P[idx4 * 4];
    float4 o = make_float4(0.f, 0.f, 0.f, 0.f);
    if (indeg[i] > 0) {
        unsigned u0 = (kv.x & 0x80000000u) ? (kv.x & 0x7fffffffu) : ~kv.x;
        unsigned u1 = (kv.y & 0x80000000u) ? (kv.y & 0x7fffffffu) : ~kv.y;
        unsigned u2 = (kv.z & 0x80000000u) ? (kv.z & 0x7fffffffu) : ~kv.z;
        unsigned u3 = (kv.w & 0x80000000u) ? (kv.w & 0x7fffffffu) : ~kv.w;
        o.x = pv.x + __uint_as_float(u0);
        o.y = pv.y + __uint_as_float(u1);
        o.z = pv.z + __uint_as_float(u2);
        o.w = pv.w + __uint_as_float(u3);
    }
    *(uint4*)&Mv[idx4 * 4] = make_uint4(0u, 0u, 0u, 0u);   // re-zero for next layer
    *(float4*)&out[idx4 * 4] = o;
    if (a2u) {
        float4 a4 = *(const float4*)&a2u[colbase];
        uint2 pk;
        pk.x = pack_h2(a4.x * o.x, a4.y * o.y);
        pk.y = pack_h2(a4.z * o.z, a4.w * o.w);
        *(uint2*)&u16[(i << 6) + (idx4 & 31) * 2] = pk;
    }
}

// ---------------- final: combine last EdgeConv + FC in one pass (warp per node) ----------------
__global__ void combine_fc(const float* __restrict__ P, const unsigned* __restrict__ Mv,
                           const int* __restrict__ indeg,
                           const float* __restrict__ W, const float* __restrict__ b,
                           float* __restrict__ out, int N)
{
    int node = blockIdx.x * 8 + (threadIdx.x >> 5);
    int lane = threadIdx.x & 31;
    if (node >= N) return;
    uint4 kv = *(const uint4*)&Mv[node * 128 + lane * 4];
    float4 pv = *(const float4*)&P[node * 128 + lane * 4];
    float4 o = make_float4(0.f, 0.f, 0.f, 0.f);
    if (indeg[node] > 0) {
        unsigned u0 = (kv.x & 0x80000000u) ? (kv.x & 0x7fffffffu) : ~kv.x;
        unsigned u1 = (kv.y & 0x80000000u) ? (kv.y & 0x7fffffffu) : ~kv.y;
        unsigned u2 = (kv.z & 0x80000000u) ? (kv.z & 0x7fffffffu) : ~kv.z;
        unsigned u3 = (kv.w & 0x80000000u) ? (kv.w & 0x7fffffffu) : ~kv.w;
        o.x = pv.x + __uint_as_float(u0);
        o.y = pv.y + __uint_as_float(u1);
        o.z = pv.z + __uint_as_float(u2);
        o.w = pv.w + __uint_as_float(u3);
    }
    float4 w = *(const float4*)&W[lane * 4];
    float s = o.x * w.x + o.y * w.y + o.z * w.z + o.w * w.w;
#pragma unroll
    for (int off = 16; off; off >>= 1) s += __shfl_down_sync(0xffffffffu, s, off);
    if (lane == 0) out[node] = s + b[0];
}

// ---------------- launch ----------------
extern "C" void kernel_launch(void* const* d_in, const int* in_sizes, int n_in,
                              void* d_out, int out_size)
{
    const float* x   = (const float*)d_in[0];
    const int*   ei  = (const int*)d_in[1];
    const float* Wm  = (const float*)d_in[2];
    const float* bm  = (const float*)d_in[3];
    const float* Wc  = (const float*)d_in[4];
    const float* bc  = (const float*)d_in[5];
    const float* Wg1 = (const float*)d_in[6];
    const float* bg1 = (const float*)d_in[7];
    const float* Wg2 = (const float*)d_in[8];
    const float* bg2 = (const float*)d_in[9];
    const float* Wg3 = (const float*)d_in[10];
    const float* bg3 = (const float*)d_in[11];
    const float* e1g = (const float*)d_in[12];
    const float* e1b = (const float*)d_in[13];
    const float* e1m = (const float*)d_in[14];
    const float* e1v = (const float*)d_in[15];
    const float* e1W = (const float*)d_in[16];
    const float* e2g = (const float*)d_in[17];
    const float* e2b = (const float*)d_in[18];
    const float* e2m = (const float*)d_in[19];
    const float* e2v = (const float*)d_in[20];
    const float* e2W = (const float*)d_in[21];
    const float* e3g = (const float*)d_in[22];
    const float* e3b = (const float*)d_in[23];
    const float* e3m = (const float*)d_in[24];
    const float* e3v = (const float*)d_in[25];
    const float* e3W = (const float*)d_in[26];
    const float* Wfc = (const float*)d_in[27];
    const float* bfc = (const float*)d_in[28];

    int N = in_sizes[0] / 512;
    int E = in_sizes[1] / 2;
    const int* src = ei;
    const int* dst = ei + E;

    float *x0, *gA, *gB, *P, *dinv, *bna, *bnb, *ecoef;
    unsigned *Mx, *u16p, *whp, *bhp, *h16;
    int *indeg, *startp, *cnt, *ssrc, *sdst;
    cudaGetSymbolAddress((void**)&x0,    d_x0);
    cudaGetSymbolAddress((void**)&h16,   d_h16);
    cudaGetSymbolAddress((void**)&gA,    d_gA);
    cudaGetSymbolAddress((void**)&gB,    d_gB);
    cudaGetSymbolAddress((void**)&P,     d_P);
    cudaGetSymbolAddress((void**)&Mx,    d_Mx);
    cudaGetSymbolAddress((void**)&u16p,  d_u16);
    cudaGetSymbolAddress((void**)&whp,   d_wh);
    cudaGetSymbolAddress((void**)&bhp,   d_bh);
    cudaGetSymbolAddress((void**)&dinv,  d_dinv);
    cudaGetSymbolAddress((void**)&indeg, d_indeg);
    cudaGetSymbolAddress((void**)&startp,d_start);
    cudaGetSymbolAddress((void**)&cnt,   d_cnt);
    cudaGetSymbolAddress((void**)&ssrc,  d_ssrc);
    cudaGetSymbolAddress((void**)&sdst,  d_sdst);
    cudaGetSymbolAddress((void**)&ecoef, d_ecoef);
    cudaGetSymbolAddress((void**)&bna,   d_bna);
    cudaGetSymbolAddress((void**)&bnb,   d_bnb);

    dim3 t256(256);
    int mb = (N + 63) / 64;
    int M4 = (N + 3) / 4;
    int mb4 = (M4 + 63) / 64;
    int eb = (E + 127) / 128;

    // fused dual projection (also zeroes indeg)
    int pg = mb + mb4;
    int zg = (N + 255) / 256;
    proj_fused<<<(pg > zg ? pg : zg), t256>>>(x, Wc, bc, Wm, bm, x0, indeg, N, mb, mb4);

    // degrees + CSR sort by dst + launch-invariant prep
    count_indeg<<<(E + 255) / 256, t256>>>(dst, indeg, E);
    scan_kernel<<<1, 1024>>>(indeg, startp, cnt, dinv, N);
    prep_all<<<(N * 128 + 255) / 256, t256>>>(
        src, dst, startp, cnt, dinv, ssrc, sdst, ecoef, E,
        e1W + 256 * 128, e2W + 128 * 128, e3W + 128 * 128,
        e1g, e1b, e1m, e1v, e2g, e2b, e2m, e2v, e3g, e3b, e3m, e3v,
        Mx, whp, bhp, bna, bnb, N);

    // GCN1: x0[N,64] @ Wg1[64,128] -> h16; gather -> gA
    gemm_tc<<<dim3(mb, 2), t256>>>(x0, Wg1, nullptr, h16, N, 64, 128);
    gcn_gather<<<(N + 7) / 8, t256>>>(h16, ssrc, ecoef, startp, dinv, bg1, gA, N, 7,
                                      nullptr, nullptr);

    // GCN2
    gemm_tc<<<dim3(mb, 2), t256>>>(gA, Wg2, nullptr, h16, N, 128, 128);
    gcn_gather<<<(N + 7) / 8, t256>>>(h16, ssrc, ecoef, startp, dinv, bg2, gB, N, 7,
                                      nullptr, nullptr);

    // GCN3 (out 256); fused u16 emit for EdgeConv1
    gemm_tc<<<dim3(mb, 4), t256>>>(gB, Wg3, nullptr, h16, N, 128, 256);
    gcn_gather<<<(N + 7) / 8, t256>>>(h16, ssrc, ecoef, startp, dinv, bg3, gA, N, 8,
                                      bna + 256, u16p);

    // EdgeConv1 (fused edgeconv + P-GEMM): gA[N,256] -> gB[N,128]
    edge_fused<<<eb + mb * 2, t256>>>(u16p, bhp, whp, ssrc, sdst, Mx, E, 7, eb,
                                      gA, e1W, P, N, 256, bna, bnb, mb);
    combine_kernel<<<(N * 32 + 255) / 256, t256>>>(P, Mx, indeg, gB, N,
                                                   bna + 640, u16p);

    // EdgeConv2: gB[N,128] -> gA[N,128]
    edge_fused<<<eb + mb * 2, t256>>>(u16p, bhp + 128, whp + 16384, ssrc, sdst, Mx, E, 6, eb,
                                      gB, e2W, P, N, 128, bna + 512, bnb + 512, mb);
    combine_kernel<<<(N * 32 + 255) / 256, t256>>>(P, Mx, indeg, gA, N,
                                                   bna + 896, u16p);

    // EdgeConv3: gA[N,128] -> final combine fused with FC -> d_out [N,1]
    edge_fused<<<eb + mb * 2, t256>>>(u16p, bhp + 192, whp + 24576, ssrc, sdst, Mx, E, 6, eb,
                                      gA, e3W, P, N, 128, bna + 768, bnb + 768, mb);
    combine_fc<<<(N + 7) / 8, t256>>>(P, Mx, indeg, Wfc, bfc, (float*)d_out, N);
}

// round 14
// speedup vs baseline: 3.9893x; 1.0303x over previous
#include <cuda_runtime.h>
#include <cuda_fp16.h>
#include <math.h>

#define NCAP 20000
#define ECAP 320000

// ---------------- static scratch (no allocation allowed) ----------------
static __device__ float    d_x0  [NCAP * 64];
static __device__ unsigned d_h16 [NCAP * 128];   // fp16-packed GCN linear outputs
static __device__ float    d_gA  [NCAP * 256];
static __device__ float    d_gB  [NCAP * 256];
static __device__ float    d_P   [NCAP * 128];
static __device__ unsigned d_Mx  [NCAP * 128];
static __device__ unsigned d_u16 [NCAP * 128];   // per-layer fp16-packed scaled node rows
static __device__ unsigned d_wh  [32768];        // fp16-interleaved weights, ALL 3 edge layers
static __device__ unsigned d_bh  [256];          // fp16-packed BN offsets, ALL 3 edge layers
static __device__ float    d_dinv[NCAP];
static __device__ int      d_indeg[NCAP];
static __device__ int      d_start[NCAP + 1];
static __device__ int      d_cnt  [NCAP];
static __device__ int      d_ssrc [ECAP];
static __device__ int      d_sdst [ECAP];
static __device__ float    d_ecoef[ECAP];
static __device__ float    d_bna [1024];         // BN scale, layers at 0 / 512 / 768
static __device__ float    d_bnb [1024];         // BN offset

// ---------------- helpers ----------------
__device__ __forceinline__ unsigned pack_h2(float lo, float hi) {
    __half2 h = __floats2half2_rn(lo, hi);
    return *(unsigned*)&h;
}

__device__ __forceinline__ unsigned h2_q(unsigned us, unsigned ud, unsigned bb) {
    __half2 z = __floats2half2_rn(0.f, 0.f);
    __half2 r = __hmax2(__hadd2(__hsub2(*(__half2*)&us, *(__half2*)&ud), *(__half2*)&bb), z);
    return *(unsigned*)&r;
}

__device__ __forceinline__ void mma_f16(float* d, const unsigned* a, const unsigned* b) {
    asm volatile(
        "mma.sync.aligned.m16n8k16.row.col.f32.f16.f16.f32 "
        "{%0,%1,%2,%3}, {%4,%5,%6,%7}, {%8,%9}, {%0,%1,%2,%3};"
        : "+f"(d[0]), "+f"(d[1]), "+f"(d[2]), "+f"(d[3])
        : "r"(a[0]), "r"(a[1]), "r"(a[2]), "r"(a[3]), "r"(b[0]), "r"(b[1]));
}

__device__ __forceinline__ void red_max_enc(unsigned* p, float v) {
    unsigned u = __float_as_uint(v);
    unsigned key = (u & 0x80000000u) ? ~u : (u | 0x80000000u);
    asm volatile("red.global.max.u32 [%0], %1;" :: "l"(p), "r"(key) : "memory");
}

// ---------------- small kernels ----------------
__global__ void count_indeg(const int* __restrict__ dstv, int* __restrict__ indeg, int E) {
    int e = blockIdx.x * 256 + threadIdx.x;
    if (e < E) atomicAdd(&indeg[dstv[e]], 1);
}

// ---------------- exclusive scan over indeg -> start; also zeros cnt, computes dinv ----------------
__global__ __launch_bounds__(1024) void scan_kernel(const int* __restrict__ indeg,
                                                    int* __restrict__ start,
                                                    int* __restrict__ cnt,
                                                    float* __restrict__ dinv, int N) {
    __shared__ int wsum[32];
    int t = threadIdx.x;
    int chunk = (N + 1023) / 1024;
    int lo = t * chunk;
    int hi = lo + chunk; if (hi > N) hi = N; if (lo > N) lo = N;
    int s = 0;
    for (int i = lo; i < hi; i++) s += indeg[i];
    int lane = t & 31, w = t >> 5;
    int v = s;
#pragma unroll
    for (int o = 1; o < 32; o <<= 1) {
        int u = __shfl_up_sync(0xffffffffu, v, o);
        if (lane >= o) v += u;
    }
    if (lane == 31) wsum[w] = v;
    __syncthreads();
    if (w == 0) {
        int x = wsum[lane];
#pragma unroll
        for (int o = 1; o < 32; o <<= 1) {
            int u = __shfl_up_sync(0xffffffffu, x, o);
            if (lane >= o) x += u;
        }
        wsum[lane] = x;
    }
    __syncthreads();
    int excl = (v - s) + (w > 0 ? wsum[w - 1] : 0);
    int run = excl;
    for (int i = lo; i < hi; i++) {
        start[i] = run;
        run += indeg[i];
        cnt[i] = 0;
        dinv[i] = rsqrtf((float)indeg[i] + 1.0f);
    }
    if (t == 1023) start[N] = run;
}

// ---------------- prep_all: edge scatter + Mx zero + packed fp16 weights/biases + BN coefs ----------------
__global__ void prep_all(
    const int* __restrict__ src, const int* __restrict__ dstv,
    const int* __restrict__ start, int* __restrict__ cnt, const float* __restrict__ dinv,
    int* __restrict__ ssrc, int* __restrict__ sdst, float* __restrict__ ecoef, int E,
    const float* __restrict__ w1, const float* __restrict__ w2, const float* __restrict__ w3,
    const float* __restrict__ g1, const float* __restrict__ b1,
    const float* __restrict__ m1, const float* __restrict__ v1,
    const float* __restrict__ g2, const float* __restrict__ b2,
    const float* __restrict__ m2, const float* __restrict__ v2,
    const float* __restrict__ g3, const float* __restrict__ b3,
    const float* __restrict__ m3, const float* __restrict__ v3,
    unsigned* __restrict__ Mx, unsigned* __restrict__ wh, unsigned* __restrict__ bh,
    float* __restrict__ bna, float* __restrict__ bnb, int N)
{
    int idx = blockIdx.x * 256 + threadIdx.x;
    if (idx < E) {
        int s = src[idx], d = dstv[idx];
        int p = start[d] + atomicAdd(&cnt[d], 1);
        ssrc[p] = s;
        sdst[p] = d;
        ecoef[p] = dinv[s] * dinv[d];
    }
    if (idx < N * 128) Mx[idx] = 0u;
    if (idx < 32768) {
        const float* W; int k2n;
        if (idx < 16384)      { W = w1; k2n = idx; }
        else if (idx < 24576) { W = w2; k2n = idx - 16384; }
        else                  { W = w3; k2n = idx - 24576; }
        int k2 = k2n >> 7, n = k2n & 127;
        wh[idx] = pack_h2(W[(2 * k2) * 128 + n], W[(2 * k2 + 1) * 128 + n]);
    }
    if (idx < 1024) {
        const float *g, *be, *me, *va; int i;
        if (idx < 512)      { g = g1; be = b1; me = m1; va = v1; i = idx; }
        else if (idx < 768) { g = g2; be = b2; me = m2; va = v2; i = idx - 512; }
        else                { g = g3; be = b3; me = m3; va = v3; i = idx - 768; }
        float a = g[i] * rsqrtf(va[i] + 1e-5f);
        bna[idx] = a;
        bnb[idx] = be[i] - me[i] * a;
    }
    if (idx < 256) {
        const float *g, *be, *me, *va; int c;
        if (idx < 128)      { g = g1; be = b1; me = m1; va = v1; c = 256 + 2 * idx; }
        else if (idx < 192) { g = g2; be = b2; me = m2; va = v2; c = 128 + 2 * (idx - 128); }
        else                { g = g3; be = b3; me = m3; va = v3; c = 128 + 2 * (idx - 192); }
        float a0 = g[c] * rsqrtf(va[c] + 1e-5f);
        float a1 = g[c + 1] * rsqrtf(va[c + 1] + 1e-5f);
        bh[idx] = pack_h2(be[c] - me[c] * a0, be[c + 1] - me[c + 1] * a1);
    }
}

// ---------------- FP16 GEMM tile body (m16n8k16) ----------------
// C[f32, opt] / outh[fp16-packed, opt] = f(A) @ B (+ bias); rows strided by rmul.
// skip4: suppress stores on rows where gr % 4 == 0 (used by dual projection).
// smem: As 64 rows x 20 u32 (16 half2 + pad) = 1280; Bs 16 k2 x 72 = 1152.
__device__ __forceinline__ void gemm_tile_body(
    const float* __restrict__ A, const float* __restrict__ B,
    float* __restrict__ C, unsigned* __restrict__ outh,
    int M, int K, int Ncols, int rmul, int skip4,
    const float* __restrict__ ta, const float* __restrict__ tb,
    const float* __restrict__ bias,
    int bx, int by, unsigned* As, unsigned* Bs)
{
    int tid = threadIdx.x;
    int lane = tid & 31, warp = tid >> 5;
    int wm = warp & 3, wn = warp >> 2;
    int gid = lane >> 2, tig = lane & 3;
    int row0 = bx * 64;
    int col0 = by * 64;
    float acc[4][4] = {};
    for (int k0 = 0; k0 < K; k0 += 32) {
#pragma unroll
        for (int i = 0; i < 2; i++) {
            int lin = tid + i * 256;          // 0..511
            int r = lin >> 3;                 // 0..63
            int k4 = (lin & 7) * 4;           // float offset in chunk
            int gr = row0 + r;
            float4 v = make_float4(0.f, 0.f, 0.f, 0.f);
            if (gr < M) {
                v = *(const float4*)&A[(long long)gr * rmul * K + k0 + k4];
                if (ta) {
                    float4 a4 = *(const float4*)&ta[k0 + k4];
                    float4 b4 = *(const float4*)&tb[k0 + k4];
                    v.x = fmaxf(a4.x * v.x + b4.x, 0.f);
                    v.y = fmaxf(a4.y * v.y + b4.y, 0.f);
                    v.z = fmaxf(a4.z * v.z + b4.z, 0.f);
                    v.w = fmaxf(a4.w * v.w + b4.w, 0.f);
                }
            }
            *(uint2*)&As[r * 20 + (lin & 7) * 2] =
                make_uint2(pack_h2(v.x, v.y), pack_h2(v.z, v.w));
        }
#pragma unroll
        for (int i = 0; i < 2; i++) {
            int lin = tid + i * 256;          // 0..511
            int k2 = lin >> 5;                // 0..15 (half2-k index)
            int n2 = (lin & 31) * 2;          // 2 columns per thread
            const float* w0 = &B[(long long)(k0 + 2 * k2) * Ncols + col0 + n2];
            const float* w1 = &B[(long long)(k0 + 2 * k2 + 1) * Ncols + col0 + n2];
            float2 wa = *(const float2*)w0;
            float2 wb = *(const float2*)w1;
            *(uint2*)&Bs[k2 * 72 + n2] =
                make_uint2(pack_h2(wa.x, wb.x), pack_h2(wa.y, wb.y));
        }
        __syncthreads();
#pragma unroll
        for (int s = 0; s < 2; s++) {
            int ac = s * 8 + tig;
            unsigned a[4];
            int ar = wm * 16 + gid;
            a[0] = As[ar * 20 + ac];
            a[1] = As[(ar + 8) * 20 + ac];
            a[2] = As[ar * 20 + ac + 4];
            a[3] = As[(ar + 8) * 20 + ac + 4];
#pragma unroll
            for (int nt = 0; nt < 4; nt++) {
                unsigned b[2];
                int bc = wn * 32 + nt * 8 + gid;
                b[0] = Bs[(s * 8 + tig) * 72 + bc];
                b[1] = Bs[(s * 8 + tig + 4) * 72 + bc];
                mma_f16(acc[nt], a, b);
            }
        }
        __syncthreads();
    }
#pragma unroll
    for (int half = 0; half < 2; half++) {
        int gr = row0 + wm * 16 + gid + half * 8;
        if (gr < M && !(skip4 && (gr & 3) == 0)) {
            long long prow = (long long)gr * rmul;
#pragma unroll
            for (int nt = 0; nt < 4; nt++) {
                int col = col0 + wn * 32 + nt * 8 + tig * 2;
                float v0 = acc[nt][half * 2 + 0];
                float v1 = acc[nt][half * 2 + 1];
                if (bias) { v0 += bias[col]; v1 += bias[col + 1]; }
                if (C) {
                    C[prow * Ncols + col]     = v0;
                    C[prow * Ncols + col + 1] = v1;
                }
                if (outh)
                    outh[prow * (Ncols >> 1) + (col >> 1)] = pack_h2(v0, v1);
            }
        }
    }
}

// ---------------- standalone GEMM kernel (GCN layers) ----------------
__global__ __launch_bounds__(256) void gemm_tc(
    const float* __restrict__ A, const float* __restrict__ B,
    float* __restrict__ C, unsigned* __restrict__ outh,
    int M, int K, int Ncols)
{
    __shared__ unsigned As[64 * 20];
    __shared__ unsigned Bs[16 * 72];
    gemm_tile_body(A, B, C, outh, M, K, Ncols, 1, 0, nullptr, nullptr, nullptr,
                   blockIdx.x, blockIdx.y, As, Bs);
}

// ---------------- fused dual projection + indeg zero ----------------
__global__ __launch_bounds__(256) void proj_fused(
    const float* __restrict__ x,
    const float* __restrict__ Wc, const float* __restrict__ bc,
    const float* __restrict__ Wm, const float* __restrict__ bm,
    float* __restrict__ x0, int* __restrict__ indeg, int N, int mb, int mb4)
{
    int gidx = blockIdx.x * 256 + threadIdx.x;
    if (gidx < N) indeg[gidx] = 0;
    __shared__ unsigned As[64 * 20];
    __shared__ unsigned Bs[16 * 72];
    if ((int)blockIdx.x < mb) {
        gemm_tile_body(x, Wc, x0, nullptr, N, 512, 64, 1, 1, nullptr, nullptr, bc,
                       blockIdx.x, 0, As, Bs);
    } else if ((int)blockIdx.x < mb + mb4) {
        gemm_tile_body(x, Wm, x0, nullptr, (N + 3) / 4, 512, 64, 4, 0, nullptr, nullptr, bm,
                       blockIdx.x - mb, 0, As, Bs);
    }
}

// ---------------- EdgeConv tile body ----------------
__device__ __forceinline__ void edgeconv_body(
    const unsigned* __restrict__ u16, const unsigned* __restrict__ b16,
    const unsigned* __restrict__ Whg,
    const int* __restrict__ ssrc, const int* __restrict__ sdstv,
    unsigned* __restrict__ Mout, int E, int lc2,
    int bid, unsigned* sh, int* ss, int* sd)
{
    unsigned* qh = sh;                 // [edge][k2] stride 20
    unsigned* wh = sh + 128 * 20;      // [k2][n]  stride 136
    int tid = threadIdx.x;
    int e0 = bid * 128;
    if (tid < 128) {
        int e = e0 + tid;
        if (e >= E) e = E - 1;
        ss[tid] = ssrc[e];
        sd[tid] = sdstv[e];
    }
    __syncthreads();
    int lane = tid & 31, warp = tid >> 5;
    int wm = warp & 3, wn = warp >> 2;
    int gid = lane >> 2, tig = lane & 3;
    int C2 = 1 << lc2;
    float acc[2][8][4] = {};
    for (int k20 = 0; k20 < C2; k20 += 16) {
#pragma unroll
        for (int i = 0; i < 2; i++) {
            int lin = tid + i * 256;          // 0..511
            int e = lin >> 2;                 // 0..127
            int q4 = (lin & 3) * 4;           // half2 offset
            int k2g = k20 + q4;
            uint4 us = *(const uint4*)&u16[(ss[e] << lc2) + k2g];
            uint4 ud = *(const uint4*)&u16[(sd[e] << lc2) + k2g];
            uint4 bb = *(const uint4*)&b16[k2g];
            uint4 r;
            r.x = h2_q(us.x, ud.x, bb.x);
            r.y = h2_q(us.y, ud.y, bb.y);
            r.z = h2_q(us.z, ud.z, bb.z);
            r.w = h2_q(us.w, ud.w, bb.w);
            *(uint4*)&qh[e * 20 + q4] = r;
        }
#pragma unroll
        for (int i = 0; i < 2; i++) {
            int lin = tid + i * 256;
            int k2 = lin >> 5;                // 0..15
            int n4 = (lin & 31) * 4;
            *(uint4*)&wh[k2 * 136 + n4] =
                *(const uint4*)&Whg[(k20 + k2) * 128 + n4];
        }
        __syncthreads();
#pragma unroll
        for (int s = 0; s < 2; s++) {
            unsigned bf[8][2];
#pragma unroll
            for (int nt = 0; nt < 8; nt++) {
                int bc = wn * 64 + nt * 8 + gid;
                bf[nt][0] = wh[(s * 8 + tig) * 136 + bc];
                bf[nt][1] = wh[(s * 8 + tig + 4) * 136 + bc];
            }
            int ac = s * 8 + tig;
#pragma unroll
            for (int mt = 0; mt < 2; mt++) {
                unsigned a[4];
                int ar = wm * 32 + mt * 16 + gid;
                a[0] = qh[ar * 20 + ac];
                a[1] = qh[(ar + 8) * 20 + ac];
                a[2] = qh[ar * 20 + ac + 4];
                a[3] = qh[(ar + 8) * 20 + ac + 4];
#pragma unroll
                for (int nt = 0; nt < 8; nt++)
                    mma_f16(acc[mt][nt], a, bf[nt]);
            }
        }
        __syncthreads();
    }
    // segmented max: 4 passes of 32 rows (dst-sorted); smem reuse
    float* sacc = (float*)sh;
#pragma unroll
    for (int pass = 0; pass < 4; pass++) {
        if (wm == pass) {
#pragma unroll
            for (int mt = 0; mt < 2; mt++) {
#pragma unroll
                for (int half = 0; half < 2; half++) {
                    int rl = mt * 16 + gid + half * 8;   // 0..31
#pragma unroll
                    for (int nt = 0; nt < 8; nt++) {
                        int col = wn * 64 + nt * 8 + tig * 2;
                        sacc[rl * 132 + col]     = acc[mt][nt][half * 2 + 0];
                        sacc[rl * 132 + col + 1] = acc[mt][nt][half * 2 + 1];
                    }
                }
            }
        }
        __syncthreads();
        {
            int col = tid & 127;
            int rh = tid >> 7;                  // 0..1
            int r0 = rh * 16, r1 = r0 + 16;
            int base = pass * 32;
            int cur = sd[base + r0];
            float m = sacc[r0 * 132 + col];
            for (int r = r0 + 1; r < r1; r++) {
                int d = sd[base + r];
                float v = sacc[r * 132 + col];
                if (d != cur) {
                    red_max_enc(&Mout[(long long)cur * 128 + col], m);
                    cur = d;
                    m = v;
                } else {
                    m = fmaxf(m, v);
                }
            }
            red_max_enc(&Mout[(long long)cur * 128 + col], m);
        }
        __syncthreads();
    }
}

// ---------------- fused per-layer kernel: edgeconv tiles + P-GEMM tiles in one launch ----------------
__global__ __launch_bounds__(256) void edge_fused(
    const unsigned* __restrict__ u16, const unsigned* __restrict__ b16,
    const unsigned* __restrict__ Whg,
    const int* __restrict__ ssrc, const int* __restrict__ sdstv,
    unsigned* __restrict__ Mout, int E, int lc2, int eb,
    const float* __restrict__ A, const float* __restrict__ B, float* __restrict__ P,
    int M, int K, const float* __restrict__ ta, const float* __restrict__ tb, int mbx)
{
    __shared__ unsigned buf[128 * 20 + 16 * 136];   // 4736 u32; gemm needs 1280+1152
    __shared__ int ssA[128], sdA[128];
    if ((int)blockIdx.x < eb) {
        edgeconv_body(u16, b16, Whg, ssrc, sdstv, Mout, E, lc2, blockIdx.x, buf, ssA, sdA);
    } else {
        int b = blockIdx.x - eb;
        gemm_tile_body(A, B, P, nullptr, M, K, 128, 1, 0, ta, tb, nullptr,
                       b % mbx, b / mbx, buf, buf + 64 * 20);
    }
}

// ---------------- GCN aggregation: CSR gather over fp16 rows, 4-way unroll; optional u16 emit ----------------
__global__ __launch_bounds__(256) void gcn_gather(
    const unsigned* __restrict__ h16, const int* __restrict__ ssrc,
    const float* __restrict__ ecoef, const int* __restrict__ start,
    const float* __restrict__ dinv, const float* __restrict__ bias,
    float* __restrict__ out, int N, int lc,
    const float* __restrict__ a2u, unsigned* __restrict__ u16)
{
    int node = blockIdx.x * 8 + (threadIdx.x >> 5);
    int lane = threadIdx.x & 31;
    if (node >= N) return;
    int groups = 1 << (lc - 7);          // 1 (128 cols) or 2 (256 cols)
    int rowlen = 1 << (lc - 1);          // u32 per row
    float di = dinv[node];
    float di2 = di * di;
    float4 acc[2];
    const unsigned* self = &h16[(long long)node * rowlen];
#pragma unroll
    for (int j = 0; j < 2; j++) {
        if (j < groups) {
            uint2 hv = *(const uint2*)&self[j * 64 + lane * 2];
            float2 f0 = __half22float2(*(__half2*)&hv.x);
            float2 f1 = __half22float2(*(__half2*)&hv.y);
            float4 bv = *(const float4*)&bias[j * 128 + lane * 4];
            acc[j].x = bv.x + di2 * f0.x;
            acc[j].y = bv.y + di2 * f0.y;
            acc[j].z = bv.z + di2 * f1.x;
            acc[j].w = bv.w + di2 * f1.y;
        }
    }
    int s0 = start[node], s1 = start[node + 1];
    for (int base = s0; base < s1; base += 32) {
        int e = base + lane;
        int sidx = 0; float cf = 0.f;
        if (e < s1) { sidx = ssrc[e]; cf = ecoef[e]; }
        int cnt = s1 - base; if (cnt > 32) cnt = 32;
        int j = 0;
        for (; j + 4 <= cnt; j += 4) {
            int sa = __shfl_sync(0xffffffffu, sidx, j);
            int sb = __shfl_sync(0xffffffffu, sidx, j + 1);
            int sc = __shfl_sync(0xffffffffu, sidx, j + 2);
            int sdd = __shfl_sync(0xffffffffu, sidx, j + 3);
            float ca = __shfl_sync(0xffffffffu, cf, j);
            float cb = __shfl_sync(0xffffffffu, cf, j + 1);
            float cc = __shfl_sync(0xffffffffu, cf, j + 2);
            float cd = __shfl_sync(0xffffffffu, cf, j + 3);
            const unsigned* ra = &h16[(long long)sa * rowlen];
            const unsigned* rb = &h16[(long long)sb * rowlen];
            const unsigned* rc = &h16[(long long)sc * rowlen];
            const unsigned* rd = &h16[(long long)sdd * rowlen];
#pragma unroll
            for (int g = 0; g < 2; g++) {
                if (g < groups) {
                    int off = g * 64 + lane * 2;
                    uint2 ha = *(const uint2*)&ra[off];
                    uint2 hb = *(const uint2*)&rb[off];
                    uint2 hc = *(const uint2*)&rc[off];
                    uint2 hd = *(const uint2*)&rd[off];
                    float2 a0 = __half22float2(*(__half2*)&ha.x);
                    float2 a1 = __half22float2(*(__half2*)&ha.y);
                    float2 b0 = __half22float2(*(__half2*)&hb.x);
                    float2 b1 = __half22float2(*(__half2*)&hb.y);
                    float2 c0 = __half22float2(*(__half2*)&hc.x);
                    float2 c1 = __half22float2(*(__half2*)&hc.y);
                    float2 d0 = __half22float2(*(__half2*)&hd.x);
                    float2 d1 = __half22float2(*(__half2*)&hd.y);
                    acc[g].x += ca * a0.x + cb * b0.x + cc * c0.x + cd * d0.x;
                    acc[g].y += ca * a0.y + cb * b0.y + cc * c0.y + cd * d0.y;
                    acc[g].z += ca * a1.x + cb * b1.x + cc * c1.x + cd * d1.x;
                    acc[g].w += ca * a1.y + cb * b1.y + cc * c1.y + cd * d1.y;
                }
            }
        }
        for (; j < cnt; j++) {
            int s = __shfl_sync(0xffffffffu, sidx, j);
            float coef = __shfl_sync(0xffffffffu, cf, j);
            const unsigned* hr = &h16[(long long)s * rowlen];
#pragma unroll
            for (int g = 0; g < 2; g++) {
                if (g < groups) {
                    uint2 hv = *(const uint2*)&hr[g * 64 + lane * 2];
                    float2 f0 = __half22float2(*(__half2*)&hv.x);
                    float2 f1 = __half22float2(*(__half2*)&hv.y);
                    acc[g].x += coef * f0.x;
                    acc[g].y += coef * f0.y;
                    acc[g].z += coef * f1.x;
                    acc[g].w += coef * f1.y;
                }
            }
        }
    }
#pragma unroll
    for (int j = 0; j < 2; j++) {
        if (j < groups) {
            int col = j * 128 + lane * 4;
            *(float4*)&out[((long long)node << lc) + col] = acc[j];
            if (a2u) {
                float4 a4 = *(const float4*)&a2u[col];
                uint2 pk;
                pk.x = pack_h2(a4.x * acc[j].x, a4.y * acc[j].y);
                pk.y = pack_h2(a4.z * acc[j].z, a4.w * acc[j].w);
                *(uint2*)&u16[((long long)node << (lc - 1)) + j * 64 + lane * 2] = pk;
            }
        }
    }
}

// ---------------- EdgeConv combine (+ optional fused u16 emit for next layer); resets M ----------------
__global__ void combine_kernel(const float* __restrict__ P, unsigned* __restrict__ Mv,
                               const int* __restrict__ indeg, float* __restrict__ out, int N,
                               const float* __restrict__ a2u, unsigned* __restrict__ u16)
{
    int idx4 = blockIdx.x * 256 + threadIdx.x;
    if (idx4 >= N * 32) return;
    int i = idx4 >> 5;
    int colbase = (idx4 & 31) * 4;
    uint4 kv = *(uint4*)&Mv[idx4 * 4];
    float4 pv = *(const float4*)&P[idx4 * 4];
    float4 o = make_float4(0.f, 0.f, 0.f, 0.f);
    if (indeg[i] > 0) {
        unsigned u0 = (kv.x & 0x80000000u) ? (kv.x & 0x7fffffffu) : ~kv.x;
        unsigned u1 = (kv.y & 0x80000000u) ? (kv.y & 0x7fffffffu) : ~kv.y;
        unsigned u2 = (kv.z & 0x80000000u) ? (kv.z & 0x7fffffffu) : ~kv.z;
        unsigned u3 = (kv.w & 0x80000000u) ? (kv.w & 0x7fffffffu) : ~kv.w;
        o.x = pv.x + __uint_as_float(u0);
        o.y = pv.y + __uint_as_float(u1);
        o.z = pv.z + __uint_as_float(u2);
        o.w = pv.w + __uint_as_float(u3);
    }
    *(uint4*)&Mv[idx4 * 4] = make_uint4(0u, 0u, 0u, 0u);   // re-zero for next layer
    *(float4*)&out[idx4 * 4] = o;
    if (a2u) {
        float4 a4 = *(const float4*)&a2u[colbase];
        uint2 pk;
        pk.x = pack_h2(a4.x * o.x, a4.y * o.y);
        pk.y = pack_h2(a4.z * o.z, a4.w * o.w);
        *(uint2*)&u16[(i << 6) + (idx4 & 31) * 2] = pk;
    }
}

// ---------------- final: combine last EdgeConv + FC in one pass (warp per node) ----------------
__global__ void combine_fc(const float* __restrict__ P, const unsigned* __restrict__ Mv,
                           const int* __restrict__ indeg,
                           const float* __restrict__ W, const float* __restrict__ b,
                           float* __restrict__ out, int N)
{
    int node = blockIdx.x * 8 + (threadIdx.x >> 5);
    int lane = threadIdx.x & 31;
    if (node >= N) return;
    uint4 kv = *(const uint4*)&Mv[node * 128 + lane * 4];
    float4 pv = *(const float4*)&P[node * 128 + lane * 4];
    float4 o = make_float4(0.f, 0.f, 0.f, 0.f);
    if (indeg[node] > 0) {
        unsigned u0 = (kv.x & 0x80000000u) ? (kv.x & 0x7fffffffu) : ~kv.x;
        unsigned u1 = (kv.y & 0x80000000u) ? (kv.y & 0x7fffffffu) : ~kv.y;
        unsigned u2 = (kv.z & 0x80000000u) ? (kv.z & 0x7fffffffu) : ~kv.z;
        unsigned u3 = (kv.w & 0x80000000u) ? (kv.w & 0x7fffffffu) : ~kv.w;
        o.x = pv.x + __uint_as_float(u0);
        o.y = pv.y + __uint_as_float(u1);
        o.z = pv.z + __uint_as_float(u2);
        o.w = pv.w + __uint_as_float(u3);
    }
    float4 w = *(const float4*)&W[lane * 4];
    float s = o.x * w.x + o.y * w.y + o.z * w.z + o.w * w.w;
#pragma unroll
    for (int off = 16; off; off >>= 1) s += __shfl_down_sync(0xffffffffu, s, off);
    if (lane == 0) out[node] = s + b[0];
}

// ---------------- launch ----------------
extern "C" void kernel_launch(void* const* d_in, const int* in_sizes, int n_in,
                              void* d_out, int out_size)
{
    const float* x   = (const float*)d_in[0];
    const int*   ei  = (const int*)d_in[1];
    const float* Wm  = (const float*)d_in[2];
    const float* bm  = (const float*)d_in[3];
    const float* Wc  = (const float*)d_in[4];
    const float* bc  = (const float*)d_in[5];
    const float* Wg1 = (const float*)d_in[6];
    const float* bg1 = (const float*)d_in[7];
    const float* Wg2 = (const float*)d_in[8];
    const float* bg2 = (const float*)d_in[9];
    const float* Wg3 = (const float*)d_in[10];
    const float* bg3 = (const float*)d_in[11];
    const float* e1g = (const float*)d_in[12];
    const float* e1b = (const float*)d_in[13];
    const float* e1m = (const float*)d_in[14];
    const float* e1v = (const float*)d_in[15];
    const float* e1W = (const float*)d_in[16];
    const float* e2g = (const float*)d_in[17];
    const float* e2b = (const float*)d_in[18];
    const float* e2m = (const float*)d_in[19];
    const float* e2v = (const float*)d_in[20];
    const float* e2W = (const float*)d_in[21];
    const float* e3g = (const float*)d_in[22];
    const float* e3b = (const float*)d_in[23];
    const float* e3m = (const float*)d_in[24];
    const float* e3v = (const float*)d_in[25];
    const float* e3W = (const float*)d_in[26];
    const float* Wfc = (const float*)d_in[27];
    const float* bfc = (const float*)d_in[28];

    int N = in_sizes[0] / 512;
    int E = in_sizes[1] / 2;
    const int* src = ei;
    const int* dst = ei + E;

    float *x0, *gA, *gB, *P, *dinv, *bna, *bnb, *ecoef;
    unsigned *Mx, *u16p, *whp, *bhp, *h16;
    int *indeg, *startp, *cnt, *ssrc, *sdst;
    cudaGetSymbolAddress((void**)&x0,    d_x0);
    cudaGetSymbolAddress((void**)&h16,   d_h16);
    cudaGetSymbolAddress((void**)&gA,    d_gA);
    cudaGetSymbolAddress((void**)&gB,    d_gB);
    cudaGetSymbolAddress((void**)&P,     d_P);
    cudaGetSymbolAddress((void**)&Mx,    d_Mx);
    cudaGetSymbolAddress((void**)&u16p,  d_u16);
    cudaGetSymbolAddress((void**)&whp,   d_wh);
    cudaGetSymbolAddress((void**)&bhp,   d_bh);
    cudaGetSymbolAddress((void**)&dinv,  d_dinv);
    cudaGetSymbolAddress((void**)&indeg, d_indeg);
    cudaGetSymbolAddress((void**)&startp,d_start);
    cudaGetSymbolAddress((void**)&cnt,   d_cnt);
    cudaGetSymbolAddress((void**)&ssrc,  d_ssrc);
    cudaGetSymbolAddress((void**)&sdst,  d_sdst);
    cudaGetSymbolAddress((void**)&ecoef, d_ecoef);
    cudaGetSymbolAddress((void**)&bna,   d_bna);
    cudaGetSymbolAddress((void**)&bnb,   d_bnb);

    dim3 t256(256);
    int mb = (N + 63) / 64;
    int M4 = (N + 3) / 4;
    int mb4 = (M4 + 63) / 64;
    int eb = (E + 127) / 128;

    // fused dual projection (also zeroes indeg)
    int pg = mb + mb4;
    int zg = (N + 255) / 256;
    proj_fused<<<(pg > zg ? pg : zg), t256>>>(x, Wc, bc, Wm, bm, x0, indeg, N, mb, mb4);

    // degrees + CSR sort by dst + launch-invariant prep
    count_indeg<<<(E + 255) / 256, t256>>>(dst, indeg, E);
    scan_kernel<<<1, 1024>>>(indeg, startp, cnt, dinv, N);
    prep_all<<<(N * 128 + 255) / 256, t256>>>(
        src, dst, startp, cnt, dinv, ssrc, sdst, ecoef, E,
        e1W + 256 * 128, e2W + 128 * 128, e3W + 128 * 128,
        e1g, e1b, e1m, e1v, e2g, e2b, e2m, e2v, e3g, e3b, e3m, e3v,
        Mx, whp, bhp, bna, bnb, N);

    // GCN1: x0[N,64] @ Wg1[64,128] -> h16; gather -> gA
    gemm_tc<<<dim3(mb, 2), t256>>>(x0, Wg1, nullptr, h16, N, 64, 128);
    gcn_gather<<<(N + 7) / 8, t256>>>(h16, ssrc, ecoef, startp, dinv, bg1, gA, N, 7,
                                      nullptr, nullptr);

    // GCN2
    gemm_tc<<<dim3(mb, 2), t256>>>(gA, Wg2, nullptr, h16, N, 128, 128);
    gcn_gather<<<(N + 7) / 8, t256>>>(h16, ssrc, ecoef, startp, dinv, bg2, gB, N, 7,
                                      nullptr, nullptr);

    // GCN3 (out 256); fused u16 emit for EdgeConv1
    gemm_tc<<<dim3(mb, 4), t256>>>(gB, Wg3, nullptr, h16, N, 128, 256);
    gcn_gather<<<(N + 7) / 8, t256>>>(h16, ssrc, ecoef, startp, dinv, bg3, gA, N, 8,
                                      bna + 256, u16p);

    // EdgeConv1 (fused edgeconv + P-GEMM): gA[N,256] -> gB[N,128]
    edge_fused<<<eb + mb * 2, t256>>>(u16p, bhp, whp, ssrc, sdst, Mx, E, 7, eb,
                                      gA, e1W, P, N, 256, bna, bnb, mb);
    combine_kernel<<<(N * 32 + 255) / 256, t256>>>(P, Mx, indeg, gB, N,
                                                   bna + 640, u16p);

    // EdgeConv2: gB[N,128] -> gA[N,128]
    edge_fused<<<eb + mb * 2, t256>>>(u16p, bhp + 128, whp + 16384, ssrc, sdst, Mx, E, 6, eb,
                                      gB, e2W, P, N, 128, bna + 512, bnb + 512, mb);
    combine_kernel<<<(N * 32 + 255) / 256, t256>>>(P, Mx, indeg, gA, N,
                                                   bna + 896, u16p);

    // EdgeConv3: gA[N,128] -> final combine fused with FC -> d_out [N,1]
    edge_fused<<<eb + mb * 2, t256>>>(u16p, bhp + 192, whp + 24576, ssrc, sdst, Mx, E, 6, eb,
                                      gA, e3W, P, N, 128, bna + 768, bnb + 768, mb);
    combine_fc<<<(N + 7) / 8, t256>>>(P, Mx, indeg, Wfc, bfc, (float*)d_out, N);
}

// round 16
// speedup vs baseline: 4.0328x; 1.0109x over previous
#include <cuda_runtime.h>
#include <cuda_fp16.h>
#include <math.h>

#define NCAP 20000
#define ECAP 320000

// ---------------- static scratch (no allocation allowed) ----------------
static __device__ float    d_x0  [NCAP * 64];    // reused as x16 (fp16-packed proj output)
static __device__ unsigned d_h16 [NCAP * 128];   // fp16-packed GCN linear outputs (g16)
static __device__ unsigned d_agg [NCAP * 64];    // fp16-packed aggregated rows
static __device__ float    d_gA  [NCAP * 256];
static __device__ float    d_gB  [NCAP * 256];
static __device__ float    d_P   [NCAP * 128];
static __device__ unsigned d_Mx  [NCAP * 128];
static __device__ unsigned d_u16 [NCAP * 128];   // per-layer fp16-packed scaled node rows
static __device__ unsigned d_wh  [32768];        // fp16-interleaved weights, ALL 3 edge layers
static __device__ unsigned d_bh  [256];          // fp16-packed BN offsets, ALL 3 edge layers
static __device__ float    d_dinv[NCAP];
static __device__ int      d_indeg[NCAP];
static __device__ int      d_start[NCAP + 1];
static __device__ int      d_cnt  [NCAP];
static __device__ int      d_ssrc [ECAP];
static __device__ int      d_sdst [ECAP];
static __device__ float    d_ecoef[ECAP];
static __device__ float    d_bna [1024];         // BN scale, layers at 0 / 512 / 768
static __device__ float    d_bnb [1024];         // BN offset

// ---------------- helpers ----------------
__device__ __forceinline__ unsigned pack_h2(float lo, float hi) {
    __half2 h = __floats2half2_rn(lo, hi);
    return *(unsigned*)&h;
}

__device__ __forceinline__ unsigned h2_q(unsigned us, unsigned ud, unsigned bb) {
    __half2 z = __floats2half2_rn(0.f, 0.f);
    __half2 r = __hmax2(__hadd2(__hsub2(*(__half2*)&us, *(__half2*)&ud), *(__half2*)&bb), z);
    return *(unsigned*)&r;
}

__device__ __forceinline__ void mma_f16(float* d, const unsigned* a, const unsigned* b) {
    asm volatile(
        "mma.sync.aligned.m16n8k16.row.col.f32.f16.f16.f32 "
        "{%0,%1,%2,%3}, {%4,%5,%6,%7}, {%8,%9}, {%0,%1,%2,%3};"
        : "+f"(d[0]), "+f"(d[1]), "+f"(d[2]), "+f"(d[3])
        : "r"(a[0]), "r"(a[1]), "r"(a[2]), "r"(a[3]), "r"(b[0]), "r"(b[1]));
}

__device__ __forceinline__ void red_max_enc(unsigned* p, float v) {
    unsigned u = __float_as_uint(v);
    unsigned key = (u & 0x80000000u) ? ~u : (u | 0x80000000u);
    asm volatile("red.global.max.u32 [%0], %1;" :: "l"(p), "r"(key) : "memory");
}

// ---------------- small kernels ----------------
__global__ void count_indeg(const int* __restrict__ dstv, int* __restrict__ indeg, int E) {
    int e = blockIdx.x * 256 + threadIdx.x;
    if (e < E) atomicAdd(&indeg[dstv[e]], 1);
}

// ---------------- exclusive scan over indeg -> start; also zeros cnt, computes dinv ----------------
__global__ __launch_bounds__(1024) void scan_kernel(const int* __restrict__ indeg,
                                                    int* __restrict__ start,
                                                    int* __restrict__ cnt,
                                                    float* __restrict__ dinv, int N) {
    __shared__ int wsum[32];
    int t = threadIdx.x;
    int chunk = (N + 1023) / 1024;
    int lo = t * chunk;
    int hi = lo + chunk; if (hi > N) hi = N; if (lo > N) lo = N;
    int s = 0;
    for (int i = lo; i < hi; i++) s += indeg[i];
    int lane = t & 31, w = t >> 5;
    int v = s;
#pragma unroll
    for (int o = 1; o < 32; o <<= 1) {
        int u = __shfl_up_sync(0xffffffffu, v, o);
        if (lane >= o) v += u;
    }
    if (lane == 31) wsum[w] = v;
    __syncthreads();
    if (w == 0) {
        int x = wsum[lane];
#pragma unroll
        for (int o = 1; o < 32; o <<= 1) {
            int u = __shfl_up_sync(0xffffffffu, x, o);
            if (lane >= o) x += u;
        }
        wsum[lane] = x;
    }
    __syncthreads();
    int excl = (v - s) + (w > 0 ? wsum[w - 1] : 0);
    int run = excl;
    for (int i = lo; i < hi; i++) {
        start[i] = run;
        run += indeg[i];
        cnt[i] = 0;
        dinv[i] = rsqrtf((float)indeg[i] + 1.0f);
    }
    if (t == 1023) start[N] = run;
}

// ---------------- prep_all: edge scatter + Mx zero + packed fp16 weights/biases + BN coefs ----------------
__global__ void prep_all(
    const int* __restrict__ src, const int* __restrict__ dstv,
    const int* __restrict__ start, int* __restrict__ cnt, const float* __restrict__ dinv,
    int* __restrict__ ssrc, int* __restrict__ sdst, float* __restrict__ ecoef, int E,
    const float* __restrict__ w1, const float* __restrict__ w2, const float* __restrict__ w3,
    const float* __restrict__ g1, const float* __restrict__ b1,
    const float* __restrict__ m1, const float* __restrict__ v1,
    const float* __restrict__ g2, const float* __restrict__ b2,
    const float* __restrict__ m2, const float* __restrict__ v2,
    const float* __restrict__ g3, const float* __restrict__ b3,
    const float* __restrict__ m3, const float* __restrict__ v3,
    unsigned* __restrict__ Mx, unsigned* __restrict__ wh, unsigned* __restrict__ bh,
    float* __restrict__ bna, float* __restrict__ bnb, int N)
{
    int idx = blockIdx.x * 256 + threadIdx.x;
    if (idx < E) {
        int s = src[idx], d = dstv[idx];
        int p = start[d] + atomicAdd(&cnt[d], 1);
        ssrc[p] = s;
        sdst[p] = d;
        ecoef[p] = dinv[s] * dinv[d];
    }
    if (idx < N * 128) Mx[idx] = 0u;
    if (idx < 32768) {
        const float* W; int k2n;
        if (idx < 16384)      { W = w1; k2n = idx; }
        else if (idx < 24576) { W = w2; k2n = idx - 16384; }
        else                  { W = w3; k2n = idx - 24576; }
        int k2 = k2n >> 7, n = k2n & 127;
        wh[idx] = pack_h2(W[(2 * k2) * 128 + n], W[(2 * k2 + 1) * 128 + n]);
    }
    if (idx < 1024) {
        const float *g, *be, *me, *va; int i;
        if (idx < 512)      { g = g1; be = b1; me = m1; va = v1; i = idx; }
        else if (idx < 768) { g = g2; be = b2; me = m2; va = v2; i = idx - 512; }
        else                { g = g3; be = b3; me = m3; va = v3; i = idx - 768; }
        float a = g[i] * rsqrtf(va[i] + 1e-5f);
        bna[idx] = a;
        bnb[idx] = be[i] - me[i] * a;
    }
    if (idx < 256) {
        const float *g, *be, *me, *va; int c;
        if (idx < 128)      { g = g1; be = b1; me = m1; va = v1; c = 256 + 2 * idx; }
        else if (idx < 192) { g = g2; be = b2; me = m2; va = v2; c = 128 + 2 * (idx - 128); }
        else                { g = g3; be = b3; me = m3; va = v3; c = 128 + 2 * (idx - 192); }
        float a0 = g[c] * rsqrtf(va[c] + 1e-5f);
        float a1 = g[c + 1] * rsqrtf(va[c + 1] + 1e-5f);
        bh[idx] = pack_h2(be[c] - me[c] * a0, be[c + 1] - me[c + 1] * a1);
    }
}

// ---------------- FP16 GEMM tile body (m16n8k16) ----------------
// A-operand: f32 (A, optional BN-ReLU via ta/tb) OR fp16-packed (Ah).
// Outputs: C f32 (opt) and/or outh fp16-packed (opt, scaled by a2u if given). Bias optional.
// skip4: suppress stores on rows where gr % 4 == 0. rmul: row stride multiplier.
__device__ __forceinline__ void gemm_tile_body(
    const float* __restrict__ A, const unsigned* __restrict__ Ah,
    const float* __restrict__ B,
    float* __restrict__ C, unsigned* __restrict__ outh,
    int M, int K, int Ncols, int rmul, int skip4,
    const float* __restrict__ ta, const float* __restrict__ tb,
    const float* __restrict__ bias, const float* __restrict__ a2u,
    int bx, int by, unsigned* As, unsigned* Bs)
{
    int tid = threadIdx.x;
    int lane = tid & 31, warp = tid >> 5;
    int wm = warp & 3, wn = warp >> 2;
    int gid = lane >> 2, tig = lane & 3;
    int row0 = bx * 64;
    int col0 = by * 64;
    float acc[4][4] = {};
    for (int k0 = 0; k0 < K; k0 += 32) {
#pragma unroll
        for (int i = 0; i < 2; i++) {
            int lin = tid + i * 256;          // 0..511
            int r = lin >> 3;                 // 0..63
            int q2 = (lin & 7) * 2;           // half2 slot
            int gr = row0 + r;
            uint2 pk = make_uint2(0u, 0u);
            if (gr < M) {
                if (Ah) {
                    pk = *(const uint2*)&Ah[(long long)gr * rmul * (K >> 1) + (k0 >> 1) + q2];
                } else {
                    float4 v = *(const float4*)&A[(long long)gr * rmul * K + k0 + q2 * 2];
                    if (ta) {
                        float4 a4 = *(const float4*)&ta[k0 + q2 * 2];
                        float4 b4 = *(const float4*)&tb[k0 + q2 * 2];
                        v.x = fmaxf(a4.x * v.x + b4.x, 0.f);
                        v.y = fmaxf(a4.y * v.y + b4.y, 0.f);
                        v.z = fmaxf(a4.z * v.z + b4.z, 0.f);
                        v.w = fmaxf(a4.w * v.w + b4.w, 0.f);
                    }
                    pk = make_uint2(pack_h2(v.x, v.y), pack_h2(v.z, v.w));
                }
            }
            *(uint2*)&As[r * 20 + q2] = pk;
        }
#pragma unroll
        for (int i = 0; i < 2; i++) {
            int lin = tid + i * 256;          // 0..511
            int k2 = lin >> 5;                // 0..15 (half2-k index)
            int n2 = (lin & 31) * 2;          // 2 columns per thread
            const float* w0 = &B[(long long)(k0 + 2 * k2) * Ncols + col0 + n2];
            const float* w1 = &B[(long long)(k0 + 2 * k2 + 1) * Ncols + col0 + n2];
            float2 wa = *(const float2*)w0;
            float2 wb = *(const float2*)w1;
            *(uint2*)&Bs[k2 * 72 + n2] =
                make_uint2(pack_h2(wa.x, wb.x), pack_h2(wa.y, wb.y));
        }
        __syncthreads();
#pragma unroll
        for (int s = 0; s < 2; s++) {
            int ac = s * 8 + tig;
            unsigned a[4];
            int ar = wm * 16 + gid;
            a[0] = As[ar * 20 + ac];
            a[1] = As[(ar + 8) * 20 + ac];
            a[2] = As[ar * 20 + ac + 4];
            a[3] = As[(ar + 8) * 20 + ac + 4];
#pragma unroll
            for (int nt = 0; nt < 4; nt++) {
                unsigned b[2];
                int bc = wn * 32 + nt * 8 + gid;
                b[0] = Bs[(s * 8 + tig) * 72 + bc];
                b[1] = Bs[(s * 8 + tig + 4) * 72 + bc];
                mma_f16(acc[nt], a, b);
            }
        }
        __syncthreads();
    }
#pragma unroll
    for (int half = 0; half < 2; half++) {
        int gr = row0 + wm * 16 + gid + half * 8;
        if (gr < M && !(skip4 && (gr & 3) == 0)) {
            long long prow = (long long)gr * rmul;
#pragma unroll
            for (int nt = 0; nt < 4; nt++) {
                int col = col0 + wn * 32 + nt * 8 + tig * 2;
                float v0 = acc[nt][half * 2 + 0];
                float v1 = acc[nt][half * 2 + 1];
                if (bias) { v0 += bias[col]; v1 += bias[col + 1]; }
                if (C) {
                    C[prow * Ncols + col]     = v0;
                    C[prow * Ncols + col + 1] = v1;
                }
                if (outh) {
                    float s0 = v0, s1 = v1;
                    if (a2u) { s0 *= a2u[col]; s1 *= a2u[col + 1]; }
                    outh[prow * (Ncols >> 1) + (col >> 1)] = pack_h2(s0, s1);
                }
            }
        }
    }
}

// ---------------- standalone GEMM kernel ----------------
__global__ __launch_bounds__(256) void gemm_tc(
    const float* __restrict__ A, const unsigned* __restrict__ Ah,
    const float* __restrict__ B,
    float* __restrict__ C, unsigned* __restrict__ outh,
    int M, int K, int Ncols, const float* __restrict__ bias,
    const float* __restrict__ a2u)
{
    __shared__ unsigned As[64 * 20];
    __shared__ unsigned Bs[16 * 72];
    gemm_tile_body(A, Ah, B, C, outh, M, K, Ncols, 1, 0, nullptr, nullptr, bias, a2u,
                   blockIdx.x, blockIdx.y, As, Bs);
}

// ---------------- fused dual projection (fp16-packed output) + indeg zero ----------------
__global__ __launch_bounds__(256) void proj_fused(
    const float* __restrict__ x,
    const float* __restrict__ Wc, const float* __restrict__ bc,
    const float* __restrict__ Wm, const float* __restrict__ bm,
    unsigned* __restrict__ x16, int* __restrict__ indeg, int N, int mb, int mb4)
{
    int gidx = blockIdx.x * 256 + threadIdx.x;
    if (gidx < N) indeg[gidx] = 0;
    __shared__ unsigned As[64 * 20];
    __shared__ unsigned Bs[16 * 72];
    if ((int)blockIdx.x < mb) {
        gemm_tile_body(x, nullptr, Wc, nullptr, x16, N, 512, 64, 1, 1,
                       nullptr, nullptr, bc, nullptr, blockIdx.x, 0, As, Bs);
    } else if ((int)blockIdx.x < mb + mb4) {
        gemm_tile_body(x, nullptr, Wm, nullptr, x16, (N + 3) / 4, 512, 64, 4, 0,
                       nullptr, nullptr, bm, nullptr, blockIdx.x - mb, 0, As, Bs);
    }
}

// ---------------- GCN aggregation FIRST (pre-GEMM): agg = dinv^2*x_i + sum coef*x_s ----------------
// fp16-packed in/out; R = u32 per row (32 or 64).
__global__ __launch_bounds__(256) void gcn_agg(
    const unsigned* __restrict__ in16, const int* __restrict__ ssrc,
    const float* __restrict__ ecoef, const int* __restrict__ start,
    const float* __restrict__ dinv, unsigned* __restrict__ out16,
    int N, int R)
{
    int node = blockIdx.x * 8 + (threadIdx.x >> 5);
    int lane = threadIdx.x & 31;
    if (node >= N) return;
    float di = dinv[node];
    float di2 = di * di;
    int s0 = start[node], s1 = start[node + 1];
    if (R == 64) {
        uint2 hv = *(const uint2*)&in16[(long long)node * 64 + lane * 2];
        float2 f0 = __half22float2(*(__half2*)&hv.x);
        float2 f1 = __half22float2(*(__half2*)&hv.y);
        float4 acc = make_float4(di2 * f0.x, di2 * f0.y, di2 * f1.x, di2 * f1.y);
        for (int base = s0; base < s1; base += 32) {
            int e = base + lane;
            int sidx = 0; float cf = 0.f;
            if (e < s1) { sidx = ssrc[e]; cf = ecoef[e]; }
            int cnt = s1 - base; if (cnt > 32) cnt = 32;
            int j = 0;
            for (; j + 4 <= cnt; j += 4) {
                int sa = __shfl_sync(0xffffffffu, sidx, j);
                int sb = __shfl_sync(0xffffffffu, sidx, j + 1);
                int sc = __shfl_sync(0xffffffffu, sidx, j + 2);
                int sdd = __shfl_sync(0xffffffffu, sidx, j + 3);
                float ca = __shfl_sync(0xffffffffu, cf, j);
                float cb = __shfl_sync(0xffffffffu, cf, j + 1);
                float cc = __shfl_sync(0xffffffffu, cf, j + 2);
                float cd = __shfl_sync(0xffffffffu, cf, j + 3);
                uint2 ha = *(const uint2*)&in16[(long long)sa * 64 + lane * 2];
                uint2 hb = *(const uint2*)&in16[(long long)sb * 64 + lane * 2];
                uint2 hc = *(const uint2*)&in16[(long long)sc * 64 + lane * 2];
                uint2 hd = *(const uint2*)&in16[(long long)sdd * 64 + lane * 2];
                float2 a0 = __half22float2(*(__half2*)&ha.x);
                float2 a1 = __half22float2(*(__half2*)&ha.y);
                float2 b0 = __half22float2(*(__half2*)&hb.x);
                float2 b1 = __half22float2(*(__half2*)&hb.y);
                float2 c0 = __half22float2(*(__half2*)&hc.x);
                float2 c1 = __half22float2(*(__half2*)&hc.y);
                float2 d0 = __half22float2(*(__half2*)&hd.x);
                float2 d1 = __half22float2(*(__half2*)&hd.y);
                acc.x += ca * a0.x + cb * b0.x + cc * c0.x + cd * d0.x;
                acc.y += ca * a0.y + cb * b0.y + cc * c0.y + cd * d0.y;
                acc.z += ca * a1.x + cb * b1.x + cc * c1.x + cd * d1.x;
                acc.w += ca * a1.y + cb * b1.y + cc * c1.y + cd * d1.y;
            }
            for (; j < cnt; j++) {
                int s = __shfl_sync(0xffffffffu, sidx, j);
                float coef = __shfl_sync(0xffffffffu, cf, j);
                uint2 hv2 = *(const uint2*)&in16[(long long)s * 64 + lane * 2];
                float2 f2 = __half22float2(*(__half2*)&hv2.x);
                float2 f3 = __half22float2(*(__half2*)&hv2.y);
                acc.x += coef * f2.x;
                acc.y += coef * f2.y;
                acc.z += coef * f3.x;
                acc.w += coef * f3.y;
            }
        }
        uint2 pk;
        pk.x = pack_h2(acc.x, acc.y);
        pk.y = pack_h2(acc.z, acc.w);
        *(uint2*)&out16[(long long)node * 64 + lane * 2] = pk;
    } else {  // R == 32
        unsigned hv = in16[(long long)node * 32 + lane];
        float2 f0 = __half22float2(*(__half2*)&hv);
        float2 acc = make_float2(di2 * f0.x, di2 * f0.y);
        for (int base = s0; base < s1; base += 32) {
            int e = base + lane;
            int sidx = 0; float cf = 0.f;
            if (e < s1) { sidx = ssrc[e]; cf = ecoef[e]; }
            int cnt = s1 - base; if (cnt > 32) cnt = 32;
            int j = 0;
            for (; j + 4 <= cnt; j += 4) {
                int sa = __shfl_sync(0xffffffffu, sidx, j);
                int sb = __shfl_sync(0xffffffffu, sidx, j + 1);
                int sc = __shfl_sync(0xffffffffu, sidx, j + 2);
                int sdd = __shfl_sync(0xffffffffu, sidx, j + 3);
                float ca = __shfl_sync(0xffffffffu, cf, j);
                float cb = __shfl_sync(0xffffffffu, cf, j + 1);
                float cc = __shfl_sync(0xffffffffu, cf, j + 2);
                float cd = __shfl_sync(0xffffffffu, cf, j + 3);
                unsigned ha = in16[(long long)sa * 32 + lane];
                unsigned hb = in16[(long long)sb * 32 + lane];
                unsigned hc = in16[(long long)sc * 32 + lane];
                unsigned hd = in16[(long long)sdd * 32 + lane];
                float2 a0 = __half22float2(*(__half2*)&ha);
                float2 b0 = __half22float2(*(__half2*)&hb);
                float2 c0 = __half22float2(*(__half2*)&hc);
                float2 d0 = __half22float2(*(__half2*)&hd);
                acc.x += ca * a0.x + cb * b0.x + cc * c0.x + cd * d0.x;
                acc.y += ca * a0.y + cb * b0.y + cc * c0.y + cd * d0.y;
            }
            for (; j < cnt; j++) {
                int s = __shfl_sync(0xffffffffu, sidx, j);
                float coef = __shfl_sync(0xffffffffu, cf, j);
                unsigned hv2 = in16[(long long)s * 32 + lane];
                float2 f2 = __half22float2(*(__half2*)&hv2);
                acc.x += coef * f2.x;
                acc.y += coef * f2.y;
            }
        }
        out16[(long long)node * 32 + lane] = pack_h2(acc.x, acc.y);
    }
}

// ---------------- EdgeConv tile body ----------------
__device__ __forceinline__ void edgeconv_body(
    const unsigned* __restrict__ u16, const unsigned* __restrict__ b16,
    const unsigned* __restrict__ Whg,
    const int* __restrict__ ssrc, const int* __restrict__ sdstv,
    unsigned* __restrict__ Mout, int E, int lc2,
    int bid, unsigned* sh, int* ss, int* sd)
{
    unsigned* qh = sh;                 // [edge][k2] stride 20
    unsigned* wh = sh + 128 * 20;      // [k2][n]  stride 136
    int tid = threadIdx.x;
    int e0 = bid * 128;
    if (tid < 128) {
        int e = e0 + tid;
        if (e >= E) e = E - 1;
        ss[tid] = ssrc[e];
        sd[tid] = sdstv[e];
    }
    __syncthreads();
    int lane = tid & 31, warp = tid >> 5;
    int wm = warp & 3, wn = warp >> 2;
    int gid = lane >> 2, tig = lane & 3;
    int C2 = 1 << lc2;
    float acc[2][8][4] = {};
    for (int k20 = 0; k20 < C2; k20 += 16) {
#pragma unroll
        for (int i = 0; i < 2; i++) {
            int lin = tid + i * 256;          // 0..511
            int e = lin >> 2;                 // 0..127
            int q4 = (lin & 3) * 4;           // half2 offset
            int k2g = k20 + q4;
            uint4 us = *(const uint4*)&u16[(ss[e] << lc2) + k2g];
            uint4 ud = *(const uint4*)&u16[(sd[e] << lc2) + k2g];
            uint4 bb = *(const uint4*)&b16[k2g];
            uint4 r;
            r.x = h2_q(us.x, ud.x, bb.x);
            r.y = h2_q(us.y, ud.y, bb.y);
            r.z = h2_q(us.z, ud.z, bb.z);
            r.w = h2_q(us.w, ud.w, bb.w);
            *(uint4*)&qh[e * 20 + q4] = r;
        }
#pragma unroll
        for (int i = 0; i < 2; i++) {
            int lin = tid + i * 256;
            int k2 = lin >> 5;                // 0..15
            int n4 = (lin & 31) * 4;
            *(uint4*)&wh[k2 * 136 + n4] =
                *(const uint4*)&Whg[(k20 + k2) * 128 + n4];
        }
        __syncthreads();
#pragma unroll
        for (int s = 0; s < 2; s++) {
            unsigned bf[8][2];
#pragma unroll
            for (int nt = 0; nt < 8; nt++) {
                int bc = wn * 64 + nt * 8 + gid;
                bf[nt][0] = wh[(s * 8 + tig) * 136 + bc];
                bf[nt][1] = wh[(s * 8 + tig + 4) * 136 + bc];
            }
            int ac = s * 8 + tig;
#pragma unroll
            for (int mt = 0; mt < 2; mt++) {
                unsigned a[4];
                int ar = wm * 32 + mt * 16 + gid;
                a[0] = qh[ar * 20 + ac];
                a[1] = qh[(ar + 8) * 20 + ac];
                a[2] = qh[ar * 20 + ac + 4];
                a[3] = qh[(ar + 8) * 20 + ac + 4];
#pragma unroll
                for (int nt = 0; nt < 8; nt++)
                    mma_f16(acc[mt][nt], a, bf[nt]);
            }
        }
        __syncthreads();
    }
    // segmented max: 4 passes of 32 rows (dst-sorted); smem reuse
    float* sacc = (float*)sh;
#pragma unroll
    for (int pass = 0; pass < 4; pass++) {
        if (wm == pass) {
#pragma unroll
            for (int mt = 0; mt < 2; mt++) {
#pragma unroll
                for (int half = 0; half < 2; half++) {
                    int rl = mt * 16 + gid + half * 8;   // 0..31
#pragma unroll
                    for (int nt = 0; nt < 8; nt++) {
                        int col = wn * 64 + nt * 8 + tig * 2;
                        sacc[rl * 132 + col]     = acc[mt][nt][half * 2 + 0];
                        sacc[rl * 132 + col + 1] = acc[mt][nt][half * 2 + 1];
                    }
                }
            }
        }
        __syncthreads();
        {
            int col = tid & 127;
            int rh = tid >> 7;                  // 0..1
            int r0 = rh * 16, r1 = r0 + 16;
            int base = pass * 32;
            int cur = sd[base + r0];
            float m = sacc[r0 * 132 + col];
            for (int r = r0 + 1; r < r1; r++) {
                int d = sd[base + r];
                float v = sacc[r * 132 + col];
                if (d != cur) {
                    red_max_enc(&Mout[(long long)cur * 128 + col], m);
                    cur = d;
                    m = v;
                } else {
                    m = fmaxf(m, v);
                }
            }
            red_max_enc(&Mout[(long long)cur * 128 + col], m);
        }
        __syncthreads();
    }
}

// ---------------- fused per-layer kernel: edgeconv tiles + P-GEMM tiles in one launch ----------------
__global__ __launch_bounds__(256) void edge_fused(
    const unsigned* __restrict__ u16, const unsigned* __restrict__ b16,
    const unsigned* __restrict__ Whg,
    const int* __restrict__ ssrc, const int* __restrict__ sdstv,
    unsigned* __restrict__ Mout, int E, int lc2, int eb,
    const float* __restrict__ A, const float* __restrict__ B, float* __restrict__ P,
    int M, int K, const float* __restrict__ ta, const float* __restrict__ tb, int mbx)
{
    __shared__ unsigned buf[128 * 20 + 16 * 136];
    __shared__ int ssA[128], sdA[128];
    if ((int)blockIdx.x < eb) {
        edgeconv_body(u16, b16, Whg, ssrc, sdstv, Mout, E, lc2, blockIdx.x, buf, ssA, sdA);
    } else {
        int b = blockIdx.x - eb;
        gemm_tile_body(A, nullptr, B, P, nullptr, M, K, 128, 1, 0, ta, tb, nullptr, nullptr,
                       b % mbx, b / mbx, buf, buf + 64 * 20);
    }
}

// ---------------- EdgeConv combine (+ optional fused u16 emit for next layer); resets M ----------------
__global__ void combine_kernel(const float* __restrict__ P, unsigned* __restrict__ Mv,
                               const int* __restrict__ indeg, float* __restrict__ out, int N,
                               const float* __restrict__ a2u, unsigned* __restrict__ u16)
{
    int idx4 = blockIdx.x * 256 + threadIdx.x;
    if (idx4 >= N * 32) return;
    int i = idx4 >> 5;
    int colbase = (idx4 & 31) * 4;
    uint4 kv = *(uint4*)&Mv[idx4 * 4];
    float4 pv = *(const float4*)&P[idx4 * 4];
    float4 o = make_float4(0.f, 0.f, 0.f, 0.f);
    if (indeg[i] > 0) {
        unsigned u0 = (kv.x & 0x80000000u) ? (kv.x & 0x7fffffffu) : ~kv.x;
        unsigned u1 = (kv.y & 0x80000000u) ? (kv.y & 0x7fffffffu) : ~kv.y;
        unsigned u2 = (kv.z & 0x80000000u) ? (kv.z & 0x7fffffffu) : ~kv.z;
        unsigned u3 = (kv.w & 0x80000000u) ? (kv.w & 0x7fffffffu) : ~kv.w;
        o.x = pv.x + __uint_as_float(u0);
        o.y = pv.y + __uint_as_float(u1);
        o.z = pv.z + __uint_as_float(u2);
        o.w = pv.w + __uint_as_float(u3);
    }
    *(uint4*)&Mv[idx4 * 4] = make_uint4(0u, 0u, 0u, 0u);   // re-zero for next layer
    *(float4*)&out[idx4 * 4] = o;
    if (a2u) {
        float4 a4 = *(const float4*)&a2u[colbase];
        uint2 pk;
        pk.x = pack_h2(a4.x * o.x, a4.y * o.y);
        pk.y = pack_h2(a4.z * o.z, a4.w * o.w);
        *(uint2*)&u16[(i << 6) + (idx4 & 31) * 2] = pk;
    }
}

// ---------------- final: combine last EdgeConv + FC in one pass (warp per node) ----------------
__global__ void combine_fc(const float* __restrict__ P, const unsigned* __restrict__ Mv,
                           const int* __restrict__ indeg,
                           const float* __restrict__ W, const float* __restrict__ b,
                           float* __restrict__ out, int N)
{
    int node = blockIdx.x * 8 + (threadIdx.x >> 5);
    int lane = threadIdx.x & 31;
    if (node >= N) return;
    uint4 kv = *(const uint4*)&Mv[node * 128 + lane * 4];
    float4 pv = *(const float4*)&P[node * 128 + lane * 4];
    float4 o = make_float4(0.f, 0.f, 0.f, 0.f);
    if (indeg[node] > 0) {
        unsigned u0 = (kv.x & 0x80000000u) ? (kv.x & 0x7fffffffu) : ~kv.x;
        unsigned u1 = (kv.y & 0x80000000u) ? (kv.y & 0x7fffffffu) : ~kv.y;
        unsigned u2 = (kv.z & 0x80000000u) ? (kv.z & 0x7fffffffu) : ~kv.z;
        unsigned u3 = (kv.w & 0x80000000u) ? (kv.w & 0x7fffffffu) : ~kv.w;
        o.x = pv.x + __uint_as_float(u0);
        o.y = pv.y + __uint_as_float(u1);
        o.z = pv.z + __uint_as_float(u2);
        o.w = pv.w + __uint_as_float(u3);
    }
    float4 w = *(const float4*)&W[lane * 4];
    float s = o.x * w.x + o.y * w.y + o.z * w.z + o.w * w.w;
#pragma unroll
    for (int off = 16; off; off >>= 1) s += __shfl_down_sync(0xffffffffu, s, off);
    if (lane == 0) out[node] = s + b[0];
}

// ---------------- launch ----------------
extern "C" void kernel_launch(void* const* d_in, const int* in_sizes, int n_in,
                              void* d_out, int out_size)
{
    const float* x   = (const float*)d_in[0];
    const int*   ei  = (const int*)d_in[1];
    const float* Wm  = (const float*)d_in[2];
    const float* bm  = (const float*)d_in[3];
    const float* Wc  = (const float*)d_in[4];
    const float* bc  = (const float*)d_in[5];
    const float* Wg1 = (const float*)d_in[6];
    const float* bg1 = (const float*)d_in[7];
    const float* Wg2 = (const float*)d_in[8];
    const float* bg2 = (const float*)d_in[9];
    const float* Wg3 = (const float*)d_in[10];
    const float* bg3 = (const float*)d_in[11];
    const float* e1g = (const float*)d_in[12];
    const float* e1b = (const float*)d_in[13];
    const float* e1m = (const float*)d_in[14];
    const float* e1v = (const float*)d_in[15];
    const float* e1W = (const float*)d_in[16];
    const float* e2g = (const float*)d_in[17];
    const float* e2b = (const float*)d_in[18];
    const float* e2m = (const float*)d_in[19];
    const float* e2v = (const float*)d_in[20];
    const float* e2W = (const float*)d_in[21];
    const float* e3g = (const float*)d_in[22];
    const float* e3b = (const float*)d_in[23];
    const float* e3m = (const float*)d_in[24];
    const float* e3v = (const float*)d_in[25];
    const float* e3W = (const float*)d_in[26];
    const float* Wfc = (const float*)d_in[27];
    const float* bfc = (const float*)d_in[28];

    int N = in_sizes[0] / 512;
    int E = in_sizes[1] / 2;
    const int* src = ei;
    const int* dst = ei + E;

    float *gA, *gB, *P, *dinv, *bna, *bnb, *ecoef;
    unsigned *Mx, *u16p, *whp, *bhp, *g16, *agg16, *x16;
    int *indeg, *startp, *cnt, *ssrc, *sdst;
    cudaGetSymbolAddress((void**)&x16,   d_x0);
    cudaGetSymbolAddress((void**)&g16,   d_h16);
    cudaGetSymbolAddress((void**)&agg16, d_agg);
    cudaGetSymbolAddress((void**)&gA,    d_gA);
    cudaGetSymbolAddress((void**)&gB,    d_gB);
    cudaGetSymbolAddress((void**)&P,     d_P);
    cudaGetSymbolAddress((void**)&Mx,    d_Mx);
    cudaGetSymbolAddress((void**)&u16p,  d_u16);
    cudaGetSymbolAddress((void**)&whp,   d_wh);
    cudaGetSymbolAddress((void**)&bhp,   d_bh);
    cudaGetSymbolAddress((void**)&dinv,  d_dinv);
    cudaGetSymbolAddress((void**)&indeg, d_indeg);
    cudaGetSymbolAddress((void**)&startp,d_start);
    cudaGetSymbolAddress((void**)&cnt,   d_cnt);
    cudaGetSymbolAddress((void**)&ssrc,  d_ssrc);
    cudaGetSymbolAddress((void**)&sdst,  d_sdst);
    cudaGetSymbolAddress((void**)&ecoef, d_ecoef);
    cudaGetSymbolAddress((void**)&bna,   d_bna);
    cudaGetSymbolAddress((void**)&bnb,   d_bnb);

    dim3 t256(256);
    int mb = (N + 63) / 64;
    int M4 = (N + 3) / 4;
    int mb4 = (M4 + 63) / 64;
    int eb = (E + 127) / 128;

    // fused dual projection -> x16 fp16-packed (also zeroes indeg)
    int pg = mb + mb4;
    int zg = (N + 255) / 256;
    proj_fused<<<(pg > zg ? pg : zg), t256>>>(x, Wc, bc, Wm, bm, x16, indeg, N, mb, mb4);

    // degrees + CSR sort by dst + launch-invariant prep
    count_indeg<<<(E + 255) / 256, t256>>>(dst, indeg, E);
    scan_kernel<<<1, 1024>>>(indeg, startp, cnt, dinv, N);
    prep_all<<<(N * 128 + 255) / 256, t256>>>(
        src, dst, startp, cnt, dinv, ssrc, sdst, ecoef, E,
        e1W + 256 * 128, e2W + 128 * 128, e3W + 128 * 128,
        e1g, e1b, e1m, e1v, e2g, e2b, e2m, e2v, e3g, e3b, e3m, e3v,
        Mx, whp, bhp, bna, bnb, N);

    // GCN layers, aggregate-then-GEMM:  g_{l} = (A_hat g_{l-1}) W_l + b_l
    // GCN1: agg(x16, 64 cols) -> agg16; gemm -> g16 (128 cols, fp16)
    gcn_agg<<<(N + 7) / 8, t256>>>(x16, ssrc, ecoef, startp, dinv, agg16, N, 32);
    gemm_tc<<<dim3(mb, 2), t256>>>(nullptr, agg16, Wg1, nullptr, g16, N, 64, 128, bg1, nullptr);

    // GCN2
    gcn_agg<<<(N + 7) / 8, t256>>>(g16, ssrc, ecoef, startp, dinv, agg16, N, 64);
    gemm_tc<<<dim3(mb, 2), t256>>>(nullptr, agg16, Wg2, nullptr, g16, N, 128, 128, bg2, nullptr);

    // GCN3: agg -> agg16; gemm -> gA (f32, for EdgeConv1 P-GEMM) + u16 (a2-scaled fp16)
    gcn_agg<<<(N + 7) / 8, t256>>>(g16, ssrc, ecoef, startp, dinv, agg16, N, 64);
    gemm_tc<<<dim3(mb, 4), t256>>>(nullptr, agg16, Wg3, gA, u16p, N, 128, 256, bg3, bna + 256);

    // EdgeConv1 (fused edgeconv + P-GEMM): gA[N,256] -> gB[N,128]
    edge_fused<<<eb + mb * 2, t256>>>(u16p, bhp, whp, ssrc, sdst, Mx, E, 7, eb,
                                      gA, e1W, P, N, 256, bna, bnb, mb);
    combine_kernel<<<(N * 32 + 255) / 256, t256>>>(P, Mx, indeg, gB, N,
                                                   bna + 640, u16p);

    // EdgeConv2: gB[N,128] -> gA[N,128]
    edge_fused<<<eb + mb * 2, t256>>>(u16p, bhp + 128, whp + 16384, ssrc, sdst, Mx, E, 6, eb,
                                      gB, e2W, P, N, 128, bna + 512, bnb + 512, mb);
    combine_kernel<<<(N * 32 + 255) / 256, t256>>>(P, Mx, indeg, gA, N,
                                                   bna + 896, u16p);

    // EdgeConv3: gA[N,128] -> final combine fused with FC -> d_out [N,1]
    edge_fused<<<eb + mb * 2, t256>>>(u16p, bhp + 192, whp + 24576, ssrc, sdst, Mx, E, 6, eb,
                                      gA, e3W, P, N, 128, bna + 768, bnb + 768, mb);
    combine_fc<<<(N + 7) / 8, t256>>>(P, Mx, indeg, Wfc, bfc, (float*)d_out, N);
}

// round 17
// speedup vs baseline: 4.4730x; 1.1092x over previous
#include <cuda_runtime.h>
#include <cuda_fp16.h>
#include <math.h>

#define NCAP 20000
#define ECAP 320000

// ---------------- static scratch (no allocation allowed) ----------------
static __device__ unsigned d_x16 [NCAP * 32];    // fp16-packed proj output (64 cols)
static __device__ unsigned d_g16 [NCAP * 64];    // fp16-packed GCN outputs (<=128 cols)
static __device__ unsigned d_agg [NCAP * 64];    // fp16-packed aggregated rows
static __device__ unsigned d_v16 [NCAP * 128];   // fp16-packed a1-scaled rows (P-GEMM input)
static __device__ float    d_P   [NCAP * 128];
static __device__ unsigned d_Mx  [NCAP * 128];
static __device__ unsigned d_u16 [NCAP * 128];   // fp16-packed a2-scaled rows (edge input)
static __device__ unsigned d_wh  [32768];        // fp16-interleaved weights, ALL 3 edge layers
static __device__ unsigned d_bh  [512];          // fp16-packed BN offsets (2nd halves, then 1st halves)
static __device__ float    d_dinv[NCAP];
static __device__ int      d_indeg[NCAP];
static __device__ int      d_start[NCAP + 1];
static __device__ int      d_cnt  [NCAP];
static __device__ int      d_ssrc [ECAP];
static __device__ int      d_sdst [ECAP];
static __device__ float    d_ecoef[ECAP];
static __device__ float    d_bna [1024];         // BN scale, layers at 0 / 512 / 768
static __device__ float    d_bnb [1024];         // BN offset (f32, kept for reference path)

// ---------------- helpers ----------------
__device__ __forceinline__ unsigned pack_h2(float lo, float hi) {
    __half2 h = __floats2half2_rn(lo, hi);
    return *(unsigned*)&h;
}

__device__ __forceinline__ unsigned h2_q(unsigned us, unsigned ud, unsigned bb) {
    __half2 z = __floats2half2_rn(0.f, 0.f);
    __half2 r = __hmax2(__hadd2(__hsub2(*(__half2*)&us, *(__half2*)&ud), *(__half2*)&bb), z);
    return *(unsigned*)&r;
}

__device__ __forceinline__ unsigned h2_relu_add(unsigned v, unsigned b) {
    __half2 z = __floats2half2_rn(0.f, 0.f);
    __half2 r = __hmax2(__hadd2(*(__half2*)&v, *(__half2*)&b), z);
    return *(unsigned*)&r;
}

__device__ __forceinline__ void mma_f16(float* d, const unsigned* a, const unsigned* b) {
    asm volatile(
        "mma.sync.aligned.m16n8k16.row.col.f32.f16.f16.f32 "
        "{%0,%1,%2,%3}, {%4,%5,%6,%7}, {%8,%9}, {%0,%1,%2,%3};"
        : "+f"(d[0]), "+f"(d[1]), "+f"(d[2]), "+f"(d[3])
        : "r"(a[0]), "r"(a[1]), "r"(a[2]), "r"(a[3]), "r"(b[0]), "r"(b[1]));
}

__device__ __forceinline__ void red_max_enc(unsigned* p, float v) {
    unsigned u = __float_as_uint(v);
    unsigned key = (u & 0x80000000u) ? ~u : (u | 0x80000000u);
    asm volatile("red.global.max.u32 [%0], %1;" :: "l"(p), "r"(key) : "memory");
}

// ---------------- exclusive scan over indeg -> start; also zeros cnt, computes dinv ----------------
__global__ __launch_bounds__(1024) void scan_kernel(const int* __restrict__ indeg,
                                                    int* __restrict__ start,
                                                    int* __restrict__ cnt,
                                                    float* __restrict__ dinv, int N) {
    __shared__ int wsum[32];
    int t = threadIdx.x;
    int chunk = (N + 1023) / 1024;
    int lo = t * chunk;
    int hi = lo + chunk; if (hi > N) hi = N; if (lo > N) lo = N;
    int s = 0;
    for (int i = lo; i < hi; i++) s += indeg[i];
    int lane = t & 31, w = t >> 5;
    int v = s;
#pragma unroll
    for (int o = 1; o < 32; o <<= 1) {
        int u = __shfl_up_sync(0xffffffffu, v, o);
        if (lane >= o) v += u;
    }
    if (lane == 31) wsum[w] = v;
    __syncthreads();
    if (w == 0) {
        int x = wsum[lane];
#pragma unroll
        for (int o = 1; o < 32; o <<= 1) {
            int u = __shfl_up_sync(0xffffffffu, x, o);
            if (lane >= o) x += u;
        }
        wsum[lane] = x;
    }
    __syncthreads();
    int excl = (v - s) + (w > 0 ? wsum[w - 1] : 0);
    int run = excl;
    for (int i = lo; i < hi; i++) {
        start[i] = run;
        run += indeg[i];
        cnt[i] = 0;
        dinv[i] = rsqrtf((float)indeg[i] + 1.0f);
    }
    if (t == 1023) start[N] = run;
}

// ---------------- prep_all: edge scatter + Mx zero + packed fp16 weights/biases + BN coefs ----------------
__global__ void prep_all(
    const int* __restrict__ src, const int* __restrict__ dstv,
    const int* __restrict__ start, int* __restrict__ cnt, const float* __restrict__ dinv,
    int* __restrict__ ssrc, int* __restrict__ sdst, float* __restrict__ ecoef, int E,
    const float* __restrict__ w1, const float* __restrict__ w2, const float* __restrict__ w3,
    const float* __restrict__ g1, const float* __restrict__ b1,
    const float* __restrict__ m1, const float* __restrict__ v1,
    const float* __restrict__ g2, const float* __restrict__ b2,
    const float* __restrict__ m2, const float* __restrict__ v2,
    const float* __restrict__ g3, const float* __restrict__ b3,
    const float* __restrict__ m3, const float* __restrict__ v3,
    unsigned* __restrict__ Mx, unsigned* __restrict__ wh, unsigned* __restrict__ bh,
    float* __restrict__ bna, float* __restrict__ bnb, int N)
{
    int idx = blockIdx.x * 256 + threadIdx.x;
    if (idx < E) {
        int s = src[idx], d = dstv[idx];
        int p = start[d] + atomicAdd(&cnt[d], 1);
        ssrc[p] = s;
        sdst[p] = d;
        ecoef[p] = dinv[s] * dinv[d];
    }
    if (idx < N * 128) Mx[idx] = 0u;
    if (idx < 32768) {
        const float* W; int k2n;
        if (idx < 16384)      { W = w1; k2n = idx; }
        else if (idx < 24576) { W = w2; k2n = idx - 16384; }
        else                  { W = w3; k2n = idx - 24576; }
        int k2 = k2n >> 7, n = k2n & 127;
        wh[idx] = pack_h2(W[(2 * k2) * 128 + n], W[(2 * k2 + 1) * 128 + n]);
    }
    if (idx < 1024) {
        const float *g, *be, *me, *va; int i;
        if (idx < 512)      { g = g1; be = b1; me = m1; va = v1; i = idx; }
        else if (idx < 768) { g = g2; be = b2; me = m2; va = v2; i = idx - 512; }
        else                { g = g3; be = b3; me = m3; va = v3; i = idx - 768; }
        float a = g[i] * rsqrtf(va[i] + 1e-5f);
        bna[idx] = a;
        bnb[idx] = be[i] - me[i] * a;
    }
    if (idx < 512) {
        const float *g, *be, *me, *va; int c;
        if (idx < 128)      { g = g1; be = b1; me = m1; va = v1; c = 256 + 2 * idx; }        // e1 2nd half
        else if (idx < 192) { g = g2; be = b2; me = m2; va = v2; c = 128 + 2 * (idx - 128); } // e2 2nd half
        else if (idx < 256) { g = g3; be = b3; me = m3; va = v3; c = 128 + 2 * (idx - 192); } // e3 2nd half
        else if (idx < 384) { g = g1; be = b1; me = m1; va = v1; c = 2 * (idx - 256); }       // e1 1st half
        else if (idx < 448) { g = g2; be = b2; me = m2; va = v2; c = 2 * (idx - 384); }       // e2 1st half
        else                { g = g3; be = b3; me = m3; va = v3; c = 2 * (idx - 448); }       // e3 1st half
        float a0 = g[c] * rsqrtf(va[c] + 1e-5f);
        float a1 = g[c + 1] * rsqrtf(va[c + 1] + 1e-5f);
        bh[idx] = pack_h2(be[c] - me[c] * a0, be[c + 1] - me[c + 1] * a1);
    }
}

// ---------------- FP16 GEMM tile body (m16n8k16) ----------------
// A-operand: f32 (A) OR fp16-packed (Ah, optional fused relu(v + tah) with packed fp16 offsets).
// Outputs: C f32 (opt), outh fp16 (opt, scaled by a2u if given), outh2 fp16 (opt, scaled by a1u).
__device__ __forceinline__ void gemm_tile_body(
    const float* __restrict__ A, const unsigned* __restrict__ Ah,
    const unsigned* __restrict__ tah,
    const float* __restrict__ B,
    float* __restrict__ C, unsigned* __restrict__ outh, const float* __restrict__ a2u,
    unsigned* __restrict__ outh2, const float* __restrict__ a1u,
    int M, int K, int Ncols, int rmul, int skip4,
    const float* __restrict__ bias,
    int bx, int by, unsigned* As, unsigned* Bs)
{
    int tid = threadIdx.x;
    int lane = tid & 31, warp = tid >> 5;
    int wm = warp & 3, wn = warp >> 2;
    int gid = lane >> 2, tig = lane & 3;
    int row0 = bx * 64;
    int col0 = by * 64;
    float acc[4][4] = {};
    for (int k0 = 0; k0 < K; k0 += 32) {
#pragma unroll
        for (int i = 0; i < 2; i++) {
            int lin = tid + i * 256;          // 0..511
            int r = lin >> 3;                 // 0..63
            int q2 = (lin & 7) * 2;           // half2 slot
            int gr = row0 + r;
            uint2 pk = make_uint2(0u, 0u);
            if (gr < M) {
                if (Ah) {
                    pk = *(const uint2*)&Ah[(long long)gr * rmul * (K >> 1) + (k0 >> 1) + q2];
                    if (tah) {
                        uint2 t = *(const uint2*)&tah[(k0 >> 1) + q2];
                        pk.x = h2_relu_add(pk.x, t.x);
                        pk.y = h2_relu_add(pk.y, t.y);
                    }
                } else {
                    float4 v = *(const float4*)&A[(long long)gr * rmul * K + k0 + q2 * 2];
                    pk = make_uint2(pack_h2(v.x, v.y), pack_h2(v.z, v.w));
                }
            }
            *(uint2*)&As[r * 20 + q2] = pk;
        }
#pragma unroll
        for (int i = 0; i < 2; i++) {
            int lin = tid + i * 256;          // 0..511
            int k2 = lin >> 5;                // 0..15 (half2-k index)
            int n2 = (lin & 31) * 2;          // 2 columns per thread
            const float* w0 = &B[(long long)(k0 + 2 * k2) * Ncols + col0 + n2];
            const float* w1 = &B[(long long)(k0 + 2 * k2 + 1) * Ncols + col0 + n2];
            float2 wa = *(const float2*)w0;
            float2 wb = *(const float2*)w1;
            *(uint2*)&Bs[k2 * 72 + n2] =
                make_uint2(pack_h2(wa.x, wb.x), pack_h2(wa.y, wb.y));
        }
        __syncthreads();
#pragma unroll
        for (int s = 0; s < 2; s++) {
            int ac = s * 8 + tig;
            unsigned a[4];
            int ar = wm * 16 + gid;
            a[0] = As[ar * 20 + ac];
            a[1] = As[(ar + 8) * 20 + ac];
            a[2] = As[ar * 20 + ac + 4];
            a[3] = As[(ar + 8) * 20 + ac + 4];
#pragma unroll
            for (int nt = 0; nt < 4; nt++) {
                unsigned b[2];
                int bc = wn * 32 + nt * 8 + gid;
                b[0] = Bs[(s * 8 + tig) * 72 + bc];
                b[1] = Bs[(s * 8 + tig + 4) * 72 + bc];
                mma_f16(acc[nt], a, b);
            }
        }
        __syncthreads();
    }
#pragma unroll
    for (int half = 0; half < 2; half++) {
        int gr = row0 + wm * 16 + gid + half * 8;
        if (gr < M && !(skip4 && (gr & 3) == 0)) {
            long long prow = (long long)gr * rmul;
#pragma unroll
            for (int nt = 0; nt < 4; nt++) {
                int col = col0 + wn * 32 + nt * 8 + tig * 2;
                float v0 = acc[nt][half * 2 + 0];
                float v1 = acc[nt][half * 2 + 1];
                if (bias) { v0 += bias[col]; v1 += bias[col + 1]; }
                if (C) {
                    C[prow * Ncols + col]     = v0;
                    C[prow * Ncols + col + 1] = v1;
                }
                if (outh) {
                    float s0 = v0, s1 = v1;
                    if (a2u) { s0 *= a2u[col]; s1 *= a2u[col + 1]; }
                    outh[prow * (Ncols >> 1) + (col >> 1)] = pack_h2(s0, s1);
                }
                if (outh2)
                    outh2[prow * (Ncols >> 1) + (col >> 1)] =
                        pack_h2(v0 * a1u[col], v1 * a1u[col + 1]);
            }
        }
    }
}

// ---------------- standalone GEMM kernel ----------------
__global__ __launch_bounds__(256) void gemm_tc(
    const unsigned* __restrict__ Ah, const float* __restrict__ B,
    unsigned* __restrict__ outh, const float* __restrict__ a2u,
    unsigned* __restrict__ outh2, const float* __restrict__ a1u,
    int M, int K, int Ncols, const float* __restrict__ bias)
{
    __shared__ unsigned As[64 * 20];
    __shared__ unsigned Bs[16 * 72];
    gemm_tile_body(nullptr, Ah, nullptr, B, nullptr, outh, a2u, outh2, a1u,
                   M, K, Ncols, 1, 0, bias, blockIdx.x, blockIdx.y, As, Bs);
}

// ---------------- fused dual projection + indeg count (indeg pre-zeroed by combine_fc/static init) ----------------
__global__ __launch_bounds__(256) void proj_fused(
    const float* __restrict__ x,
    const float* __restrict__ Wc, const float* __restrict__ bc,
    const float* __restrict__ Wm, const float* __restrict__ bm,
    unsigned* __restrict__ x16,
    const int* __restrict__ dstv, int* __restrict__ indeg, int N, int E, int mb, int mb4)
{
    int gidx = blockIdx.x * 256 + threadIdx.x;
    if (gidx < E) atomicAdd(&indeg[dstv[gidx]], 1);
    __shared__ unsigned As[64 * 20];
    __shared__ unsigned Bs[16 * 72];
    if ((int)blockIdx.x < mb) {
        gemm_tile_body(x, nullptr, nullptr, Wc, nullptr, x16, nullptr, nullptr, nullptr,
                       N, 512, 64, 1, 1, bc, blockIdx.x, 0, As, Bs);
    } else if ((int)blockIdx.x < mb + mb4) {
        gemm_tile_body(x, nullptr, nullptr, Wm, nullptr, x16, nullptr, nullptr, nullptr,
                       (N + 3) / 4, 512, 64, 4, 0, bm, blockIdx.x - mb, 0, As, Bs);
    }
}

// ---------------- GCN aggregation (pre-GEMM): agg = dinv^2*x_i + sum coef*x_s (fp16 in/out) ----------------
__global__ __launch_bounds__(256) void gcn_agg(
    const unsigned* __restrict__ in16, const int* __restrict__ ssrc,
    const float* __restrict__ ecoef, const int* __restrict__ start,
    const float* __restrict__ dinv, unsigned* __restrict__ out16,
    int N, int R)
{
    int node = blockIdx.x * 8 + (threadIdx.x >> 5);
    int lane = threadIdx.x & 31;
    if (node >= N) return;
    float di = dinv[node];
    float di2 = di * di;
    int s0 = start[node], s1 = start[node + 1];
    if (R == 64) {
        uint2 hv = *(const uint2*)&in16[(long long)node * 64 + lane * 2];
        float2 f0 = __half22float2(*(__half2*)&hv.x);
        float2 f1 = __half22float2(*(__half2*)&hv.y);
        float4 acc = make_float4(di2 * f0.x, di2 * f0.y, di2 * f1.x, di2 * f1.y);
        for (int base = s0; base < s1; base += 32) {
            int e = base + lane;
            int sidx = 0; float cf = 0.f;
            if (e < s1) { sidx = ssrc[e]; cf = ecoef[e]; }
            int cnt = s1 - base; if (cnt > 32) cnt = 32;
            int j = 0;
            for (; j + 4 <= cnt; j += 4) {
                int sa = __shfl_sync(0xffffffffu, sidx, j);
                int sb = __shfl_sync(0xffffffffu, sidx, j + 1);
                int sc = __shfl_sync(0xffffffffu, sidx, j + 2);
                int sdd = __shfl_sync(0xffffffffu, sidx, j + 3);
                float ca = __shfl_sync(0xffffffffu, cf, j);
                float cb = __shfl_sync(0xffffffffu, cf, j + 1);
                float cc = __shfl_sync(0xffffffffu, cf, j + 2);
                float cd = __shfl_sync(0xffffffffu, cf, j + 3);
                uint2 ha = *(const uint2*)&in16[(long long)sa * 64 + lane * 2];
                uint2 hb = *(const uint2*)&in16[(long long)sb * 64 + lane * 2];
                uint2 hc = *(const uint2*)&in16[(long long)sc * 64 + lane * 2];
                uint2 hd = *(const uint2*)&in16[(long long)sdd * 64 + lane * 2];
                float2 a0 = __half22float2(*(__half2*)&ha.x);
                float2 a1 = __half22float2(*(__half2*)&ha.y);
                float2 b0 = __half22float2(*(__half2*)&hb.x);
                float2 b1 = __half22float2(*(__half2*)&hb.y);
                float2 c0 = __half22float2(*(__half2*)&hc.x);
                float2 c1 = __half22float2(*(__half2*)&hc.y);
                float2 d0 = __half22float2(*(__half2*)&hd.x);
                float2 d1 = __half22float2(*(__half2*)&hd.y);
                acc.x += ca * a0.x + cb * b0.x + cc * c0.x + cd * d0.x;
                acc.y += ca * a0.y + cb * b0.y + cc * c0.y + cd * d0.y;
                acc.z += ca * a1.x + cb * b1.x + cc * c1.x + cd * d1.x;
                acc.w += ca * a1.y + cb * b1.y + cc * c1.y + cd * d1.y;
            }
            for (; j < cnt; j++) {
                int s = __shfl_sync(0xffffffffu, sidx, j);
                float coef = __shfl_sync(0xffffffffu, cf, j);
                uint2 hv2 = *(const uint2*)&in16[(long long)s * 64 + lane * 2];
                float2 f2 = __half22float2(*(__half2*)&hv2.x);
                float2 f3 = __half22float2(*(__half2*)&hv2.y);
                acc.x += coef * f2.x;
                acc.y += coef * f2.y;
                acc.z += coef * f3.x;
                acc.w += coef * f3.y;
            }
        }
        uint2 pk;
        pk.x = pack_h2(acc.x, acc.y);
        pk.y = pack_h2(acc.z, acc.w);
        *(uint2*)&out16[(long long)node * 64 + lane * 2] = pk;
    } else {  // R == 32
        unsigned hv = in16[(long long)node * 32 + lane];
        float2 f0 = __half22float2(*(__half2*)&hv);
        float2 acc = make_float2(di2 * f0.x, di2 * f0.y);
        for (int base = s0; base < s1; base += 32) {
            int e = base + lane;
            int sidx = 0; float cf = 0.f;
            if (e < s1) { sidx = ssrc[e]; cf = ecoef[e]; }
            int cnt = s1 - base; if (cnt > 32) cnt = 32;
            int j = 0;
            for (; j + 4 <= cnt; j += 4) {
                int sa = __shfl_sync(0xffffffffu, sidx, j);
                int sb = __shfl_sync(0xffffffffu, sidx, j + 1);
                int sc = __shfl_sync(0xffffffffu, sidx, j + 2);
                int sdd = __shfl_sync(0xffffffffu, sidx, j + 3);
                float ca = __shfl_sync(0xffffffffu, cf, j);
                float cb = __shfl_sync(0xffffffffu, cf, j + 1);
                float cc = __shfl_sync(0xffffffffu, cf, j + 2);
                float cd = __shfl_sync(0xffffffffu, cf, j + 3);
                unsigned ha = in16[(long long)sa * 32 + lane];
                unsigned hb = in16[(long long)sb * 32 + lane];
                unsigned hc = in16[(long long)sc * 32 + lane];
                unsigned hd = in16[(long long)sdd * 32 + lane];
                float2 a0 = __half22float2(*(__half2*)&ha);
                float2 b0 = __half22float2(*(__half2*)&hb);
                float2 c0 = __half22float2(*(__half2*)&hc);
                float2 d0 = __half22float2(*(__half2*)&hd);
                acc.x += ca * a0.x + cb * b0.x + cc * c0.x + cd * d0.x;
                acc.y += ca * a0.y + cb * b0.y + cc * c0.y + cd * d0.y;
            }
            for (; j < cnt; j++) {
                int s = __shfl_sync(0xffffffffu, sidx, j);
                float coef = __shfl_sync(0xffffffffu, cf, j);
                unsigned hv2 = in16[(long long)s * 32 + lane];
                float2 f2 = __half22float2(*(__half2*)&hv2);
                acc.x += coef * f2.x;
                acc.y += coef * f2.y;
            }
        }
        out16[(long long)node * 32 + lane] = pack_h2(acc.x, acc.y);
    }
}

// ---------------- EdgeConv tile body: SOFTWARE-PIPELINED gathers ----------------
__device__ __forceinline__ void edgeconv_body(
    const unsigned* __restrict__ u16, const unsigned* __restrict__ b16,
    const unsigned* __restrict__ Whg,
    const int* __restrict__ ssrc, const int* __restrict__ sdstv,
    unsigned* __restrict__ Mout, int E, int lc2,
    int bid, unsigned* sh, int* ss, int* sd)
{
    unsigned* qh = sh;                 // [edge][k2] stride 20
    unsigned* wh = sh + 128 * 20;      // [k2][n]  stride 136
    int tid = threadIdx.x;
    int e0 = bid * 128;
    if (tid < 128) {
        int e = e0 + tid;
        if (e >= E) e = E - 1;
        ss[tid] = ssrc[e];
        sd[tid] = sdstv[e];
    }
    __syncthreads();
    int lane = tid & 31, warp = tid >> 5;
    int wm = warp & 3, wn = warp >> 2;
    int gid = lane >> 2, tig = lane & 3;
    int C2 = 1 << lc2;
    // per-thread fill coordinates (two items: A at lin=tid, B at lin=tid+256)
    int eA = tid >> 2, q4 = (tid & 3) * 4;      // eB = eA + 64, same q4
    int kA = tid >> 5, n4 = (tid & 31) * 4;     // kB = kA + 8,  same n4
    long long rsA = (long long)ss[eA] << lc2,      rdA = (long long)sd[eA] << lc2;
    long long rsB = (long long)ss[eA + 64] << lc2, rdB = (long long)sd[eA + 64] << lc2;
    uint4 usA, udA, usB, udB, wA, wB;
    // prologue: chunk 0 loads
    usA = *(const uint4*)&u16[rsA + q4];
    udA = *(const uint4*)&u16[rdA + q4];
    usB = *(const uint4*)&u16[rsB + q4];
    udB = *(const uint4*)&u16[rdB + q4];
    wA  = *(const uint4*)&Whg[(long long)kA * 128 + n4];
    wB  = *(const uint4*)&Whg[(long long)(kA + 8) * 128 + n4];
    float acc[2][8][4] = {};
    for (int k20 = 0; k20 < C2; k20 += 16) {
        // convert + store current chunk
        {
            uint4 bbA = *(const uint4*)&b16[k20 + q4];
            uint4 r;
            r.x = h2_q(usA.x, udA.x, bbA.x);
            r.y = h2_q(usA.y, udA.y, bbA.y);
            r.z = h2_q(usA.z, udA.z, bbA.z);
            r.w = h2_q(usA.w, udA.w, bbA.w);
            *(uint4*)&qh[eA * 20 + q4] = r;
            r.x = h2_q(usB.x, udB.x, bbA.x);
            r.y = h2_q(usB.y, udB.y, bbA.y);
            r.z = h2_q(usB.z, udB.z, bbA.z);
            r.w = h2_q(usB.w, udB.w, bbA.w);
            *(uint4*)&qh[(eA + 64) * 20 + q4] = r;
            *(uint4*)&wh[kA * 136 + n4] = wA;
            *(uint4*)&wh[(kA + 8) * 136 + n4] = wB;
        }
        __syncthreads();
        // prefetch next chunk while mma runs
        if (k20 + 16 < C2) {
            int kg = k20 + 16;
            usA = *(const uint4*)&u16[rsA + kg + q4];
            udA = *(const uint4*)&u16[rdA + kg + q4];
            usB = *(const uint4*)&u16[rsB + kg + q4];
            udB = *(const uint4*)&u16[rdB + kg + q4];
            wA  = *(const uint4*)&Whg[(long long)(kg + kA) * 128 + n4];
            wB  = *(const uint4*)&Whg[(long long)(kg + kA + 8) * 128 + n4];
        }
#pragma unroll
        for (int s = 0; s < 2; s++) {
            unsigned bf[8][2];
#pragma unroll
            for (int nt = 0; nt < 8; nt++) {
                int bc = wn * 64 + nt * 8 + gid;
                bf[nt][0] = wh[(s * 8 + tig) * 136 + bc];
                bf[nt][1] = wh[(s * 8 + tig + 4) * 136 + bc];
            }
            int ac = s * 8 + tig;
#pragma unroll
            for (int mt = 0; mt < 2; mt++) {
                unsigned a[4];
                int ar = wm * 32 + mt * 16 + gid;
                a[0] = qh[ar * 20 + ac];
                a[1] = qh[(ar + 8) * 20 + ac];
                a[2] = qh[ar * 20 + ac + 4];
                a[3] = qh[(ar + 8) * 20 + ac + 4];
#pragma unroll
                for (int nt = 0; nt < 8; nt++)
                    mma_f16(acc[mt][nt], a, bf[nt]);
            }
        }
        __syncthreads();
    }
    // segmented max: 4 passes of 32 rows (dst-sorted); smem reuse
    float* sacc = (float*)sh;
#pragma unroll
    for (int pass = 0; pass < 4; pass++) {
        if (wm == pass) {
#pragma unroll
            for (int mt = 0; mt < 2; mt++) {
#pragma unroll
                for (int half = 0; half < 2; half++) {
                    int rl = mt * 16 + gid + half * 8;   // 0..31
#pragma unroll
                    for (int nt = 0; nt < 8; nt++) {
                        int col = wn * 64 + nt * 8 + tig * 2;
                        sacc[rl * 132 + col]     = acc[mt][nt][half * 2 + 0];
                        sacc[rl * 132 + col + 1] = acc[mt][nt][half * 2 + 1];
                    }
                }
            }
        }
        __syncthreads();
        {
            int col = tid & 127;
            int rh = tid >> 7;                  // 0..1
            int r0 = rh * 16, r1 = r0 + 16;
            int base = pass * 32;
            int cur = sd[base + r0];
            float m = sacc[r0 * 132 + col];
            for (int r = r0 + 1; r < r1; r++) {
                int d = sd[base + r];
                float v = sacc[r * 132 + col];
                if (d != cur) {
                    red_max_enc(&Mout[(long long)cur * 128 + col], m);
                    cur = d;
                    m = v;
                } else {
                    m = fmaxf(m, v);
                }
            }
            red_max_enc(&Mout[(long long)cur * 128 + col], m);
        }
        __syncthreads();
    }
}

// ---------------- fused per-layer kernel: edgeconv tiles + P-GEMM tiles in one launch ----------------
// P-GEMM consumes fp16 v16 with fused relu(v + tah).
__global__ __launch_bounds__(256, 2) void edge_fused(
    const unsigned* __restrict__ u16, const unsigned* __restrict__ b16,
    const unsigned* __restrict__ Whg,
    const int* __restrict__ ssrc, const int* __restrict__ sdstv,
    unsigned* __restrict__ Mout, int E, int lc2, int eb,
    const unsigned* __restrict__ v16, const unsigned* __restrict__ tah,
    const float* __restrict__ B, float* __restrict__ P,
    int M, int K, int mbx)
{
    __shared__ unsigned buf[128 * 20 + 16 * 136];
    __shared__ int ssA[128], sdA[128];
    if ((int)blockIdx.x < eb) {
        edgeconv_body(u16, b16, Whg, ssrc, sdstv, Mout, E, lc2, blockIdx.x, buf, ssA, sdA);
    } else {
        int b = blockIdx.x - eb;
        gemm_tile_body(nullptr, v16, tah, B, P, nullptr, nullptr, nullptr, nullptr,
                       M, K, 128, 1, 0, nullptr, b % mbx, b / mbx, buf, buf + 64 * 20);
    }
}

// ---------------- EdgeConv combine -> fp16 u16 (a2-scaled) + v16 (a1-scaled); resets M ----------------
__global__ void combine_kernel(const float* __restrict__ P, unsigned* __restrict__ Mv,
                               const int* __restrict__ indeg, int N,
                               const float* __restrict__ a2u, unsigned* __restrict__ u16,
                               const float* __restrict__ a1u, unsigned* __restrict__ v16)
{
    int idx4 = blockIdx.x * 256 + threadIdx.x;
    if (idx4 >= N * 32) return;
    int i = idx4 >> 5;
    int colbase = (idx4 & 31) * 4;
    uint4 kv = *(uint4*)&Mv[idx4 * 4];
    float4 pv = *(const float4*)&P[idx4 * 4];
    float4 o = make_float4(0.f, 0.f, 0.f, 0.f);
    if (indeg[i] > 0) {
        unsigned u0 = (kv.x & 0x80000000u) ? (kv.x & 0x7fffffffu) : ~kv.x;
        unsigned u1 = (kv.y & 0x80000000u) ? (kv.y & 0x7fffffffu) : ~kv.y;
        unsigned u2 = (kv.z & 0x80000000u) ? (kv.z & 0x7fffffffu) : ~kv.z;
        unsigned u3 = (kv.w & 0x80000000u) ? (kv.w & 0x7fffffffu) : ~kv.w;
        o.x = pv.x + __uint_as_float(u0);
        o.y = pv.y + __uint_as_float(u1);
        o.z = pv.z + __uint_as_float(u2);
        o.w = pv.w + __uint_as_float(u3);
    }
    *(uint4*)&Mv[idx4 * 4] = make_uint4(0u, 0u, 0u, 0u);   // re-zero for next layer
    float4 a2 = *(const float4*)&a2u[colbase];
    float4 a1 = *(const float4*)&a1u[colbase];
    uint2 pu, pvv;
    pu.x = pack_h2(a2.x * o.x, a2.y * o.y);
    pu.y = pack_h2(a2.z * o.z, a2.w * o.w);
    pvv.x = pack_h2(a1.x * o.x, a1.y * o.y);
    pvv.y = pack_h2(a1.z * o.z, a1.w * o.w);
    *(uint2*)&u16[(i << 6) + (idx4 & 31) * 2] = pu;
    *(uint2*)&v16[(i << 6) + (idx4 & 31) * 2] = pvv;
}

// ---------------- final: combine last EdgeConv + FC; zeroes indeg for next graph replay ----------------
__global__ void combine_fc(const float* __restrict__ P, const unsigned* __restrict__ Mv,
                           int* __restrict__ indeg,
                           const float* __restrict__ W, const float* __restrict__ b,
                           float* __restrict__ out, int N)
{
    int node = blockIdx.x * 8 + (threadIdx.x >> 5);
    int lane = threadIdx.x & 31;
    if (node >= N) return;
    uint4 kv = *(const uint4*)&Mv[node * 128 + lane * 4];
    float4 pv = *(const float4*)&P[node * 128 + lane * 4];
    float4 o = make_float4(0.f, 0.f, 0.f, 0.f);
    if (indeg[node] > 0) {
        unsigned u0 = (kv.x & 0x80000000u) ? (kv.x & 0x7fffffffu) : ~kv.x;
        unsigned u1 = (kv.y & 0x80000000u) ? (kv.y & 0x7fffffffu) : ~kv.y;
        unsigned u2 = (kv.z & 0x80000000u) ? (kv.z & 0x7fffffffu) : ~kv.z;
        unsigned u3 = (kv.w & 0x80000000u) ? (kv.w & 0x7fffffffu) : ~kv.w;
        o.x = pv.x + __uint_as_float(u0);
        o.y = pv.y + __uint_as_float(u1);
        o.z = pv.z + __uint_as_float(u2);
        o.w = pv.w + __uint_as_float(u3);
    }
    float4 w = *(const float4*)&W[lane * 4];
    float s = o.x * w.x + o.y * w.y + o.z * w.z + o.w * w.w;
#pragma unroll
    for (int off = 16; off; off >>= 1) s += __shfl_down_sync(0xffffffffu, s, off);
    if (lane == 0) {
        out[node] = s + b[0];
        indeg[node] = 0;            // self-clean for next graph replay
    }
}

// ---------------- launch ----------------
extern "C" void kernel_launch(void* const* d_in, const int* in_sizes, int n_in,
                              void* d_out, int out_size)
{
    const float* x   = (const float*)d_in[0];
    const int*   ei  = (const int*)d_in[1];
    const float* Wm  = (const float*)d_in[2];
    const float* bm  = (const float*)d_in[3];
    const float* Wc  = (const float*)d_in[4];
    const float* bc  = (const float*)d_in[5];
    const float* Wg1 = (const float*)d_in[6];
    const float* bg1 = (const float*)d_in[7];
    const float* Wg2 = (const float*)d_in[8];
    const float* bg2 = (const float*)d_in[9];
    const float* Wg3 = (const float*)d_in[10];
    const float* bg3 = (const float*)d_in[11];
    const float* e1g = (const float*)d_in[12];
    const float* e1b = (const float*)d_in[13];
    const float* e1m = (const float*)d_in[14];
    const float* e1v = (const float*)d_in[15];
    const float* e1W = (const float*)d_in[16];
    const float* e2g = (const float*)d_in[17];
    const float* e2b = (const float*)d_in[18];
    const float* e2m = (const float*)d_in[19];
    const float* e2v = (const float*)d_in[20];
    const float* e2W = (const float*)d_in[21];
    const float* e3g = (const float*)d_in[22];
    const float* e3b = (const float*)d_in[23];
    const float* e3m = (const float*)d_in[24];
    const float* e3v = (const float*)d_in[25];
    const float* e3W = (const float*)d_in[26];
    const float* Wfc = (const float*)d_in[27];
    const float* bfc = (const float*)d_in[28];

    int N = in_sizes[0] / 512;
    int E = in_sizes[1] / 2;
    const int* src = ei;
    const int* dst = ei + E;

    float *P, *dinv, *bna, *bnb, *ecoef;
    unsigned *Mx, *u16p, *whp, *bhp, *g16, *agg16, *x16, *v16;
    int *indeg, *startp, *cnt, *ssrc, *sdst;
    cudaGetSymbolAddress((void**)&x16,   d_x16);
    cudaGetSymbolAddress((void**)&g16,   d_g16);
    cudaGetSymbolAddress((void**)&agg16, d_agg);
    cudaGetSymbolAddress((void**)&v16,   d_v16);
    cudaGetSymbolAddress((void**)&P,     d_P);
    cudaGetSymbolAddress((void**)&Mx,    d_Mx);
    cudaGetSymbolAddress((void**)&u16p,  d_u16);
    cudaGetSymbolAddress((void**)&whp,   d_wh);
    cudaGetSymbolAddress((void**)&bhp,   d_bh);
    cudaGetSymbolAddress((void**)&dinv,  d_dinv);
    cudaGetSymbolAddress((void**)&indeg, d_indeg);
    cudaGetSymbolAddress((void**)&startp,d_start);
    cudaGetSymbolAddress((void**)&cnt,   d_cnt);
    cudaGetSymbolAddress((void**)&ssrc,  d_ssrc);
    cudaGetSymbolAddress((void**)&sdst,  d_sdst);
    cudaGetSymbolAddress((void**)&ecoef, d_ecoef);
    cudaGetSymbolAddress((void**)&bna,   d_bna);
    cudaGetSymbolAddress((void**)&bnb,   d_bnb);

    dim3 t256(256);
    int mb = (N + 63) / 64;
    int M4 = (N + 3) / 4;
    int mb4 = (M4 + 63) / 64;
    int eb = (E + 127) / 128;

    // fused dual projection + indeg count (indeg zeroed by previous run / static init)
    int pg = mb + mb4;
    int cg = (E + 255) / 256;
    proj_fused<<<(pg > cg ? pg : cg), t256>>>(x, Wc, bc, Wm, bm, x16, dst, indeg, N, E, mb, mb4);

    // CSR sort by dst + launch-invariant prep
    scan_kernel<<<1, 1024>>>(indeg, startp, cnt, dinv, N);
    prep_all<<<(N * 128 + 255) / 256, t256>>>(
        src, dst, startp, cnt, dinv, ssrc, sdst, ecoef, E,
        e1W + 256 * 128, e2W + 128 * 128, e3W + 128 * 128,
        e1g, e1b, e1m, e1v, e2g, e2b, e2m, e2v, e3g, e3b, e3m, e3v,
        Mx, whp, bhp, bna, bnb, N);

    // GCN layers: aggregate-then-GEMM
    gcn_agg<<<(N + 7) / 8, t256>>>(x16, ssrc, ecoef, startp, dinv, agg16, N, 32);
    gemm_tc<<<dim3(mb, 2), t256>>>(agg16, Wg1, g16, nullptr, nullptr, nullptr, N, 64, 128, bg1);

    gcn_agg<<<(N + 7) / 8, t256>>>(g16, ssrc, ecoef, startp, dinv, agg16, N, 64);
    gemm_tc<<<dim3(mb, 2), t256>>>(agg16, Wg2, g16, nullptr, nullptr, nullptr, N, 128, 128, bg2);

    // GCN3: emit u16 (a2-scaled, edge input) + v16 (a1-scaled, P-GEMM input), 256 cols
    gcn_agg<<<(N + 7) / 8, t256>>>(g16, ssrc, ecoef, startp, dinv, agg16, N, 64);
    gemm_tc<<<dim3(mb, 4), t256>>>(agg16, Wg3, u16p, bna + 256, v16, bna, N, 128, 256, bg3);

    // EdgeConv1 (fused edgeconv + fp16 P-GEMM)
    edge_fused<<<eb + mb * 2, t256>>>(u16p, bhp, whp, ssrc, sdst, Mx, E, 7, eb,
                                      v16, bhp + 256, e1W, P, N, 256, mb);
    combine_kernel<<<(N * 32 + 255) / 256, t256>>>(P, Mx, indeg, N,
                                                   bna + 640, u16p, bna + 512, v16);

    // EdgeConv2
    edge_fused<<<eb + mb * 2, t256>>>(u16p, bhp + 128, whp + 16384, ssrc, sdst, Mx, E, 6, eb,
                                      v16, bhp + 384, e2W, P, N, 128, mb);
    combine_kernel<<<(N * 32 + 255) / 256, t256>>>(P, Mx, indeg, N,
                                                   bna + 896, u16p, bna + 768, v16);

    // EdgeConv3 -> combine fused with FC (also zeroes indeg for next replay)
    edge_fused<<<eb + mb * 2, t256>>>(u16p, bhp + 192, whp + 24576, ssrc, sdst, Mx, E, 6, eb,
                                      v16, bhp + 448, e3W, P, N, 128, mb);
    combine_fc<<<(N + 7) / 8, t256>>>(P, Mx, indeg, Wfc, bfc, (float*)d_out, N);
}